// round 5
// baseline (speedup 1.0000x reference)
#include <cuda_runtime.h>

#define BATCH 16
#define NT 3
#define NSEQ 1024
#define IND 512
#define FD 256
#define NLAY 3
#define NWRD 32
#define ALPHAV 0.2f
#define NEGV -9e15f

// ---------------- scratch (device globals; no allocations allowed) ----------
__device__ unsigned g_mask[NLAY][BATCH * NT * NSEQ * NWRD];
__device__ float g_h[(size_t)9 * BATCH * NSEQ * FD];
__device__ float g_f1[9 * BATCH * NSEQ];
__device__ float g_f2[9 * BATCH * NSEQ];
__device__ unsigned g_attf[(size_t)BATCH * NSEQ * NSEQ];          // att A-fragments
__device__ unsigned g_xfrag[(size_t)BATCH * NSEQ * IND];          // X A-fragments
__device__ unsigned g_wfrag[9 * IND * FD];                        // W B-fragments
__device__ unsigned g_hfrag[(size_t)NT * BATCH * NSEQ * FD];      // h B-frags (k=2 z's)
__device__ float g_H[(size_t)BATCH * NSEQ * NLAY * FD];

__device__ __forceinline__ unsigned cvt_tf32(float x) {
    unsigned r;
    asm("cvt.rna.tf32.f32 %0, %1;" : "=r"(r) : "f"(x));
    return r;
}

// ---------------- adj -> bitset --------------------------------------------
__global__ void bits_kernel(const float* __restrict__ adj) {
    int r = blockIdx.x;
    int tid = threadIdx.x;
    float v = adj[(size_t)r * NSEQ + tid];
    unsigned bal = __ballot_sync(0xffffffffu, v > 0.0f);
    if ((tid & 31) == 0) g_mask[0][(size_t)r * NWRD + (tid >> 5)] = bal;
}

__global__ void bmm_kernel(int src, int dst) {
    int r = blockIdx.x;
    int bt = r / NSEQ;
    int lane = threadIdx.x;
    const unsigned* lrow = &g_mask[src][(size_t)r * NWRD];
    const unsigned* rbase = &g_mask[0][(size_t)bt * NSEQ * NWRD];
    unsigned myw = lrow[lane];
    unsigned acc = 0;
    #pragma unroll 1
    for (int w = 0; w < NWRD; ++w) {
        unsigned bitsw = __shfl_sync(0xffffffffu, myw, w);
        while (bitsw) {
            int j = (w << 5) + (__ffs(bitsw) - 1);
            bitsw &= bitsw - 1;
            acc |= rbase[(size_t)j * NWRD + lane];
        }
    }
    g_mask[dst][(size_t)r * NWRD + lane] = acc;
}

// ---------------- operand pre-fragmentization -------------------------------
// A-frag for value (m,k): lane=(m&7)*4+(k&3), reg=((m>>3)&1)+2*((k>>2)&1)
//   uint4 word index: (mtile*(K/8)+ktile)*32+lane  (mtile=m/16, ktile=k/8)
// B-frag for value (k,n): lane=(n&7)*4+(k&3), reg=(k>>2)&1
//   uint2 word index: (ntile*(K/8)+ktile)*32+lane  (ntile=n/8)

__global__ void xfrag_kernel(const float* __restrict__ X) {
    // one thread per uint4 word; K=IND, M=BATCH*NSEQ
    int idx = blockIdx.x * blockDim.x + threadIdx.x;   // (mt*(IND/8)+kt)*32+lane
    int lane = idx & 31;
    int kt = (idx >> 5) & (IND / 8 - 1);
    int mt = idx >> 5 >> 6;                             // /(IND/8)=64
    int m0 = mt * 16 + (lane >> 2);
    int k0 = kt * 8 + (lane & 3);
    uint4 t;
    t.x = cvt_tf32(X[(size_t)m0 * IND + k0]);
    t.y = cvt_tf32(X[(size_t)(m0 + 8) * IND + k0]);
    t.z = cvt_tf32(X[(size_t)m0 * IND + k0 + 4]);
    t.w = cvt_tf32(X[(size_t)(m0 + 8) * IND + k0 + 4]);
    ((uint4*)g_xfrag)[idx] = t;
}

__global__ void wfrag_kernel(const float* __restrict__ W) {
    // one thread per uint2 word per z; K=IND, N=FD
    int idx = blockIdx.x * blockDim.x + threadIdx.x;
    int z = idx / (IND * FD / 2);
    int w = idx % (IND * FD / 2);                       // (nt*(IND/8)+kt)*32+lane
    int lane = w & 31;
    int kt = (w >> 5) & (IND / 8 - 1);
    int nt = w >> 5 >> 6;
    int n = nt * 8 + (lane >> 2);
    int k0 = kt * 8 + (lane & 3);
    const float* Wz = W + (size_t)z * IND * FD;
    uint2 t;
    t.x = cvt_tf32(Wz[(size_t)k0 * FD + n]);
    t.y = cvt_tf32(Wz[(size_t)(k0 + 4) * FD + n]);
    ((uint2*)g_wfrag)[idx] = t;
}

// ---------------- fragment-direct tf32 GEMM (no smem) -----------------------
// Afrag/Bfrag pre-fragmented; C fp32 row-major. 128x128 CTA tile, 8 warps.
#define BM 128
#define BN 128

__global__ __launch_bounds__(256, 2) void tgemm_ff(
    const unsigned* __restrict__ Af, const unsigned* __restrict__ Bf,
    float* __restrict__ C,
    int ktiles, int ldc,
    long long sAf, long long sBf, long long sC,
    int accum, int hfrag_t)                 // hfrag_t >= 0: also emit B-frags of C
{
    int z = blockIdx.z;
    const uint4* Ap = (const uint4*)(Af + (size_t)z * sAf);
    const uint2* Bp = (const uint2*)(Bf + (size_t)z * sBf);
    C += (size_t)z * sC;

    int tid = threadIdx.x;
    int lane = tid & 31;
    int wid = tid >> 5;
    int wm = wid >> 2;
    int wn = wid & 3;

    int mt0 = blockIdx.y * 8 + wm * 4;      // mtile base (16-row tiles)
    int nt0 = blockIdx.x * 16 + wn * 4;     // ntile base (8-col tiles)

    float d[4][4][4];
    #pragma unroll
    for (int i = 0; i < 4; i++)
        #pragma unroll
        for (int j = 0; j < 4; j++)
            #pragma unroll
            for (int r = 0; r < 4; r++) d[i][j][r] = 0.0f;

    uint4 aR[2][4];
    uint2 bR[2][4];

    #define LD_FRAG(buf, kt)                                                 \
        {                                                                    \
            _Pragma("unroll")                                                \
            for (int mt = 0; mt < 4; mt++)                                   \
                aR[buf][mt] = Ap[((size_t)(mt0 + mt) * ktiles + (kt)) * 32 + lane]; \
            _Pragma("unroll")                                                \
            for (int nt = 0; nt < 4; nt++)                                   \
                bR[buf][nt] = Bp[((size_t)(nt0 + nt) * ktiles + (kt)) * 32 + lane]; \
        }

    LD_FRAG(0, 0);
    for (int kt = 0; kt < ktiles; kt++) {
        int cur = kt & 1;
        if (kt + 1 < ktiles) LD_FRAG(cur ^ 1, kt + 1);
        #pragma unroll
        for (int mt = 0; mt < 4; mt++)
            #pragma unroll
            for (int nt = 0; nt < 4; nt++) {
                asm volatile(
                    "mma.sync.aligned.m16n8k8.row.col.f32.tf32.tf32.f32 "
                    "{%0,%1,%2,%3}, {%4,%5,%6,%7}, {%8,%9}, {%0,%1,%2,%3};"
                    : "+f"(d[mt][nt][0]), "+f"(d[mt][nt][1]),
                      "+f"(d[mt][nt][2]), "+f"(d[mt][nt][3])
                    : "r"(aR[cur][mt].x), "r"(aR[cur][mt].y),
                      "r"(aR[cur][mt].z), "r"(aR[cur][mt].w),
                      "r"(bR[cur][nt].x), "r"(bR[cur][nt].y));
            }
    }

    unsigned* hfz = (hfrag_t >= 0)
        ? g_hfrag + (size_t)hfrag_t * BATCH * NSEQ * FD : (unsigned*)0;

    int cr = lane >> 2;
    int cc = (lane & 3) * 2;
    int bm = blockIdx.y * BM, bn = blockIdx.x * BN;
    #pragma unroll
    for (int mt = 0; mt < 4; mt++) {
        #pragma unroll
        for (int half = 0; half < 2; half++) {
            int row = bm + wm * 64 + mt * 16 + cr + half * 8;
            float* cp = C + (size_t)row * ldc + bn + wn * 32 + cc;
            #pragma unroll
            for (int nt = 0; nt < 4; nt++) {
                float2 v = make_float2(d[mt][nt][half * 2], d[mt][nt][half * 2 + 1]);
                float* p = cp + nt * 8;
                if (accum) {
                    float2 o = *(const float2*)p;
                    v.x += o.x; v.y += o.y;
                }
                *(float2*)p = v;
                if (hfz) {
                    int b = row >> 10;
                    int k = row & (NSEQ - 1);
                    unsigned* hb = hfz + (size_t)b * NSEQ * FD;
                    int col0 = bn + wn * 32 + cc + nt * 8;
                    #pragma unroll
                    for (int e = 0; e < 2; e++) {
                        int n = col0 + e;
                        int word = (((n >> 3) * (NSEQ / 8) + (k >> 3)) << 5)
                                   + ((n & 7) * 4 + (k & 3));
                        hb[word * 2 + ((k >> 2) & 1)] = cvt_tf32(e ? v.y : v.x);
                    }
                }
            }
        }
    }
}

// ---------------- f1/f2 -----------------------------------------------------
__global__ void f_kernel(const float* __restrict__ a1, const float* __restrict__ a2) {
    int gw = (blockIdx.x * blockDim.x + threadIdx.x) >> 5;
    int lane = threadIdx.x & 31;
    if (gw >= 9 * BATCH * NSEQ) return;
    int z = gw / (BATCH * NSEQ);
    const float* hp = &g_h[(size_t)gw * FD];
    const float* a1p = a1 + (size_t)z * FD;
    const float* a2p = a2 + (size_t)z * FD;
    float s1 = 0.0f, s2 = 0.0f;
    #pragma unroll
    for (int i = lane; i < FD; i += 32) {
        float hv = hp[i];
        s1 = fmaf(hv, a1p[i], s1);
        s2 = fmaf(hv, a2p[i], s2);
    }
    #pragma unroll
    for (int off = 16; off > 0; off >>= 1) {
        s1 += __shfl_down_sync(0xffffffffu, s1, off);
        s2 += __shfl_down_sync(0xffffffffu, s2, off);
    }
    if (lane == 0) { g_f1[gw] = s1; g_f2[gw] = s2; }
}

// ---------------- fused sparse softmax + SpMM (layers k=0,1) ----------------
__global__ __launch_bounds__(256) void spmm_kernel(int k, float* __restrict__ Hout) {
    int n = blockIdx.x, b = blockIdx.y;
    int tid = threadIdx.x;

    __shared__ int   list[NSEQ];
    __shared__ float pn[NSEQ];
    __shared__ int   s_cnt;
    __shared__ float red[256];

    float acc = 0.0f;

    for (int t = 0; t < NT; t++) {
        int z = t * 3 + k;
        if (tid == 0) s_cnt = 0;
        __syncthreads();
        if (tid < NWRD) {
            unsigned w = g_mask[k][(((size_t)b * NT + t) * NSEQ + n) * NWRD + tid];
            while (w) {
                int j = (tid << 5) + (__ffs(w) - 1);
                w &= w - 1;
                int p = atomicAdd(&s_cnt, 1);
                list[p] = j;
            }
        }
        __syncthreads();
        int cnt = s_cnt;

        const float* f2p = &g_f2[(size_t)z * BATCH * NSEQ + (size_t)b * NSEQ];
        float f1v = g_f1[(size_t)z * BATCH * NSEQ + (size_t)b * NSEQ + n];
        const float* hp = &g_h[((size_t)z * BATCH + b) * NSEQ * FD];

        if (cnt == 0) {
            float a = 0.0f;
            for (int j = 0; j < NSEQ; j++) a += hp[(size_t)j * FD + tid];
            acc += a * (1.0f / NSEQ);
            __syncthreads();
            continue;
        }

        float lmax = -1e30f;
        for (int i = tid; i < cnt; i += 256) {
            float x = f1v + f2p[list[i]];
            x = (x > 0.0f) ? x : ALPHAV * x;
            pn[i] = x;
            lmax = fmaxf(lmax, x);
        }
        red[tid] = lmax;
        __syncthreads();
        for (int s = 128; s > 0; s >>= 1) {
            if (tid < s) red[tid] = fmaxf(red[tid], red[tid + s]);
            __syncthreads();
        }
        float m = red[0];
        __syncthreads();

        float lsum = 0.0f;
        for (int i = tid; i < cnt; i += 256) {
            float p = __expf(pn[i] - m);
            pn[i] = p;
            lsum += p;
        }
        red[tid] = lsum;
        __syncthreads();
        for (int s = 128; s > 0; s >>= 1) {
            if (tid < s) red[tid] += red[tid + s];
            __syncthreads();
        }
        float inv = 1.0f / red[0];
        __syncthreads();

        int i = 0;
        for (; i + 4 <= cnt; i += 4) {
            int j0 = list[i], j1 = list[i + 1], j2 = list[i + 2], j3 = list[i + 3];
            float p0 = pn[i] * inv, p1 = pn[i + 1] * inv;
            float p2 = pn[i + 2] * inv, p3 = pn[i + 3] * inv;
            float h0 = hp[(size_t)j0 * FD + tid];
            float h1 = hp[(size_t)j1 * FD + tid];
            float h2 = hp[(size_t)j2 * FD + tid];
            float h3 = hp[(size_t)j3 * FD + tid];
            acc = fmaf(p0, h0, acc);
            acc = fmaf(p1, h1, acc);
            acc = fmaf(p2, h2, acc);
            acc = fmaf(p3, h3, acc);
        }
        for (; i < cnt; i++)
            acc = fmaf(pn[i] * inv, hp[(size_t)list[i] * FD + tid], acc);
        __syncthreads();
    }

    Hout[(((size_t)b * NSEQ + n) * NLAY + k) * FD + tid] = acc;
}

// ---------------- dense masked-softmax row -> A-fragments (k=2) -------------
__global__ void att_kernel(int t, int k) {
    int i = blockIdx.x, b = blockIdx.y;
    int tid = threadIdx.x;
    int z = t * 3 + k;

    __shared__ float sf2[NSEQ];
    __shared__ unsigned smask[NWRD];
    __shared__ float red[256];

    const float* f2p = &g_f2[(size_t)z * BATCH * NSEQ + (size_t)b * NSEQ];
    for (int j = tid; j < NSEQ; j += 256) sf2[j] = f2p[j];
    if (tid < NWRD)
        smask[tid] = g_mask[k][(((size_t)b * NT + t) * NSEQ + i) * NWRD + tid];
    __syncthreads();

    float f1v = g_f1[(size_t)z * BATCH * NSEQ + (size_t)b * NSEQ + i];

    float e[4];
    bool msk[4];
    float lmax = NEGV;
    #pragma unroll
    for (int q = 0; q < 4; q++) {
        int j = tid + q * 256;
        bool m = (smask[j >> 5] >> (j & 31)) & 1u;
        float x = f1v + sf2[j];
        x = (x > 0.0f) ? x : ALPHAV * x;
        e[q] = m ? x : NEGV;
        msk[q] = m;
        lmax = fmaxf(lmax, e[q]);
    }
    red[tid] = lmax;
    __syncthreads();
    for (int s = 128; s > 0; s >>= 1) {
        if (tid < s) red[tid] = fmaxf(red[tid], red[tid + s]);
        __syncthreads();
    }
    float m = red[0];
    __syncthreads();

    bool empty = (m < -8.9e15f);
    float p[4];
    float lsum = 0.0f;
    #pragma unroll
    for (int q = 0; q < 4; q++) {
        p[q] = empty ? 1.0f : (msk[q] ? __expf(e[q] - m) : 0.0f);
        lsum += p[q];
    }
    red[tid] = lsum;
    __syncthreads();
    for (int s = 128; s > 0; s >>= 1) {
        if (tid < s) red[tid] += red[tid + s];
        __syncthreads();
    }
    float inv = 1.0f / red[0];

    // write A-fragment layout: value att(i, j)
    unsigned* ab = g_attf + ((size_t)b << 20);
    int mt = i >> 4;
    int lanebase = (i & 7) * 4;
    int reghalf = (i >> 3) & 1;
    #pragma unroll
    for (int q = 0; q < 4; q++) {
        int j = tid + q * 256;
        int word = ((mt * (NSEQ / 8) + (j >> 3)) << 5) + lanebase + (j & 3);
        ab[word * 4 + reghalf + 2 * ((j >> 2) & 1)] = cvt_tf32(p[q] * inv);
    }
}

// ---------------- final combine ---------------------------------------------
__global__ void combine_kernel(const float* __restrict__ Ww, const float* __restrict__ bw,
                               const float* __restrict__ Wc, float* __restrict__ out) {
    int bn = blockIdx.x;
    int tid = threadIdx.x;
    __shared__ float sh[NLAY * FD];
    __shared__ float part[NLAY][128];
    __shared__ float sy[NLAY];

    const float* Hp = &g_H[(size_t)bn * NLAY * FD];
    for (int i = tid; i < NLAY * FD; i += 128) sh[i] = Hp[i];
    __syncthreads();

    float loc[NLAY] = {0.0f, 0.0f, 0.0f};
    if (tid < 100) {
        float wc = Wc[tid];
        float bwv = bw[tid];
        #pragma unroll
        for (int k = 0; k < NLAY; k++) {
            float y = bwv;
            #pragma unroll 8
            for (int i = 0; i < FD; i++)
                y = fmaf(sh[k * FD + i], Ww[i * 100 + tid], y);
            loc[k] = tanhf(y) * wc;
        }
    }
    #pragma unroll
    for (int k = 0; k < NLAY; k++) part[k][tid] = loc[k];
    __syncthreads();
    for (int s = 64; s > 0; s >>= 1) {
        if (tid < s) {
            part[0][tid] += part[0][tid + s];
            part[1][tid] += part[1][tid + s];
            part[2][tid] += part[2][tid + s];
        }
        __syncthreads();
    }
    if (tid == 0) {
        float s0 = part[0][0], s1 = part[1][0], s2 = part[2][0];
        float mx = fmaxf(s0, fmaxf(s1, s2));
        float e0 = __expf(s0 - mx), e1 = __expf(s1 - mx), e2 = __expf(s2 - mx);
        float invs = 1.0f / (e0 + e1 + e2);
        sy[0] = e0 * invs; sy[1] = e1 * invs; sy[2] = e2 * invs;
    }
    __syncthreads();

    float w0 = sy[0], w1 = sy[1], w2 = sy[2];
    for (int f = tid; f < FD; f += 128)
        out[(size_t)bn * FD + f] =
            w0 * sh[f] + w1 * sh[FD + f] + w2 * sh[2 * FD + f];
}

// ---------------- launch ----------------------------------------------------
extern "C" void kernel_launch(void* const* d_in, const int* in_sizes, int n_in,
                              void* d_out, int out_size) {
    const float* adj = (const float*)d_in[0];
    const float* X   = (const float*)d_in[1];
    const float* W   = (const float*)d_in[2];
    const float* a1  = (const float*)d_in[3];
    const float* a2  = (const float*)d_in[4];
    const float* Ww  = (const float*)d_in[5];
    const float* bw  = (const float*)d_in[6];
    const float* Wc  = (const float*)d_in[7];
    float* out = (float*)d_out;

    void *ph, *pH, *pxf, *pwf, *paf;
    cudaGetSymbolAddress(&ph, g_h);
    cudaGetSymbolAddress(&pH, g_H);
    cudaGetSymbolAddress(&pxf, g_xfrag);
    cudaGetSymbolAddress(&pwf, g_wfrag);
    cudaGetSymbolAddress(&paf, g_attf);
    float* hbuf = (float*)ph;
    float* Hbuf = (float*)pH;

    // 1. adjacency bitsets + boolean powers
    bits_kernel<<<BATCH * NT * NSEQ, 1024>>>(adj);
    bmm_kernel<<<BATCH * NT * NSEQ, 32>>>(0, 1);
    bmm_kernel<<<BATCH * NT * NSEQ, 32>>>(1, 2);

    // 2. pre-fragment X and W
    xfrag_kernel<<<(BATCH * NSEQ * IND / 4) / 256, 256>>>(X);
    wfrag_kernel<<<(9 * IND * FD / 2) / 256, 256>>>(W);

    // 3. h[t,k] = X @ W[t,k]; for k==2 z's also emit B-fragments of h
    for (int z = 0; z < 9; z++) {
        dim3 grid(FD / BN, (BATCH * NSEQ) / BM, 1);
        tgemm_ff<<<grid, 256>>>(
            (const unsigned*)pxf, (const unsigned*)pwf + (size_t)z * IND * FD / 2 * 2,
            hbuf + (size_t)z * BATCH * NSEQ * FD,
            IND / 8, FD, 0LL, 0LL, 0LL, 0,
            (z % 3 == 2) ? (z / 3) : -1);
    }

    // 4. f1/f2 projections
    f_kernel<<<(9 * BATCH * NSEQ) / 8, 256>>>(a1, a2);

    // 5. sparse layers k=0,1
    spmm_kernel<<<dim3(NSEQ, BATCH), 256>>>(0, Hbuf);
    spmm_kernel<<<dim3(NSEQ, BATCH), 256>>>(1, Hbuf);

    // 6. dense layer k=2: masked softmax (frag out) + fragment-direct GEMM
    void *phf;
    cudaGetSymbolAddress(&phf, g_hfrag);
    for (int t = 0; t < NT; t++) {
        att_kernel<<<dim3(NSEQ, BATCH), 256>>>(t, 2);
        dim3 grid(FD / BN, NSEQ / BM, BATCH);
        tgemm_ff<<<grid, 256>>>(
            (const unsigned*)paf,
            (const unsigned*)phf + (size_t)t * BATCH * NSEQ * FD,
            Hbuf + 2 * FD,
            NSEQ / 8, NLAY * FD,
            (long long)NSEQ * NSEQ,
            (long long)NSEQ * FD,
            (long long)NSEQ * NLAY * FD,
            t > 0 ? 1 : 0, -1);
    }

    // 7. combine
    combine_kernel<<<BATCH * NSEQ, 128>>>(Ww, bw, Wc, out);
}

// round 7
// speedup vs baseline: 1.3063x; 1.3063x over previous
#include <cuda_runtime.h>

#define BATCH 16
#define NT 3
#define NSEQ 1024
#define IND 512
#define FD 256
#define NLAY 3
#define NWRD 32
#define ALPHAV 0.2f
#define NEGV -9e15f

// ---------------- scratch (device globals; no allocations allowed) ----------
__device__ unsigned g_mask[NLAY][BATCH * NT * NSEQ * NWRD];
__device__ float g_h[(size_t)9 * BATCH * NSEQ * FD];
__device__ float g_f1[9 * BATCH * NSEQ];
__device__ float g_f2[9 * BATCH * NSEQ];
__device__ float g_att3[(size_t)NT * BATCH * NSEQ * NSEQ];   // att rows, 3 relations
__device__ float g_H[(size_t)BATCH * NSEQ * NLAY * FD];

// ---------------- adj -> bitset --------------------------------------------
__global__ void bits_kernel(const float* __restrict__ adj) {
    int r = blockIdx.x;
    int tid = threadIdx.x;
    float v = adj[(size_t)r * NSEQ + tid];
    unsigned bal = __ballot_sync(0xffffffffu, v > 0.0f);
    if ((tid & 31) == 0) g_mask[0][(size_t)r * NWRD + (tid >> 5)] = bal;
}

__global__ void bmm_kernel(int src, int dst) {
    int r = blockIdx.x;
    int bt = r / NSEQ;
    int lane = threadIdx.x;
    const unsigned* lrow = &g_mask[src][(size_t)r * NWRD];
    const unsigned* rbase = &g_mask[0][(size_t)bt * NSEQ * NWRD];
    unsigned myw = lrow[lane];
    unsigned acc = 0;
    #pragma unroll 1
    for (int w = 0; w < NWRD; ++w) {
        unsigned bitsw = __shfl_sync(0xffffffffu, myw, w);
        while (bitsw) {
            int j = (w << 5) + (__ffs(bitsw) - 1);
            bitsw &= bitsw - 1;
            acc |= rbase[(size_t)j * NWRD + lane];
        }
    }
    g_mask[dst][(size_t)r * NWRD + lane] = acc;
}

// ---------------- tf32 tensor-core GEMM (128x128, BK=16, segmented-K) -------
__device__ __forceinline__ unsigned cvt_tf32(float x) {
    unsigned r;
    asm("cvt.rna.tf32.f32 %0, %1;" : "=r"(r) : "f"(x));
    return r;
}

#define BM 128
#define BN 128
#define BK 16

// A [M,K] row-major (+ seg stride), B [K,N] row-major (+ seg stride), C [M,N].
// Accumulates over nseg segments in registers.
__global__ __launch_bounds__(256) void tgemm(
    const float* __restrict__ A, const float* __restrict__ Bm, float* __restrict__ C,
    int Kk, int lda, int ldb, int ldc,
    long long sA, long long sB, long long sC,
    long long sAseg, long long sBseg, int nseg)
{
    int z = blockIdx.z;
    A  += (size_t)z * sA;
    Bm += (size_t)z * sB;
    C  += (size_t)z * sC;

    __shared__ unsigned Asm[2][2][8][32][4];
    __shared__ unsigned Bsm[2][2][16][32][2];

    int tid = threadIdx.x;
    int lane = tid & 31;
    int wid = tid >> 5;
    int wm = wid >> 2;
    int wn = wid & 3;

    int bm = blockIdx.y * BM, bn = blockIdx.x * BN;

    int lane4 = lane >> 2;
    int lanek = lane & 3;

    const float* Arow0 = A + (size_t)(bm + wid * 16 + lane4) * lda + lanek;
    const float* Arow8 = Arow0 + (size_t)8 * lda;
    int bkt = wid >> 2;
    int bnt0 = (wid & 3) * 4;
    const float* Bbase = Bm + (size_t)(bkt * 8 + lanek) * ldb + bn + lane4;

    float d[4][4][4];
    #pragma unroll
    for (int i = 0; i < 4; i++)
        #pragma unroll
        for (int j = 0; j < 4; j++)
            #pragma unroll
            for (int r = 0; r < 4; r++) d[i][j][r] = 0.0f;

    float av[2][4];
    float bv[4][2];

    #define LOAD_GLOBAL(aofs, bofs, koff)                                    \
        {                                                                    \
            _Pragma("unroll")                                                \
            for (int q = 0; q < 2; q++) {                                    \
                long long kk = (long long)(koff) + q * 8;                    \
                av[q][0] = Arow0[(aofs) + kk];                               \
                av[q][1] = Arow8[(aofs) + kk];                               \
                av[q][2] = Arow0[(aofs) + kk + 4];                           \
                av[q][3] = Arow8[(aofs) + kk + 4];                           \
            }                                                                \
            _Pragma("unroll")                                                \
            for (int f = 0; f < 4; f++) {                                    \
                const float* bp = Bbase + (bofs) + (size_t)(koff) * ldb      \
                                  + (bnt0 + f) * 8;                          \
                bv[f][0] = bp[0];                                            \
                bv[f][1] = bp[(size_t)4 * ldb];                              \
            }                                                                \
        }

    #define STORE_STAGE(st)                                                  \
        {                                                                    \
            _Pragma("unroll")                                                \
            for (int q = 0; q < 2; q++) {                                    \
                uint4 t;                                                     \
                t.x = cvt_tf32(av[q][0]); t.y = cvt_tf32(av[q][1]);          \
                t.z = cvt_tf32(av[q][2]); t.w = cvt_tf32(av[q][3]);          \
                *(uint4*)(&Asm[st][q][wid][lane][0]) = t;                    \
            }                                                                \
            _Pragma("unroll")                                                \
            for (int f = 0; f < 4; f++) {                                    \
                uint2 t;                                                     \
                t.x = cvt_tf32(bv[f][0]); t.y = cvt_tf32(bv[f][1]);          \
                *(uint2*)(&Bsm[st][bkt][bnt0 + f][lane][0]) = t;             \
            }                                                                \
        }

    int kiter = Kk >> 4;
    int total = nseg * kiter;

    LOAD_GLOBAL(0LL, 0LL, 0);
    STORE_STAGE(0);
    __syncthreads();

    long long aso = 0, bso = 0;
    int kc_n = 0;
    for (int c = 0; c < total; c++) {
        int cur = c & 1;
        bool more = (c + 1 < total);
        if (more) {
            if (++kc_n == kiter) { kc_n = 0; aso += sAseg; bso += sBseg; }
            LOAD_GLOBAL(aso, bso, kc_n * BK);
        }
        #pragma unroll
        for (int kt = 0; kt < 2; kt++) {
            unsigned af[4][4];
            unsigned bf[4][2];
            #pragma unroll
            for (int mt = 0; mt < 4; mt++) {
                uint4 t = *(const uint4*)(&Asm[cur][kt][wm * 4 + mt][lane][0]);
                af[mt][0] = t.x; af[mt][1] = t.y; af[mt][2] = t.z; af[mt][3] = t.w;
            }
            #pragma unroll
            for (int nt = 0; nt < 4; nt++) {
                uint2 t = *(const uint2*)(&Bsm[cur][kt][wn * 4 + nt][lane][0]);
                bf[nt][0] = t.x; bf[nt][1] = t.y;
            }
            #pragma unroll
            for (int mt = 0; mt < 4; mt++)
                #pragma unroll
                for (int nt = 0; nt < 4; nt++) {
                    asm volatile(
                        "mma.sync.aligned.m16n8k8.row.col.f32.tf32.tf32.f32 "
                        "{%0,%1,%2,%3}, {%4,%5,%6,%7}, {%8,%9}, {%0,%1,%2,%3};"
                        : "+f"(d[mt][nt][0]), "+f"(d[mt][nt][1]),
                          "+f"(d[mt][nt][2]), "+f"(d[mt][nt][3])
                        : "r"(af[mt][0]), "r"(af[mt][1]),
                          "r"(af[mt][2]), "r"(af[mt][3]),
                          "r"(bf[nt][0]), "r"(bf[nt][1]));
                }
        }
        if (more) {
            __syncthreads();
            STORE_STAGE(cur ^ 1);
            __syncthreads();
        }
    }

    int cr = lane >> 2;
    int cc = (lane & 3) * 2;
    #pragma unroll
    for (int mt = 0; mt < 4; mt++) {
        #pragma unroll
        for (int half = 0; half < 2; half++) {
            int row = bm + wm * 64 + mt * 16 + cr + half * 8;
            float* cp = C + (size_t)row * ldc + bn + wn * 32 + cc;
            #pragma unroll
            for (int nt = 0; nt < 4; nt++) {
                float2 v = make_float2(d[mt][nt][half * 2], d[mt][nt][half * 2 + 1]);
                *(float2*)(cp + nt * 8) = v;
            }
        }
    }
}

// ---------------- f1/f2 -----------------------------------------------------
__global__ void f_kernel(const float* __restrict__ a1, const float* __restrict__ a2) {
    int gw = (blockIdx.x * blockDim.x + threadIdx.x) >> 5;
    int lane = threadIdx.x & 31;
    if (gw >= 9 * BATCH * NSEQ) return;
    int z = gw / (BATCH * NSEQ);
    const float* hp = &g_h[(size_t)gw * FD];
    const float* a1p = a1 + (size_t)z * FD;
    const float* a2p = a2 + (size_t)z * FD;
    float s1 = 0.0f, s2 = 0.0f;
    #pragma unroll
    for (int i = lane; i < FD; i += 32) {
        float hv = hp[i];
        s1 = fmaf(hv, a1p[i], s1);
        s2 = fmaf(hv, a2p[i], s2);
    }
    #pragma unroll
    for (int off = 16; off > 0; off >>= 1) {
        s1 += __shfl_down_sync(0xffffffffu, s1, off);
        s2 += __shfl_down_sync(0xffffffffu, s2, off);
    }
    if (lane == 0) { g_f1[gw] = s1; g_f2[gw] = s2; }
}

// ---------------- fused sparse softmax + SpMM (layer k=0 only) --------------
__global__ __launch_bounds__(256) void spmm_kernel(int k, float* __restrict__ Hout) {
    int n = blockIdx.x, b = blockIdx.y;
    int tid = threadIdx.x;

    __shared__ int   list[NSEQ];
    __shared__ float pn[NSEQ];
    __shared__ int   s_cnt;
    __shared__ float red[256];

    float acc = 0.0f;

    for (int t = 0; t < NT; t++) {
        int z = t * 3 + k;
        if (tid == 0) s_cnt = 0;
        __syncthreads();
        if (tid < NWRD) {
            unsigned w = g_mask[k][(((size_t)b * NT + t) * NSEQ + n) * NWRD + tid];
            while (w) {
                int j = (tid << 5) + (__ffs(w) - 1);
                w &= w - 1;
                int p = atomicAdd(&s_cnt, 1);
                list[p] = j;
            }
        }
        __syncthreads();
        int cnt = s_cnt;

        const float* f2p = &g_f2[(size_t)z * BATCH * NSEQ + (size_t)b * NSEQ];
        float f1v = g_f1[(size_t)z * BATCH * NSEQ + (size_t)b * NSEQ + n];
        const float* hp = &g_h[((size_t)z * BATCH + b) * NSEQ * FD];

        if (cnt == 0) {
            float a = 0.0f;
            for (int j = 0; j < NSEQ; j++) a += hp[(size_t)j * FD + tid];
            acc += a * (1.0f / NSEQ);
            __syncthreads();
            continue;
        }

        float lmax = -1e30f;
        for (int i = tid; i < cnt; i += 256) {
            float x = f1v + f2p[list[i]];
            x = (x > 0.0f) ? x : ALPHAV * x;
            pn[i] = x;
            lmax = fmaxf(lmax, x);
        }
        red[tid] = lmax;
        __syncthreads();
        for (int s = 128; s > 0; s >>= 1) {
            if (tid < s) red[tid] = fmaxf(red[tid], red[tid + s]);
            __syncthreads();
        }
        float m = red[0];
        __syncthreads();

        float lsum = 0.0f;
        for (int i = tid; i < cnt; i += 256) {
            float p = __expf(pn[i] - m);
            pn[i] = p;
            lsum += p;
        }
        red[tid] = lsum;
        __syncthreads();
        for (int s = 128; s > 0; s >>= 1) {
            if (tid < s) red[tid] += red[tid + s];
            __syncthreads();
        }
        float inv = 1.0f / red[0];
        __syncthreads();

        int i = 0;
        for (; i + 4 <= cnt; i += 4) {
            int j0 = list[i], j1 = list[i + 1], j2 = list[i + 2], j3 = list[i + 3];
            float p0 = pn[i] * inv, p1 = pn[i + 1] * inv;
            float p2 = pn[i + 2] * inv, p3 = pn[i + 3] * inv;
            float h0 = hp[(size_t)j0 * FD + tid];
            float h1 = hp[(size_t)j1 * FD + tid];
            float h2 = hp[(size_t)j2 * FD + tid];
            float h3 = hp[(size_t)j3 * FD + tid];
            acc = fmaf(p0, h0, acc);
            acc = fmaf(p1, h1, acc);
            acc = fmaf(p2, h2, acc);
            acc = fmaf(p3, h3, acc);
        }
        for (; i < cnt; i++)
            acc = fmaf(pn[i] * inv, hp[(size_t)list[i] * FD + tid], acc);
        __syncthreads();
    }

    Hout[(((size_t)b * NSEQ + n) * NLAY + k) * FD + tid] = acc;
}

// ---------------- dense masked-softmax attention row ------------------------
__global__ void att_kernel(int t, int k) {
    int i = blockIdx.x, b = blockIdx.y;
    int tid = threadIdx.x;
    int z = t * 3 + k;

    __shared__ float sf2[NSEQ];
    __shared__ unsigned smask[NWRD];
    __shared__ float red[256];

    const float* f2p = &g_f2[(size_t)z * BATCH * NSEQ + (size_t)b * NSEQ];
    for (int j = tid; j < NSEQ; j += 256) sf2[j] = f2p[j];
    if (tid < NWRD)
        smask[tid] = g_mask[k][(((size_t)b * NT + t) * NSEQ + i) * NWRD + tid];
    __syncthreads();

    float f1v = g_f1[(size_t)z * BATCH * NSEQ + (size_t)b * NSEQ + i];

    float e[4];
    bool msk[4];
    float lmax = NEGV;
    #pragma unroll
    for (int q = 0; q < 4; q++) {
        int j = tid + q * 256;
        bool m = (smask[j >> 5] >> (j & 31)) & 1u;
        float x = f1v + sf2[j];
        x = (x > 0.0f) ? x : ALPHAV * x;
        e[q] = m ? x : NEGV;
        msk[q] = m;
        lmax = fmaxf(lmax, e[q]);
    }
    red[tid] = lmax;
    __syncthreads();
    for (int s = 128; s > 0; s >>= 1) {
        if (tid < s) red[tid] = fmaxf(red[tid], red[tid + s]);
        __syncthreads();
    }
    float m = red[0];
    __syncthreads();

    bool empty = (m < -8.9e15f);
    float p[4];
    float lsum = 0.0f;
    #pragma unroll
    for (int q = 0; q < 4; q++) {
        p[q] = empty ? 1.0f : (msk[q] ? __expf(e[q] - m) : 0.0f);
        lsum += p[q];
    }
    red[tid] = lsum;
    __syncthreads();
    for (int s = 128; s > 0; s >>= 1) {
        if (tid < s) red[tid] += red[tid + s];
        __syncthreads();
    }
    float inv = 1.0f / red[0];

    float* arow = &g_att3[(((size_t)t * BATCH + b) * NSEQ + i) * NSEQ];
    #pragma unroll
    for (int q = 0; q < 4; q++) arow[tid + q * 256] = p[q] * inv;
}

// ---------------- final combine ---------------------------------------------
__global__ void combine_kernel(const float* __restrict__ Ww, const float* __restrict__ bw,
                               const float* __restrict__ Wc, float* __restrict__ out) {
    int bn = blockIdx.x;
    int tid = threadIdx.x;
    __shared__ float sh[NLAY * FD];
    __shared__ float part[NLAY][128];
    __shared__ float sy[NLAY];

    const float* Hp = &g_H[(size_t)bn * NLAY * FD];
    for (int i = tid; i < NLAY * FD; i += 128) sh[i] = Hp[i];
    __syncthreads();

    float loc[NLAY] = {0.0f, 0.0f, 0.0f};
    if (tid < 100) {
        float wc = Wc[tid];
        float bwv = bw[tid];
        #pragma unroll
        for (int k = 0; k < NLAY; k++) {
            float y = bwv;
            #pragma unroll 8
            for (int i = 0; i < FD; i++)
                y = fmaf(sh[k * FD + i], Ww[i * 100 + tid], y);
            loc[k] = tanhf(y) * wc;
        }
    }
    #pragma unroll
    for (int k = 0; k < NLAY; k++) part[k][tid] = loc[k];
    __syncthreads();
    for (int s = 64; s > 0; s >>= 1) {
        if (tid < s) {
            part[0][tid] += part[0][tid + s];
            part[1][tid] += part[1][tid + s];
            part[2][tid] += part[2][tid + s];
        }
        __syncthreads();
    }
    if (tid == 0) {
        float s0 = part[0][0], s1 = part[1][0], s2 = part[2][0];
        float mx = fmaxf(s0, fmaxf(s1, s2));
        float e0 = __expf(s0 - mx), e1 = __expf(s1 - mx), e2 = __expf(s2 - mx);
        float invs = 1.0f / (e0 + e1 + e2);
        sy[0] = e0 * invs; sy[1] = e1 * invs; sy[2] = e2 * invs;
    }
    __syncthreads();

    float w0 = sy[0], w1 = sy[1], w2 = sy[2];
    for (int f = tid; f < FD; f += 128)
        out[(size_t)bn * FD + f] =
            w0 * sh[f] + w1 * sh[FD + f] + w2 * sh[2 * FD + f];
}

// ---------------- launch ----------------------------------------------------
extern "C" void kernel_launch(void* const* d_in, const int* in_sizes, int n_in,
                              void* d_out, int out_size) {
    const float* adj = (const float*)d_in[0];
    const float* X   = (const float*)d_in[1];
    const float* W   = (const float*)d_in[2];
    const float* a1  = (const float*)d_in[3];
    const float* a2  = (const float*)d_in[4];
    const float* Ww  = (const float*)d_in[5];
    const float* bw  = (const float*)d_in[6];
    const float* Wc  = (const float*)d_in[7];
    float* out = (float*)d_out;

    void *ph, *pH, *pa3;
    cudaGetSymbolAddress(&ph, g_h);
    cudaGetSymbolAddress(&pH, g_H);
    cudaGetSymbolAddress(&pa3, g_att3);
    float* hbuf = (float*)ph;
    float* Hbuf = (float*)pH;
    float* att3 = (float*)pa3;

    // 1. adjacency bitsets + boolean powers
    bits_kernel<<<BATCH * NT * NSEQ, 1024>>>(adj);
    bmm_kernel<<<BATCH * NT * NSEQ, 32>>>(0, 1);
    bmm_kernel<<<BATCH * NT * NSEQ, 32>>>(1, 2);

    // 2. h[t,k] = X @ W[t,k]  for all 9 (t,k)
    {
        dim3 grid(FD / BN, (BATCH * NSEQ) / BM, 9);
        tgemm<<<grid, 256>>>(X, W, hbuf,
                             IND, IND, FD, FD,
                             0LL, (long long)IND * FD,
                             (long long)BATCH * NSEQ * FD,
                             0LL, 0LL, 1);
    }

    // 3. f1/f2 projections
    f_kernel<<<(9 * BATCH * NSEQ) / 8, 256>>>(a1, a2);

    // 4. sparse layer k=0
    spmm_kernel<<<dim3(NSEQ, BATCH), 256>>>(0, Hbuf);

    // 5/6. dense layers k=1,2: masked softmax rows + one segmented-K GEMM each
    for (int k = 1; k < NLAY; k++) {
        for (int t = 0; t < NT; t++)
            att_kernel<<<dim3(NSEQ, BATCH), 256>>>(t, k);
        dim3 grid(FD / BN, NSEQ / BM, BATCH);
        tgemm<<<grid, 256>>>(
            att3,
            hbuf + (size_t)k * BATCH * NSEQ * FD,   // z = 0*3+k, t stride below
            Hbuf + k * FD,
            NSEQ, NSEQ, FD, NLAY * FD,
            (long long)NSEQ * NSEQ,                 // A batch stride (b)
            (long long)NSEQ * FD,                   // B batch stride (b)
            (long long)NSEQ * NLAY * FD,            // C batch stride (b)
            (long long)BATCH * NSEQ * NSEQ,         // A segment stride (t)
            (long long)3 * BATCH * NSEQ * FD,       // B segment stride (t)
            NT);
    }

    // 7. combine
    combine_kernel<<<BATCH * NSEQ, 128>>>(Ww, bw, Wc, out);
}

// round 8
// speedup vs baseline: 1.4741x; 1.1285x over previous
#include <cuda_runtime.h>
#include <cuda_fp16.h>
#include <cstdint>

#define BATCH 16
#define NT 3
#define NSEQ 1024
#define IND 512
#define FD 256
#define NLAY 3
#define NWRD 32
#define ALPHAV 0.2f
#define NEGV -9e15f

// ---------------- scratch (device globals; no allocations allowed) ----------
__device__ unsigned g_mask[NLAY][BATCH * NT * NSEQ * NWRD];
__device__ float g_h[(size_t)9 * BATCH * NSEQ * FD];
__device__ float g_f1[9 * BATCH * NSEQ];
__device__ float g_f2[9 * BATCH * NSEQ];
__device__ __half g_att3h[(size_t)2 * NT * BATCH * NSEQ * NSEQ];  // [kk][t][b][i][j]
__device__ float g_H[(size_t)BATCH * NSEQ * NLAY * FD];

// ---------------- adj -> bitset --------------------------------------------
__global__ void bits_kernel(const float* __restrict__ adj) {
    int r = blockIdx.x;
    int tid = threadIdx.x;
    float v = adj[(size_t)r * NSEQ + tid];
    unsigned bal = __ballot_sync(0xffffffffu, v > 0.0f);
    if ((tid & 31) == 0) g_mask[0][(size_t)r * NWRD + (tid >> 5)] = bal;
}

__global__ void bmm_kernel(int src, int dst) {
    int r = blockIdx.x;
    int bt = r / NSEQ;
    int lane = threadIdx.x;
    const unsigned* lrow = &g_mask[src][(size_t)r * NWRD];
    const unsigned* rbase = &g_mask[0][(size_t)bt * NSEQ * NWRD];
    unsigned myw = lrow[lane];
    unsigned acc = 0;
    #pragma unroll 1
    for (int w = 0; w < NWRD; ++w) {
        unsigned bitsw = __shfl_sync(0xffffffffu, myw, w);
        while (bitsw) {
            int j = (w << 5) + (__ffs(bitsw) - 1);
            bitsw &= bitsw - 1;
            acc |= rbase[(size_t)j * NWRD + lane];
        }
    }
    g_mask[dst][(size_t)r * NWRD + lane] = acc;
}

// ---------------- fp16 tensor-core GEMM (128x128, BK=16, segmented-K) -------
#define BM 128
#define BN 128

__device__ __forceinline__ unsigned packh2(float a, float b) {
    __half2 h = __floats2half2_rn(a, b);
    return *(unsigned*)&h;
}

// A [M,K] row-major (fp32 or fp16), B [K,N] row-major fp32, C [M,N] fp32.
// Accumulates over nseg segments in registers.
template <bool AHALF>
__global__ __launch_bounds__(256) void tgemm16(
    const void* __restrict__ Avoid, const float* __restrict__ Bm, float* __restrict__ C,
    int Kk, int lda, int ldb, int ldc,
    long long sA, long long sB, long long sC,
    long long sAseg, long long sBseg, int nseg)
{
    int z = blockIdx.z;
    Bm += (size_t)z * sB;
    C  += (size_t)z * sC;

    __shared__ unsigned Asm[2][8][32][4];    // [stage][mtile][lane][reg]
    __shared__ unsigned Bsm[2][16][32][2];   // [stage][ntile][lane][reg]

    int tid = threadIdx.x;
    int lane = tid & 31;
    int wid = tid >> 5;
    int wm = wid >> 2;
    int wn = wid & 3;

    int bm = blockIdx.y * BM, bn = blockIdx.x * BN;

    int lane4 = lane >> 2;      // row-in-group / n-in-tile
    int k0 = (lane & 3) * 2;    // fragment k pair base

    // A staging: warp wid stages mtile wid
    int aRow = bm + wid * 16 + lane4;
    const float* ApF0 = 0; const float* ApF8 = 0;
    const __half* ApH0 = 0; const __half* ApH8 = 0;
    if (AHALF) {
        const __half* Ah = (const __half*)Avoid + (size_t)z * sA;
        ApH0 = Ah + (size_t)aRow * lda + k0;
        ApH8 = ApH0 + (size_t)8 * lda;
    } else {
        const float* Af = (const float*)Avoid + (size_t)z * sA;
        ApF0 = Af + (size_t)aRow * lda + k0;
        ApF8 = ApF0 + (size_t)8 * lda;
    }
    // B staging: warp wid stages ntiles 2*wid, 2*wid+1
    const float* Bbase = Bm + (size_t)k0 * ldb + bn + wid * 16 + lane4;

    float d[4][4][4];
    #pragma unroll
    for (int i = 0; i < 4; i++)
        #pragma unroll
        for (int j = 0; j < 4; j++)
            #pragma unroll
            for (int r = 0; r < 4; r++) d[i][j][r] = 0.0f;

    unsigned ar[4];
    unsigned br[2][2];

    #define LOAD_GLOBAL(aofs, bofs, koff)                                      \
        {                                                                      \
            if (AHALF) {                                                       \
                ar[0] = *(const unsigned*)(ApH0 + (aofs) + (koff));            \
                ar[1] = *(const unsigned*)(ApH8 + (aofs) + (koff));            \
                ar[2] = *(const unsigned*)(ApH0 + (aofs) + (koff) + 8);        \
                ar[3] = *(const unsigned*)(ApH8 + (aofs) + (koff) + 8);        \
            } else {                                                           \
                float2 v0 = *(const float2*)(ApF0 + (aofs) + (koff));          \
                float2 v1 = *(const float2*)(ApF8 + (aofs) + (koff));          \
                float2 v2 = *(const float2*)(ApF0 + (aofs) + (koff) + 8);      \
                float2 v3 = *(const float2*)(ApF8 + (aofs) + (koff) + 8);      \
                ar[0] = packh2(v0.x, v0.y);                                    \
                ar[1] = packh2(v1.x, v1.y);                                    \
                ar[2] = packh2(v2.x, v2.y);                                    \
                ar[3] = packh2(v3.x, v3.y);                                    \
            }                                                                  \
            _Pragma("unroll")                                                  \
            for (int f = 0; f < 2; f++) {                                      \
                const float* bp = Bbase + (bofs) + (size_t)(koff) * ldb + f * 8; \
                br[f][0] = packh2(bp[0], bp[ldb]);                             \
                br[f][1] = packh2(bp[(size_t)8 * ldb], bp[(size_t)9 * ldb]);   \
            }                                                                  \
        }

    #define STORE_STAGE(st)                                                    \
        {                                                                      \
            *(uint4*)(&Asm[st][wid][lane][0]) =                                \
                make_uint4(ar[0], ar[1], ar[2], ar[3]);                        \
            *(uint2*)(&Bsm[st][2 * wid][lane][0]) = make_uint2(br[0][0], br[0][1]); \
            *(uint2*)(&Bsm[st][2 * wid + 1][lane][0]) = make_uint2(br[1][0], br[1][1]); \
        }

    int kiter = Kk >> 4;
    int total = nseg * kiter;

    LOAD_GLOBAL(0LL, 0LL, 0);
    STORE_STAGE(0);
    __syncthreads();

    long long aso = 0, bso = 0;
    int kc_n = 0;
    for (int c = 0; c < total; c++) {
        int cur = c & 1;
        bool more = (c + 1 < total);
        if (more) {
            if (++kc_n == kiter) { kc_n = 0; aso += sAseg; bso += sBseg; }
            LOAD_GLOBAL(aso, bso, kc_n * 16);
        }
        unsigned af[4][4];
        unsigned bf[4][2];
        #pragma unroll
        for (int mt = 0; mt < 4; mt++) {
            uint4 t = *(const uint4*)(&Asm[cur][wm * 4 + mt][lane][0]);
            af[mt][0] = t.x; af[mt][1] = t.y; af[mt][2] = t.z; af[mt][3] = t.w;
        }
        #pragma unroll
        for (int nt = 0; nt < 4; nt++) {
            uint2 t = *(const uint2*)(&Bsm[cur][wn * 4 + nt][lane][0]);
            bf[nt][0] = t.x; bf[nt][1] = t.y;
        }
        #pragma unroll
        for (int mt = 0; mt < 4; mt++)
            #pragma unroll
            for (int nt = 0; nt < 4; nt++) {
                asm volatile(
                    "mma.sync.aligned.m16n8k16.row.col.f32.f16.f16.f32 "
                    "{%0,%1,%2,%3}, {%4,%5,%6,%7}, {%8,%9}, {%0,%1,%2,%3};"
                    : "+f"(d[mt][nt][0]), "+f"(d[mt][nt][1]),
                      "+f"(d[mt][nt][2]), "+f"(d[mt][nt][3])
                    : "r"(af[mt][0]), "r"(af[mt][1]),
                      "r"(af[mt][2]), "r"(af[mt][3]),
                      "r"(bf[nt][0]), "r"(bf[nt][1]));
            }
        if (more) {
            __syncthreads();
            STORE_STAGE(cur ^ 1);
            __syncthreads();
        }
    }

    int cr = lane >> 2;
    int cc = (lane & 3) * 2;
    #pragma unroll
    for (int mt = 0; mt < 4; mt++) {
        #pragma unroll
        for (int half = 0; half < 2; half++) {
            int row = bm + wm * 64 + mt * 16 + cr + half * 8;
            float* cp = C + (size_t)row * ldc + bn + wn * 32 + cc;
            #pragma unroll
            for (int nt = 0; nt < 4; nt++) {
                float2 v = make_float2(d[mt][nt][half * 2], d[mt][nt][half * 2 + 1]);
                *(float2*)(cp + nt * 8) = v;
            }
        }
    }
}

// ---------------- f1/f2 -----------------------------------------------------
__global__ void f_kernel(const float* __restrict__ a1, const float* __restrict__ a2) {
    int gw = (blockIdx.x * blockDim.x + threadIdx.x) >> 5;
    int lane = threadIdx.x & 31;
    if (gw >= 9 * BATCH * NSEQ) return;
    int z = gw / (BATCH * NSEQ);
    const float* hp = &g_h[(size_t)gw * FD];
    const float* a1p = a1 + (size_t)z * FD;
    const float* a2p = a2 + (size_t)z * FD;
    float s1 = 0.0f, s2 = 0.0f;
    #pragma unroll
    for (int i = lane; i < FD; i += 32) {
        float hv = hp[i];
        s1 = fmaf(hv, a1p[i], s1);
        s2 = fmaf(hv, a2p[i], s2);
    }
    #pragma unroll
    for (int off = 16; off > 0; off >>= 1) {
        s1 += __shfl_down_sync(0xffffffffu, s1, off);
        s2 += __shfl_down_sync(0xffffffffu, s2, off);
    }
    if (lane == 0) { g_f1[gw] = s1; g_f2[gw] = s2; }
}

// ---------------- fused sparse softmax + SpMM (layer k=0 only) --------------
__global__ __launch_bounds__(256) void spmm_kernel(int k, float* __restrict__ Hout) {
    int n = blockIdx.x, b = blockIdx.y;
    int tid = threadIdx.x;

    __shared__ int   list[NSEQ];
    __shared__ float pn[NSEQ];
    __shared__ int   s_cnt;
    __shared__ float red[256];

    float acc = 0.0f;

    for (int t = 0; t < NT; t++) {
        int z = t * 3 + k;
        if (tid == 0) s_cnt = 0;
        __syncthreads();
        if (tid < NWRD) {
            unsigned w = g_mask[k][(((size_t)b * NT + t) * NSEQ + n) * NWRD + tid];
            while (w) {
                int j = (tid << 5) + (__ffs(w) - 1);
                w &= w - 1;
                int p = atomicAdd(&s_cnt, 1);
                list[p] = j;
            }
        }
        __syncthreads();
        int cnt = s_cnt;

        const float* f2p = &g_f2[(size_t)z * BATCH * NSEQ + (size_t)b * NSEQ];
        float f1v = g_f1[(size_t)z * BATCH * NSEQ + (size_t)b * NSEQ + n];
        const float* hp = &g_h[((size_t)z * BATCH + b) * NSEQ * FD];

        if (cnt == 0) {
            float a = 0.0f;
            for (int j = 0; j < NSEQ; j++) a += hp[(size_t)j * FD + tid];
            acc += a * (1.0f / NSEQ);
            __syncthreads();
            continue;
        }

        float lmax = -1e30f;
        for (int i = tid; i < cnt; i += 256) {
            float x = f1v + f2p[list[i]];
            x = (x > 0.0f) ? x : ALPHAV * x;
            pn[i] = x;
            lmax = fmaxf(lmax, x);
        }
        red[tid] = lmax;
        __syncthreads();
        for (int s = 128; s > 0; s >>= 1) {
            if (tid < s) red[tid] = fmaxf(red[tid], red[tid + s]);
            __syncthreads();
        }
        float m = red[0];
        __syncthreads();

        float lsum = 0.0f;
        for (int i = tid; i < cnt; i += 256) {
            float p = __expf(pn[i] - m);
            pn[i] = p;
            lsum += p;
        }
        red[tid] = lsum;
        __syncthreads();
        for (int s = 128; s > 0; s >>= 1) {
            if (tid < s) red[tid] += red[tid + s];
            __syncthreads();
        }
        float inv = 1.0f / red[0];
        __syncthreads();

        int i = 0;
        for (; i + 4 <= cnt; i += 4) {
            int j0 = list[i], j1 = list[i + 1], j2 = list[i + 2], j3 = list[i + 3];
            float p0 = pn[i] * inv, p1 = pn[i + 1] * inv;
            float p2 = pn[i + 2] * inv, p3 = pn[i + 3] * inv;
            float h0 = hp[(size_t)j0 * FD + tid];
            float h1 = hp[(size_t)j1 * FD + tid];
            float h2 = hp[(size_t)j2 * FD + tid];
            float h3 = hp[(size_t)j3 * FD + tid];
            acc = fmaf(p0, h0, acc);
            acc = fmaf(p1, h1, acc);
            acc = fmaf(p2, h2, acc);
            acc = fmaf(p3, h3, acc);
        }
        for (; i < cnt; i++)
            acc = fmaf(pn[i] * inv, hp[(size_t)list[i] * FD + tid], acc);
        __syncthreads();
    }

    Hout[(((size_t)b * NSEQ + n) * NLAY + k) * FD + tid] = acc;
}

// ---------------- dense masked-softmax attention rows (k=1,2 merged) --------
// grid (NSEQ, BATCH, 6): zz -> t = zz%3, k = 1 + zz/3. Writes fp16 rows.
__global__ __launch_bounds__(256) void att_kernel(void) {
    int i = blockIdx.x, b = blockIdx.y, zz = blockIdx.z;
    int t = zz % 3, kk = zz / 3, k = kk + 1;
    int tid = threadIdx.x;
    int lane = tid & 31, wid = tid >> 5;
    int z = t * 3 + k;

    __shared__ float sf2[NSEQ];
    __shared__ unsigned smask[NWRD];
    __shared__ float redmax[8];
    __shared__ float redsum[8];

    const float* f2p = &g_f2[(size_t)z * BATCH * NSEQ + (size_t)b * NSEQ];
    for (int j = tid; j < NSEQ; j += 256) sf2[j] = f2p[j];
    if (tid < NWRD)
        smask[tid] = g_mask[k][(((size_t)b * NT + t) * NSEQ + i) * NWRD + tid];
    __syncthreads();

    float f1v = g_f1[(size_t)z * BATCH * NSEQ + (size_t)b * NSEQ + i];

    float e[4];
    bool msk[4];
    float lmax = NEGV;
    #pragma unroll
    for (int q = 0; q < 4; q++) {
        int j = tid + q * 256;
        bool m = (smask[j >> 5] >> (j & 31)) & 1u;
        float x = f1v + sf2[j];
        x = (x > 0.0f) ? x : ALPHAV * x;
        e[q] = m ? x : NEGV;
        msk[q] = m;
        lmax = fmaxf(lmax, e[q]);
    }
    #pragma unroll
    for (int off = 16; off > 0; off >>= 1)
        lmax = fmaxf(lmax, __shfl_xor_sync(0xffffffffu, lmax, off));
    if (lane == 0) redmax[wid] = lmax;
    __syncthreads();
    float m = redmax[0];
    #pragma unroll
    for (int w = 1; w < 8; w++) m = fmaxf(m, redmax[w]);

    bool empty = (m < -8.9e15f);
    float p[4];
    float lsum = 0.0f;
    #pragma unroll
    for (int q = 0; q < 4; q++) {
        p[q] = empty ? 1.0f : (msk[q] ? __expf(e[q] - m) : 0.0f);
        lsum += p[q];
    }
    #pragma unroll
    for (int off = 16; off > 0; off >>= 1)
        lsum += __shfl_xor_sync(0xffffffffu, lsum, off);
    if (lane == 0) redsum[wid] = lsum;
    __syncthreads();
    float s = 0.0f;
    #pragma unroll
    for (int w = 0; w < 8; w++) s += redsum[w];
    float inv = 1.0f / s;

    __half* arow = &g_att3h[((((size_t)kk * NT + t) * BATCH + b) * NSEQ + i) * NSEQ];
    #pragma unroll
    for (int q = 0; q < 2; q++) {
        int j = tid * 2 + q * 512;
        // re-map: each thread wrote e/p for indices tid + q*256; instead store
        // pairwise for vectorized half2 write via shuffle of neighbor value.
        (void)j;
    }
    #pragma unroll
    for (int q = 0; q < 4; q++)
        arow[tid + q * 256] = __float2half(p[q] * inv);
}

// ---------------- final combine ---------------------------------------------
__global__ void combine_kernel(const float* __restrict__ Ww, const float* __restrict__ bw,
                               const float* __restrict__ Wc, float* __restrict__ out) {
    int bn = blockIdx.x;
    int tid = threadIdx.x;
    __shared__ float sh[NLAY * FD];
    __shared__ float part[NLAY][128];
    __shared__ float sy[NLAY];

    const float* Hp = &g_H[(size_t)bn * NLAY * FD];
    for (int i = tid; i < NLAY * FD; i += 128) sh[i] = Hp[i];
    __syncthreads();

    float loc[NLAY] = {0.0f, 0.0f, 0.0f};
    if (tid < 100) {
        float wc = Wc[tid];
        float bwv = bw[tid];
        #pragma unroll
        for (int k = 0; k < NLAY; k++) {
            float y = bwv;
            #pragma unroll 8
            for (int i = 0; i < FD; i++)
                y = fmaf(sh[k * FD + i], Ww[i * 100 + tid], y);
            loc[k] = tanhf(y) * wc;
        }
    }
    #pragma unroll
    for (int k = 0; k < NLAY; k++) part[k][tid] = loc[k];
    __syncthreads();
    for (int s = 64; s > 0; s >>= 1) {
        if (tid < s) {
            part[0][tid] += part[0][tid + s];
            part[1][tid] += part[1][tid + s];
            part[2][tid] += part[2][tid + s];
        }
        __syncthreads();
    }
    if (tid == 0) {
        float s0 = part[0][0], s1 = part[1][0], s2 = part[2][0];
        float mx = fmaxf(s0, fmaxf(s1, s2));
        float e0 = __expf(s0 - mx), e1 = __expf(s1 - mx), e2 = __expf(s2 - mx);
        float invs = 1.0f / (e0 + e1 + e2);
        sy[0] = e0 * invs; sy[1] = e1 * invs; sy[2] = e2 * invs;
    }
    __syncthreads();

    float w0 = sy[0], w1 = sy[1], w2 = sy[2];
    for (int f = tid; f < FD; f += 128)
        out[(size_t)bn * FD + f] =
            w0 * sh[f] + w1 * sh[FD + f] + w2 * sh[2 * FD + f];
}

// ---------------- launch ----------------------------------------------------
extern "C" void kernel_launch(void* const* d_in, const int* in_sizes, int n_in,
                              void* d_out, int out_size) {
    const float* adj = (const float*)d_in[0];
    const float* X   = (const float*)d_in[1];
    const float* W   = (const float*)d_in[2];
    const float* a1  = (const float*)d_in[3];
    const float* a2  = (const float*)d_in[4];
    const float* Ww  = (const float*)d_in[5];
    const float* bw  = (const float*)d_in[6];
    const float* Wc  = (const float*)d_in[7];
    float* out = (float*)d_out;

    void *ph, *pH, *pa3;
    cudaGetSymbolAddress(&ph, g_h);
    cudaGetSymbolAddress(&pH, g_H);
    cudaGetSymbolAddress(&pa3, g_att3h);
    float* hbuf = (float*)ph;
    float* Hbuf = (float*)pH;
    const __half* att3h = (const __half*)pa3;

    // 1. adjacency bitsets + boolean powers
    bits_kernel<<<BATCH * NT * NSEQ, 1024>>>(adj);
    bmm_kernel<<<BATCH * NT * NSEQ, 32>>>(0, 1);
    bmm_kernel<<<BATCH * NT * NSEQ, 32>>>(1, 2);

    // 2. h[t,k] = X @ W[t,k]  for all 9 (t,k) — fp16 MMA
    {
        dim3 grid(FD / BN, (BATCH * NSEQ) / BM, 9);
        tgemm16<false><<<grid, 256>>>(X, W, hbuf,
                                      IND, IND, FD, FD,
                                      0LL, (long long)IND * FD,
                                      (long long)BATCH * NSEQ * FD,
                                      0LL, 0LL, 1);
    }

    // 3. f1/f2 projections
    f_kernel<<<(9 * BATCH * NSEQ) / 8, 256>>>(a1, a2);

    // 4. sparse layer k=0
    spmm_kernel<<<dim3(NSEQ, BATCH), 256>>>(0, Hbuf);

    // 5. all dense masked-softmax rows (k=1,2 x t=0..2) in one launch
    att_kernel<<<dim3(NSEQ, BATCH, 6), 256>>>();

    // 6. dense layers k=1,2: one segmented-K fp16 GEMM each (A = fp16 att)
    for (int k = 1; k < NLAY; k++) {
        dim3 grid(FD / BN, NSEQ / BM, BATCH);
        tgemm16<true><<<grid, 256>>>(
            att3h + (size_t)(k - 1) * NT * BATCH * NSEQ * NSEQ,
            hbuf + (size_t)k * BATCH * NSEQ * FD,
            Hbuf + k * FD,
            NSEQ, NSEQ, FD, NLAY * FD,
            (long long)NSEQ * NSEQ,                 // A batch stride (b)
            (long long)NSEQ * FD,                   // B batch stride (b)
            (long long)NSEQ * NLAY * FD,            // C batch stride (b)
            (long long)BATCH * NSEQ * NSEQ,         // A segment stride (t)
            (long long)3 * BATCH * NSEQ * FD,       // B segment stride (t)
            NT);
    }

    // 7. combine
    combine_kernel<<<BATCH * NSEQ, 128>>>(Ww, bw, Wc, out);
}

// round 9
// speedup vs baseline: 1.7188x; 1.1660x over previous
#include <cuda_runtime.h>
#include <cuda_fp16.h>
#include <cstdint>

#define BATCH 16
#define NT 3
#define NSEQ 1024
#define IND 512
#define FD 256
#define NLAY 3
#define NWRD 32
#define ALPHAV 0.2f
#define NEGV -9e15f

// ---------------- scratch (device globals; no allocations allowed) ----------
__device__ unsigned g_mask[NLAY][BATCH * NT * NSEQ * NWRD];
__device__ float g_h[(size_t)9 * BATCH * NSEQ * FD];
__device__ float g_f1[9 * BATCH * NSEQ];
__device__ float g_f2[9 * BATCH * NSEQ];
__device__ __half g_att3h[(size_t)2 * NT * BATCH * NSEQ * NSEQ]; // [kk][t][b][i][j]
__device__ __half g_Xh[(size_t)BATCH * NSEQ * IND];              // fp16 X row-major
__device__ __half g_Wh[9 * FD * IND];                            // fp16 W n-major [z][n][k]
__device__ __half g_ht[(size_t)2 * NT * BATCH * FD * NSEQ];      // fp16 h n-major [kk*3+t][b][f][s]
__device__ float g_H[(size_t)BATCH * NSEQ * NLAY * FD];

// ---------------- adj -> bitset --------------------------------------------
__global__ void bits_kernel(const float* __restrict__ adj) {
    int r = blockIdx.x;
    int tid = threadIdx.x;
    float v = adj[(size_t)r * NSEQ + tid];
    unsigned bal = __ballot_sync(0xffffffffu, v > 0.0f);
    if ((tid & 31) == 0) g_mask[0][(size_t)r * NWRD + (tid >> 5)] = bal;
}

// g_mask[dst] row i = OR_{j in g_mask[lft] row i} g_mask[rgt] row j   (per b,t)
__global__ void bmm_kernel(int lft, int rgt, int dst) {
    int r = blockIdx.x;
    int bt = r / NSEQ;
    int lane = threadIdx.x;
    const unsigned* lrow = &g_mask[lft][(size_t)r * NWRD];
    const unsigned* rbase = &g_mask[rgt][(size_t)bt * NSEQ * NWRD];
    unsigned myw = lrow[lane];
    unsigned acc = 0;
    #pragma unroll 1
    for (int w = 0; w < NWRD; ++w) {
        unsigned bitsw = __shfl_sync(0xffffffffu, myw, w);
        while (bitsw) {
            int j = (w << 5) + (__ffs(bitsw) - 1);
            bitsw &= bitsw - 1;
            acc |= rbase[(size_t)j * NWRD + lane];
        }
    }
    g_mask[dst][(size_t)r * NWRD + lane] = acc;
}

// ---------------- fp16 operand prep -----------------------------------------
__global__ void xh_kernel(const float* __restrict__ X) {
    int i = blockIdx.x * blockDim.x + threadIdx.x;   // one per 4 elements
    float4 v = ((const float4*)X)[i];
    __half2 a = __floats2half2_rn(v.x, v.y);
    __half2 b = __floats2half2_rn(v.z, v.w);
    ((uint2*)g_Xh)[i] = make_uint2(*(unsigned*)&a, *(unsigned*)&b);
}

__global__ void wh_kernel(const float* __restrict__ W) {
    __shared__ float tl[32][33];
    int z = blockIdx.z;
    int k0 = blockIdx.x * 32, n0 = blockIdx.y * 32;
    const float* src = W + (size_t)z * IND * FD;
    for (int r = threadIdx.y; r < 32; r += 8)
        tl[r][threadIdx.x] = src[(size_t)(k0 + r) * FD + n0 + threadIdx.x];
    __syncthreads();
    __half* dst = g_Wh + (size_t)z * FD * IND;
    for (int r = threadIdx.y; r < 32; r += 8)
        dst[(size_t)(n0 + r) * IND + k0 + threadIdx.x] =
            __float2half(tl[threadIdx.x][r]);
}

__global__ void hth_kernel() {
    __shared__ float tl[32][33];
    int z6 = blockIdx.z % 6, b = blockIdx.z / 6;   // z6 = kk*3 + t
    int t = z6 % 3, kk = z6 / 3;
    int z = t * 3 + (kk + 1);
    int s0 = blockIdx.x * 32, f0 = blockIdx.y * 32;
    const float* src = g_h + ((size_t)z * BATCH + b) * NSEQ * FD;
    for (int r = threadIdx.y; r < 32; r += 8)
        tl[r][threadIdx.x] = src[(size_t)(s0 + r) * FD + f0 + threadIdx.x];
    __syncthreads();
    __half* dst = g_ht + ((size_t)z6 * BATCH + b) * FD * NSEQ;
    for (int r = threadIdx.y; r < 32; r += 8)
        dst[(size_t)(f0 + r) * NSEQ + s0 + threadIdx.x] =
            __float2half(tl[threadIdx.x][r]);
}

// ---------------- fp16 tensor-core GEMM (128x128, BK=16, 3-stage) -----------
// A fp16 [M][K] row-major; B fp16 [N][K] n-major; C fp32 [M][N].
// Accumulates over nseg segments (A: +sAseg, B: +sBseg per segment).
#define BM 128
#define BN 128

__global__ __launch_bounds__(256) void tgemm16(
    const __half* __restrict__ Ah, const __half* __restrict__ Bh, float* __restrict__ C,
    int Kk, int lda, int ldb, int ldc,
    long long sA, long long sB, long long sC,
    long long sAseg, long long sBseg, int nseg)
{
    int z = blockIdx.z;
    Ah += (size_t)z * sA;
    Bh += (size_t)z * sB;
    C  += (size_t)z * sC;

    __shared__ unsigned Asm[3][8][32][4];    // [stage][mtile][lane][reg]
    __shared__ unsigned Bsm[3][16][32][2];   // [stage][ntile][lane][reg]

    int tid = threadIdx.x;
    int lane = tid & 31;
    int wid = tid >> 5;
    int wm = wid >> 2;
    int wn = wid & 3;

    int bm = blockIdx.y * BM, bn = blockIdx.x * BN;

    int lane4 = lane >> 2;
    int k0 = (lane & 3) * 2;

    const __half* Ap0 = Ah + (size_t)(bm + wid * 16 + lane4) * lda + k0;
    const __half* Ap8 = Ap0 + (size_t)8 * lda;
    const __half* Bb = Bh + (size_t)(bn + wid * 16 + lane4) * ldb + k0;

    float d[4][4][4];
    #pragma unroll
    for (int i = 0; i < 4; i++)
        #pragma unroll
        for (int j = 0; j < 4; j++)
            #pragma unroll
            for (int r = 0; r < 4; r++) d[i][j][r] = 0.0f;

    unsigned ar[4];
    unsigned br[2][2];

    int kiter = Kk >> 4;
    int total = nseg * kiter;

    #define LOADQ(q)                                                           \
        {                                                                      \
            int _seg = (q) / kiter;                                            \
            long long _ko = (long long)((q) - _seg * kiter) * 16;              \
            long long _ao = (long long)_seg * sAseg + _ko;                     \
            long long _bo = (long long)_seg * sBseg + _ko;                     \
            ar[0] = *(const unsigned*)(Ap0 + _ao);                             \
            ar[1] = *(const unsigned*)(Ap8 + _ao);                             \
            ar[2] = *(const unsigned*)(Ap0 + _ao + 8);                         \
            ar[3] = *(const unsigned*)(Ap8 + _ao + 8);                         \
            br[0][0] = *(const unsigned*)(Bb + _bo);                           \
            br[0][1] = *(const unsigned*)(Bb + _bo + 8);                       \
            br[1][0] = *(const unsigned*)(Bb + _bo + (size_t)8 * ldb);         \
            br[1][1] = *(const unsigned*)(Bb + _bo + (size_t)8 * ldb + 8);     \
        }

    #define STORE_STAGE(st)                                                    \
        {                                                                      \
            *(uint4*)(&Asm[st][wid][lane][0]) =                                \
                make_uint4(ar[0], ar[1], ar[2], ar[3]);                        \
            *(uint2*)(&Bsm[st][2 * wid][lane][0]) = make_uint2(br[0][0], br[0][1]); \
            *(uint2*)(&Bsm[st][2 * wid + 1][lane][0]) = make_uint2(br[1][0], br[1][1]); \
        }

    LOADQ(0);
    STORE_STAGE(0);
    if (total > 1) LOADQ(1);
    __syncthreads();

    for (int c = 0; c < total; c++) {
        int cur = c - (c / 3) * 3;
        if (c + 1 < total) {
            int nst = cur + 1; if (nst == 3) nst = 0;
            STORE_STAGE(nst);
            if (c + 2 < total) LOADQ(c + 2);
        }
        unsigned af[4][4];
        unsigned bf[4][2];
        #pragma unroll
        for (int mt = 0; mt < 4; mt++) {
            uint4 t = *(const uint4*)(&Asm[cur][wm * 4 + mt][lane][0]);
            af[mt][0] = t.x; af[mt][1] = t.y; af[mt][2] = t.z; af[mt][3] = t.w;
        }
        #pragma unroll
        for (int nt = 0; nt < 4; nt++) {
            uint2 t = *(const uint2*)(&Bsm[cur][wn * 4 + nt][lane][0]);
            bf[nt][0] = t.x; bf[nt][1] = t.y;
        }
        #pragma unroll
        for (int mt = 0; mt < 4; mt++)
            #pragma unroll
            for (int nt = 0; nt < 4; nt++) {
                asm volatile(
                    "mma.sync.aligned.m16n8k16.row.col.f32.f16.f16.f32 "
                    "{%0,%1,%2,%3}, {%4,%5,%6,%7}, {%8,%9}, {%0,%1,%2,%3};"
                    : "+f"(d[mt][nt][0]), "+f"(d[mt][nt][1]),
                      "+f"(d[mt][nt][2]), "+f"(d[mt][nt][3])
                    : "r"(af[mt][0]), "r"(af[mt][1]),
                      "r"(af[mt][2]), "r"(af[mt][3]),
                      "r"(bf[nt][0]), "r"(bf[nt][1]));
            }
        __syncthreads();
    }

    int cr = lane >> 2;
    int cc = (lane & 3) * 2;
    #pragma unroll
    for (int mt = 0; mt < 4; mt++) {
        #pragma unroll
        for (int half = 0; half < 2; half++) {
            int row = bm + wm * 64 + mt * 16 + cr + half * 8;
            float* cp = C + (size_t)row * ldc + bn + wn * 32 + cc;
            #pragma unroll
            for (int nt = 0; nt < 4; nt++) {
                float2 v = make_float2(d[mt][nt][half * 2], d[mt][nt][half * 2 + 1]);
                *(float2*)(cp + nt * 8) = v;
            }
        }
    }
}

// ---------------- f1/f2 -----------------------------------------------------
__global__ void f_kernel(const float* __restrict__ a1, const float* __restrict__ a2) {
    int gw = (blockIdx.x * blockDim.x + threadIdx.x) >> 5;
    int lane = threadIdx.x & 31;
    if (gw >= 9 * BATCH * NSEQ) return;
    int z = gw / (BATCH * NSEQ);
    const float* hp = &g_h[(size_t)gw * FD];
    const float* a1p = a1 + (size_t)z * FD;
    const float* a2p = a2 + (size_t)z * FD;
    float s1 = 0.0f, s2 = 0.0f;
    #pragma unroll
    for (int i = lane; i < FD; i += 32) {
        float hv = hp[i];
        s1 = fmaf(hv, a1p[i], s1);
        s2 = fmaf(hv, a2p[i], s2);
    }
    #pragma unroll
    for (int off = 16; off > 0; off >>= 1) {
        s1 += __shfl_down_sync(0xffffffffu, s1, off);
        s2 += __shfl_down_sync(0xffffffffu, s2, off);
    }
    if (lane == 0) { g_f1[gw] = s1; g_f2[gw] = s2; }
}

// ---------------- fused sparse softmax + SpMM (layer k=0 only) --------------
__global__ __launch_bounds__(256) void spmm_kernel(int k, float* __restrict__ Hout) {
    int n = blockIdx.x, b = blockIdx.y;
    int tid = threadIdx.x;

    __shared__ int   list[NSEQ];
    __shared__ float pn[NSEQ];
    __shared__ int   s_cnt;
    __shared__ float red[256];

    float acc = 0.0f;

    for (int t = 0; t < NT; t++) {
        int z = t * 3 + k;
        if (tid == 0) s_cnt = 0;
        __syncthreads();
        if (tid < NWRD) {
            unsigned w = g_mask[k][(((size_t)b * NT + t) * NSEQ + n) * NWRD + tid];
            while (w) {
                int j = (tid << 5) + (__ffs(w) - 1);
                w &= w - 1;
                int p = atomicAdd(&s_cnt, 1);
                list[p] = j;
            }
        }
        __syncthreads();
        int cnt = s_cnt;

        const float* f2p = &g_f2[(size_t)z * BATCH * NSEQ + (size_t)b * NSEQ];
        float f1v = g_f1[(size_t)z * BATCH * NSEQ + (size_t)b * NSEQ + n];
        const float* hp = &g_h[((size_t)z * BATCH + b) * NSEQ * FD];

        if (cnt == 0) {
            float a = 0.0f;
            for (int j = 0; j < NSEQ; j++) a += hp[(size_t)j * FD + tid];
            acc += a * (1.0f / NSEQ);
            __syncthreads();
            continue;
        }

        float lmax = -1e30f;
        for (int i = tid; i < cnt; i += 256) {
            float x = f1v + f2p[list[i]];
            x = (x > 0.0f) ? x : ALPHAV * x;
            pn[i] = x;
            lmax = fmaxf(lmax, x);
        }
        red[tid] = lmax;
        __syncthreads();
        for (int s = 128; s > 0; s >>= 1) {
            if (tid < s) red[tid] = fmaxf(red[tid], red[tid + s]);
            __syncthreads();
        }
        float m = red[0];
        __syncthreads();

        float lsum = 0.0f;
        for (int i = tid; i < cnt; i += 256) {
            float p = __expf(pn[i] - m);
            pn[i] = p;
            lsum += p;
        }
        red[tid] = lsum;
        __syncthreads();
        for (int s = 128; s > 0; s >>= 1) {
            if (tid < s) red[tid] += red[tid + s];
            __syncthreads();
        }
        float inv = 1.0f / red[0];
        __syncthreads();

        int i = 0;
        for (; i + 4 <= cnt; i += 4) {
            int j0 = list[i], j1 = list[i + 1], j2 = list[i + 2], j3 = list[i + 3];
            float p0 = pn[i] * inv, p1 = pn[i + 1] * inv;
            float p2 = pn[i + 2] * inv, p3 = pn[i + 3] * inv;
            float h0 = hp[(size_t)j0 * FD + tid];
            float h1 = hp[(size_t)j1 * FD + tid];
            float h2 = hp[(size_t)j2 * FD + tid];
            float h3 = hp[(size_t)j3 * FD + tid];
            acc = fmaf(p0, h0, acc);
            acc = fmaf(p1, h1, acc);
            acc = fmaf(p2, h2, acc);
            acc = fmaf(p3, h3, acc);
        }
        for (; i < cnt; i++)
            acc = fmaf(pn[i] * inv, hp[(size_t)list[i] * FD + tid], acc);
        __syncthreads();
    }

    Hout[(((size_t)b * NSEQ + n) * NLAY + k) * FD + tid] = acc;
}

// ---------------- dense masked-softmax attention rows (k=1,2 merged) --------
// grid (NSEQ, BATCH, 6): zz -> t = zz%3, k = 1 + zz/3. Writes fp16 rows.
__global__ __launch_bounds__(256) void att_kernel(void) {
    int i = blockIdx.x, b = blockIdx.y, zz = blockIdx.z;
    int t = zz % 3, kk = zz / 3, k = kk + 1;
    int tid = threadIdx.x;
    int lane = tid & 31, wid = tid >> 5;
    int z = t * 3 + k;

    __shared__ float sf2[NSEQ];
    __shared__ unsigned smask[NWRD];
    __shared__ float redmax[8];
    __shared__ float redsum[8];

    const float* f2p = &g_f2[(size_t)z * BATCH * NSEQ + (size_t)b * NSEQ];
    for (int j = tid; j < NSEQ; j += 256) sf2[j] = f2p[j];
    if (tid < NWRD)
        smask[tid] = g_mask[k][(((size_t)b * NT + t) * NSEQ + i) * NWRD + tid];
    __syncthreads();

    float f1v = g_f1[(size_t)z * BATCH * NSEQ + (size_t)b * NSEQ + i];

    int j0 = tid * 4;
    unsigned mw = (smask[j0 >> 5] >> (j0 & 31)) & 0xFu;

    float e[4];
    float lmax = NEGV;
    #pragma unroll
    for (int q = 0; q < 4; q++) {
        float x = f1v + sf2[j0 + q];
        x = (x > 0.0f) ? x : ALPHAV * x;
        e[q] = ((mw >> q) & 1u) ? x : NEGV;
        lmax = fmaxf(lmax, e[q]);
    }
    #pragma unroll
    for (int off = 16; off > 0; off >>= 1)
        lmax = fmaxf(lmax, __shfl_xor_sync(0xffffffffu, lmax, off));
    if (lane == 0) redmax[wid] = lmax;
    __syncthreads();
    float m = redmax[0];
    #pragma unroll
    for (int w = 1; w < 8; w++) m = fmaxf(m, redmax[w]);

    bool empty = (m < -8.9e15f);
    float p[4];
    float lsum = 0.0f;
    #pragma unroll
    for (int q = 0; q < 4; q++) {
        p[q] = empty ? 1.0f : (((mw >> q) & 1u) ? __expf(e[q] - m) : 0.0f);
        lsum += p[q];
    }
    #pragma unroll
    for (int off = 16; off > 0; off >>= 1)
        lsum += __shfl_xor_sync(0xffffffffu, lsum, off);
    if (lane == 0) redsum[wid] = lsum;
    __syncthreads();
    float s = 0.0f;
    #pragma unroll
    for (int w = 0; w < 8; w++) s += redsum[w];
    float inv = 1.0f / s;

    __half* arow = &g_att3h[((((size_t)kk * NT + t) * BATCH + b) * NSEQ + i) * NSEQ];
    __half2 h01 = __floats2half2_rn(p[0] * inv, p[1] * inv);
    __half2 h23 = __floats2half2_rn(p[2] * inv, p[3] * inv);
    *(uint2*)(arow + j0) = make_uint2(*(unsigned*)&h01, *(unsigned*)&h23);
}

// ---------------- final combine ---------------------------------------------
__global__ void combine_kernel(const float* __restrict__ Ww, const float* __restrict__ bw,
                               const float* __restrict__ Wc, float* __restrict__ out) {
    int bn = blockIdx.x;
    int tid = threadIdx.x;
    __shared__ float sh[NLAY * FD];
    __shared__ float part[NLAY][128];
    __shared__ float sy[NLAY];

    const float* Hp = &g_H[(size_t)bn * NLAY * FD];
    for (int i = tid; i < NLAY * FD; i += 128) sh[i] = Hp[i];
    __syncthreads();

    float loc[NLAY] = {0.0f, 0.0f, 0.0f};
    if (tid < 100) {
        float wc = Wc[tid];
        float bwv = bw[tid];
        #pragma unroll
        for (int k = 0; k < NLAY; k++) {
            float y = bwv;
            #pragma unroll 8
            for (int i = 0; i < FD; i++)
                y = fmaf(sh[k * FD + i], Ww[i * 100 + tid], y);
            loc[k] = tanhf(y) * wc;
        }
    }
    #pragma unroll
    for (int k = 0; k < NLAY; k++) part[k][tid] = loc[k];
    __syncthreads();
    for (int s = 64; s > 0; s >>= 1) {
        if (tid < s) {
            part[0][tid] += part[0][tid + s];
            part[1][tid] += part[1][tid + s];
            part[2][tid] += part[2][tid + s];
        }
        __syncthreads();
    }
    if (tid == 0) {
        float s0 = part[0][0], s1 = part[1][0], s2 = part[2][0];
        float mx = fmaxf(s0, fmaxf(s1, s2));
        float e0 = __expf(s0 - mx), e1 = __expf(s1 - mx), e2 = __expf(s2 - mx);
        float invs = 1.0f / (e0 + e1 + e2);
        sy[0] = e0 * invs; sy[1] = e1 * invs; sy[2] = e2 * invs;
    }
    __syncthreads();

    float w0 = sy[0], w1 = sy[1], w2 = sy[2];
    for (int f = tid; f < FD; f += 128)
        out[(size_t)bn * FD + f] =
            w0 * sh[f] + w1 * sh[FD + f] + w2 * sh[2 * FD + f];
}

// ---------------- launch ----------------------------------------------------
extern "C" void kernel_launch(void* const* d_in, const int* in_sizes, int n_in,
                              void* d_out, int out_size) {
    const float* adj = (const float*)d_in[0];
    const float* X   = (const float*)d_in[1];
    const float* W   = (const float*)d_in[2];
    const float* a1  = (const float*)d_in[3];
    const float* a2  = (const float*)d_in[4];
    const float* Ww  = (const float*)d_in[5];
    const float* bw  = (const float*)d_in[6];
    const float* Wc  = (const float*)d_in[7];
    float* out = (float*)d_out;

    void *ph, *pH, *pa3, *pxh, *pwh, *pht;
    cudaGetSymbolAddress(&ph, g_h);
    cudaGetSymbolAddress(&pH, g_H);
    cudaGetSymbolAddress(&pa3, g_att3h);
    cudaGetSymbolAddress(&pxh, g_Xh);
    cudaGetSymbolAddress(&pwh, g_Wh);
    cudaGetSymbolAddress(&pht, g_ht);
    float* hbuf = (float*)ph;
    float* Hbuf = (float*)pH;

    // 1. adjacency bitsets + boolean powers (adj^3 via adj * adj^2: ~10 gathers)
    bits_kernel<<<BATCH * NT * NSEQ, 1024>>>(adj);
    bmm_kernel<<<BATCH * NT * NSEQ, 32>>>(0, 0, 1);
    bmm_kernel<<<BATCH * NT * NSEQ, 32>>>(0, 1, 2);

    // 2. fp16 operand prep: X row-major, W n-major
    xh_kernel<<<(BATCH * NSEQ * IND / 4) / 256, 256>>>(X);
    wh_kernel<<<dim3(IND / 32, FD / 32, 9), dim3(32, 8)>>>(W);

    // 3. h[t,k] = X @ W[t,k]  for all 9 (t,k)
    {
        dim3 grid(FD / BN, (BATCH * NSEQ) / BM, 9);
        tgemm16<<<grid, 256>>>((const __half*)pxh, (const __half*)pwh, hbuf,
                               IND, IND, IND, FD,
                               0LL, (long long)FD * IND,
                               (long long)BATCH * NSEQ * FD,
                               0LL, 0LL, 1);
    }

    // 4. f1/f2 projections
    f_kernel<<<(9 * BATCH * NSEQ) / 8, 256>>>(a1, a2);

    // 5. fp16 n-major h for k=1,2 relations
    hth_kernel<<<dim3(NSEQ / 32, FD / 32, 6 * BATCH), dim3(32, 8)>>>();

    // 6. sparse layer k=0
    spmm_kernel<<<dim3(NSEQ, BATCH), 256>>>(0, Hbuf);

    // 7. all dense masked-softmax rows (k=1,2 x t=0..2) in one launch
    att_kernel<<<dim3(NSEQ, BATCH, 6), 256>>>();

    // 8. dense layers k=1,2: one segmented-K fp16 GEMM each
    for (int k = 1; k < NLAY; k++) {
        dim3 grid(FD / BN, NSEQ / BM, BATCH);
        tgemm16<<<grid, 256>>>(
            (const __half*)pa3 + (size_t)(k - 1) * NT * BATCH * NSEQ * NSEQ,
            (const __half*)pht + (size_t)(k - 1) * NT * BATCH * FD * NSEQ,
            Hbuf + k * FD,
            NSEQ, NSEQ, NSEQ, NLAY * FD,
            (long long)NSEQ * NSEQ,                 // A batch stride (b)
            (long long)FD * NSEQ,                   // B batch stride (b)
            (long long)NSEQ * NLAY * FD,            // C batch stride (b)
            (long long)BATCH * NSEQ * NSEQ,         // A segment stride (t)
            (long long)BATCH * FD * NSEQ,           // B segment stride (t)
            NT);
    }

    // 9. combine
    combine_kernel<<<BATCH * NSEQ, 128>>>(Ww, bw, Wc, out);
}

// round 12
// speedup vs baseline: 2.0984x; 1.2208x over previous
#include <cuda_runtime.h>
#include <cuda_fp16.h>
#include <cstdint>

#define BATCH 16
#define NT 3
#define NSEQ 1024
#define IND 512
#define FD 256
#define NLAY 3
#define NWRD 32
#define ALPHAV 0.2f
#define NEGV -9e15f

// ---------------- scratch (device globals; no allocations allowed) ----------
__device__ unsigned g_mask[NLAY][BATCH * NT * NSEQ * NWRD];
__device__ float g_h[(size_t)9 * BATCH * NSEQ * FD];
__device__ float g_f1[9 * BATCH * NSEQ];
__device__ float g_f2[9 * BATCH * NSEQ];
// fragment-major operand buffers
__device__ uint4 g_xf[(size_t)(BATCH * NSEQ / 16) * (IND / 16) * 32];       // 16MB
__device__ uint2 g_wf[9 * (FD / 8) * (IND / 16) * 32];                      // 2.4MB
__device__ uint4 g_attf[(size_t)2 * NT * BATCH * 64 * 64 * 32];             // 201MB
__device__ uint2 g_htf[(size_t)6 * BATCH * 32 * 64 * 32];                   // 50MB
__device__ float g_H[(size_t)BATCH * NSEQ * NLAY * FD];

__device__ __forceinline__ unsigned packh2(float a, float b) {
    __half2 h = __floats2half2_rn(a, b);
    return *(unsigned*)&h;
}

// ---------------- adj -> bitset --------------------------------------------
__global__ void bits_kernel(const float* __restrict__ adj) {
    int r = blockIdx.x;
    int tid = threadIdx.x;
    float v = adj[(size_t)r * NSEQ + tid];
    unsigned bal = __ballot_sync(0xffffffffu, v > 0.0f);
    if ((tid & 31) == 0) g_mask[0][(size_t)r * NWRD + (tid >> 5)] = bal;
}

__global__ void bmm_kernel(int lft, int rgt, int dst) {
    int r = blockIdx.x;
    int bt = r / NSEQ;
    int lane = threadIdx.x;
    const unsigned* lrow = &g_mask[lft][(size_t)r * NWRD];
    const unsigned* rbase = &g_mask[rgt][(size_t)bt * NSEQ * NWRD];
    unsigned myw = lrow[lane];
    unsigned acc = 0;
    #pragma unroll 1
    for (int w = 0; w < NWRD; ++w) {
        unsigned bitsw = __shfl_sync(0xffffffffu, myw, w);
        while (bitsw) {
            int j = (w << 5) + (__ffs(bitsw) - 1);
            bitsw &= bitsw - 1;
            acc |= rbase[(size_t)j * NWRD + lane];
        }
    }
    g_mask[dst][(size_t)r * NWRD + lane] = acc;
}

// ---------------- operand prep (fragment-major) ------------------------------
// A-word(mt,kt,lane): m=mt*16+lane/4, k=kt*16+(lane%4)*2
//   uint4 = { (m,k..k+1), (m+8,k..k+1), (m,k+8..k+9), (m+8,k+8..k+9) }
// B-word(nt,kt,lane): n=nt*8+lane/4, k=kt*16+(lane%4)*2
//   uint2 = { (n,k..k+1), (n,k+8..k+9) }

__global__ void xf_kernel(const float* __restrict__ X) {
    int idx = blockIdx.x * blockDim.x + threadIdx.x;
    int lane = idx & 31;
    int kt = (idx >> 5) & 31;          // IND/16 = 32
    int mt = idx >> 10;
    int m = mt * 16 + (lane >> 2);
    int k = kt * 16 + (lane & 3) * 2;
    const float* p0 = X + (size_t)m * IND + k;
    const float* p8 = p0 + (size_t)8 * IND;
    uint4 t;
    t.x = packh2(p0[0], p0[1]);
    t.y = packh2(p8[0], p8[1]);
    t.z = packh2(p0[8], p0[9]);
    t.w = packh2(p8[8], p8[9]);
    g_xf[idx] = t;
}

__global__ void wf_kernel(const float* __restrict__ W) {
    int idx = blockIdx.x * blockDim.x + threadIdx.x;   // 9*32*32*32
    int lane = idx & 31;
    int kt = (idx >> 5) & 31;
    int nt = (idx >> 10) & 31;
    int z = idx >> 15;
    int n = nt * 8 + (lane >> 2);
    int k = kt * 16 + (lane & 3) * 2;
    const float* Wz = W + (size_t)z * IND * FD;
    uint2 t;
    t.x = packh2(Wz[(size_t)k * FD + n], Wz[(size_t)(k + 1) * FD + n]);
    t.y = packh2(Wz[(size_t)(k + 8) * FD + n], Wz[(size_t)(k + 9) * FD + n]);
    g_wf[idx] = t;
}

__global__ void htf_kernel() {
    int idx = blockIdx.x * blockDim.x + threadIdx.x;   // 6*16*32*64*32
    int lane = idx & 31;
    int kt = (idx >> 5) & 63;
    int nt = (idx >> 11) & 31;
    int b = (idx >> 16) & 15;
    int z6 = idx >> 20;                  // kk*3 + t
    int t = z6 % 3, kk = z6 / 3;
    int z = t * 3 + (kk + 1);
    int f = nt * 8 + (lane >> 2);
    int s = kt * 16 + (lane & 3) * 2;
    const float* src = g_h + ((size_t)z * BATCH + b) * NSEQ * FD;
    uint2 w;
    w.x = packh2(src[(size_t)s * FD + f], src[(size_t)(s + 1) * FD + f]);
    w.y = packh2(src[(size_t)(s + 8) * FD + f], src[(size_t)(s + 9) * FD + f]);
    g_htf[idx] = w;
}

// ---------------- cp.async helpers ------------------------------------------
__device__ __forceinline__ uint32_t smem_u32(const void* p) {
    return (uint32_t)__cvta_generic_to_shared(p);
}
#define CPA16(dst, src) \
    asm volatile("cp.async.cg.shared.global [%0], [%1], 16;" :: "r"(dst), "l"(src))
#define CPA8(dst, src) \
    asm volatile("cp.async.ca.shared.global [%0], [%1], 8;" :: "r"(dst), "l"(src))
#define CPCOMMIT() asm volatile("cp.async.commit_group;" ::: "memory")
#define CPWAIT2()  asm volatile("cp.async.wait_group 2;" ::: "memory")

// ---------------- fp16 fragment-direct GEMM (128x128, BK=16, 4-stage) -------
// A/B pre-fragmented fp16; C fp32 row-major. Segmented K accumulation.
#define BM 128
#define BN 128

__global__ __launch_bounds__(256) void tgemm16f(
    const uint4* __restrict__ Af, const uint2* __restrict__ Bf, float* __restrict__ C,
    int kiter, int ldc,
    long long sA, long long sB, long long sC,      // word strides (z) / elem (C)
    long long sAseg, long long sBseg, int nseg)    // word strides (segment)
{
    __shared__ uint4 As[4][8][32];
    __shared__ uint2 Bs[4][16][32];

    int tid = threadIdx.x;
    int lane = tid & 31;
    int wid = tid >> 5;
    int wm = wid >> 2;
    int wn = wid & 3;
    int z = blockIdx.z;
    int mt0 = blockIdx.y * 8;
    int nt0 = blockIdx.x * 16;

    C += (size_t)z * sC;

    // per-thread issue-state source pointers
    const uint4* asrc = Af + (size_t)z * sA + ((size_t)(mt0 + wid) * kiter) * 32 + lane;
    const uint2* bsrc0 = Bf + (size_t)z * sB + ((size_t)(nt0 + 2 * wid) * kiter) * 32 + lane;
    const uint2* bsrc1 = Bf + (size_t)z * sB + ((size_t)(nt0 + 2 * wid + 1) * kiter) * 32 + lane;
    long long awrap = sAseg - (long long)kiter * 32;
    long long bwrap = sBseg - (long long)kiter * 32;
    int ktc = 0;

    uint32_t sa = smem_u32(&As[0][wid][lane]);
    uint32_t sb0 = smem_u32(&Bs[0][2 * wid][lane]);
    uint32_t sb1 = smem_u32(&Bs[0][2 * wid + 1][lane]);

    #define ISSUE(st)                                                          \
        do {                                                                   \
            CPA16(sa + (st) * 4096, asrc);                                     \
            CPA8(sb0 + (st) * 4096, bsrc0);                                    \
            CPA8(sb1 + (st) * 4096, bsrc1);                                    \
            CPCOMMIT();                                                        \
            asrc += 32; bsrc0 += 32; bsrc1 += 32;                              \
            if (++ktc == kiter) {                                              \
                ktc = 0;                                                       \
                asrc += awrap; bsrc0 += bwrap; bsrc1 += bwrap;                 \
            }                                                                  \
        } while (0)

    float d[4][4][4];
    #pragma unroll
    for (int i = 0; i < 4; i++)
        #pragma unroll
        for (int j = 0; j < 4; j++)
            #pragma unroll
            for (int r = 0; r < 4; r++) d[i][j][r] = 0.0f;

    int total = nseg * kiter;
    ISSUE(0);
    if (total > 1) { ISSUE(1); } else { CPCOMMIT(); }
    if (total > 2) { ISSUE(2); } else { CPCOMMIT(); }

    for (int c = 0; c < total; c++) {
        CPWAIT2();
        __syncthreads();
        // Always commit a group per iteration so wait_group 2 at iteration c
        // guarantees group c is complete (empty groups complete immediately).
        if (c + 3 < total) { ISSUE((c + 3) & 3); } else { CPCOMMIT(); }
        int cur = c & 3;
        unsigned af[4][4];
        unsigned bf[4][2];
        #pragma unroll
        for (int mt = 0; mt < 4; mt++) {
            uint4 t = As[cur][wm * 4 + mt][lane];
            af[mt][0] = t.x; af[mt][1] = t.y; af[mt][2] = t.z; af[mt][3] = t.w;
        }
        #pragma unroll
        for (int nt = 0; nt < 4; nt++) {
            uint2 t = Bs[cur][wn * 4 + nt][lane];
            bf[nt][0] = t.x; bf[nt][1] = t.y;
        }
        #pragma unroll
        for (int mt = 0; mt < 4; mt++)
            #pragma unroll
            for (int nt = 0; nt < 4; nt++) {
                asm volatile(
                    "mma.sync.aligned.m16n8k16.row.col.f32.f16.f16.f32 "
                    "{%0,%1,%2,%3}, {%4,%5,%6,%7}, {%8,%9}, {%0,%1,%2,%3};"
                    : "+f"(d[mt][nt][0]), "+f"(d[mt][nt][1]),
                      "+f"(d[mt][nt][2]), "+f"(d[mt][nt][3])
                    : "r"(af[mt][0]), "r"(af[mt][1]),
                      "r"(af[mt][2]), "r"(af[mt][3]),
                      "r"(bf[nt][0]), "r"(bf[nt][1]));
            }
        __syncthreads();
    }

    int cr = lane >> 2;
    int cc = (lane & 3) * 2;
    int bm = blockIdx.y * BM, bn = blockIdx.x * BN;
    #pragma unroll
    for (int mt = 0; mt < 4; mt++) {
        #pragma unroll
        for (int half = 0; half < 2; half++) {
            int row = bm + wm * 64 + mt * 16 + cr + half * 8;
            float* cp = C + (size_t)row * ldc + bn + wn * 32 + cc;
            #pragma unroll
            for (int nt = 0; nt < 4; nt++) {
                float2 v = make_float2(d[mt][nt][half * 2], d[mt][nt][half * 2 + 1]);
                *(float2*)(cp + nt * 8) = v;
            }
        }
    }
}

// ---------------- f1/f2 -----------------------------------------------------
__global__ void f_kernel(const float* __restrict__ a1, const float* __restrict__ a2) {
    int gw = (blockIdx.x * blockDim.x + threadIdx.x) >> 5;
    int lane = threadIdx.x & 31;
    if (gw >= 9 * BATCH * NSEQ) return;
    int z = gw / (BATCH * NSEQ);
    const float* hp = &g_h[(size_t)gw * FD];
    const float* a1p = a1 + (size_t)z * FD;
    const float* a2p = a2 + (size_t)z * FD;
    float s1 = 0.0f, s2 = 0.0f;
    #pragma unroll
    for (int i = lane; i < FD; i += 32) {
        float hv = hp[i];
        s1 = fmaf(hv, a1p[i], s1);
        s2 = fmaf(hv, a2p[i], s2);
    }
    #pragma unroll
    for (int off = 16; off > 0; off >>= 1) {
        s1 += __shfl_down_sync(0xffffffffu, s1, off);
        s2 += __shfl_down_sync(0xffffffffu, s2, off);
    }
    if (lane == 0) { g_f1[gw] = s1; g_f2[gw] = s2; }
}

// ---------------- fused sparse softmax + SpMM (layer k=0 only) --------------
__global__ __launch_bounds__(256) void spmm_kernel(int k, float* __restrict__ Hout) {
    int n = blockIdx.x, b = blockIdx.y;
    int tid = threadIdx.x;

    __shared__ int   list[NSEQ];
    __shared__ float pn[NSEQ];
    __shared__ int   s_cnt;
    __shared__ float red[256];

    float acc = 0.0f;

    for (int t = 0; t < NT; t++) {
        int z = t * 3 + k;
        if (tid == 0) s_cnt = 0;
        __syncthreads();
        if (tid < NWRD) {
            unsigned w = g_mask[k][(((size_t)b * NT + t) * NSEQ + n) * NWRD + tid];
            while (w) {
                int j = (tid << 5) + (__ffs(w) - 1);
                w &= w - 1;
                int p = atomicAdd(&s_cnt, 1);
                list[p] = j;
            }
        }
        __syncthreads();
        int cnt = s_cnt;

        const float* f2p = &g_f2[(size_t)z * BATCH * NSEQ + (size_t)b * NSEQ];
        float f1v = g_f1[(size_t)z * BATCH * NSEQ + (size_t)b * NSEQ + n];
        const float* hp = &g_h[((size_t)z * BATCH + b) * NSEQ * FD];

        if (cnt == 0) {
            float a = 0.0f;
            for (int j = 0; j < NSEQ; j++) a += hp[(size_t)j * FD + tid];
            acc += a * (1.0f / NSEQ);
            __syncthreads();
            continue;
        }

        float lmax = -1e30f;
        for (int i = tid; i < cnt; i += 256) {
            float x = f1v + f2p[list[i]];
            x = (x > 0.0f) ? x : ALPHAV * x;
            pn[i] = x;
            lmax = fmaxf(lmax, x);
        }
        red[tid] = lmax;
        __syncthreads();
        for (int s = 128; s > 0; s >>= 1) {
            if (tid < s) red[tid] = fmaxf(red[tid], red[tid + s]);
            __syncthreads();
        }
        float m = red[0];
        __syncthreads();

        float lsum = 0.0f;
        for (int i = tid; i < cnt; i += 256) {
            float p = __expf(pn[i] - m);
            pn[i] = p;
            lsum += p;
        }
        red[tid] = lsum;
        __syncthreads();
        for (int s = 128; s > 0; s >>= 1) {
            if (tid < s) red[tid] += red[tid + s];
            __syncthreads();
        }
        float inv = 1.0f / red[0];
        __syncthreads();

        int i = 0;
        for (; i + 4 <= cnt; i += 4) {
            int j0 = list[i], j1 = list[i + 1], j2 = list[i + 2], j3 = list[i + 3];
            float p0 = pn[i] * inv, p1 = pn[i + 1] * inv;
            float p2 = pn[i + 2] * inv, p3 = pn[i + 3] * inv;
            float h0 = hp[(size_t)j0 * FD + tid];
            float h1 = hp[(size_t)j1 * FD + tid];
            float h2 = hp[(size_t)j2 * FD + tid];
            float h3 = hp[(size_t)j3 * FD + tid];
            acc = fmaf(p0, h0, acc);
            acc = fmaf(p1, h1, acc);
            acc = fmaf(p2, h2, acc);
            acc = fmaf(p3, h3, acc);
        }
        for (; i < cnt; i++)
            acc = fmaf(pn[i] * inv, hp[(size_t)list[i] * FD + tid], acc);
        __syncthreads();
    }

    Hout[(((size_t)b * NSEQ + n) * NLAY + k) * FD + tid] = acc;
}

// ---------------- dense masked-softmax rows -> A-fragments (k=1,2) ----------
// grid (NSEQ, BATCH, 6): zz -> t = zz%3, k = 1 + zz/3.
__global__ __launch_bounds__(256) void att_kernel(void) {
    int i = blockIdx.x, b = blockIdx.y, zz = blockIdx.z;
    int t = zz % 3, kk = zz / 3, k = kk + 1;
    int tid = threadIdx.x;
    int lane = tid & 31, wid = tid >> 5;
    int z = t * 3 + k;

    __shared__ float sf2[NSEQ];
    __shared__ unsigned smask[NWRD];
    __shared__ float redmax[8];
    __shared__ float redsum[8];

    const float* f2p = &g_f2[(size_t)z * BATCH * NSEQ + (size_t)b * NSEQ];
    for (int j = tid; j < NSEQ; j += 256) sf2[j] = f2p[j];
    if (tid < NWRD)
        smask[tid] = g_mask[k][(((size_t)b * NT + t) * NSEQ + i) * NWRD + tid];
    __syncthreads();

    float f1v = g_f1[(size_t)z * BATCH * NSEQ + (size_t)b * NSEQ + i];

    int j0 = tid * 4;
    unsigned mw = (smask[j0 >> 5] >> (j0 & 31)) & 0xFu;

    float e[4];
    float lmax = NEGV;
    #pragma unroll
    for (int q = 0; q < 4; q++) {
        float x = f1v + sf2[j0 + q];
        x = (x > 0.0f) ? x : ALPHAV * x;
        e[q] = ((mw >> q) & 1u) ? x : NEGV;
        lmax = fmaxf(lmax, e[q]);
    }
    #pragma unroll
    for (int off = 16; off > 0; off >>= 1)
        lmax = fmaxf(lmax, __shfl_xor_sync(0xffffffffu, lmax, off));
    if (lane == 0) redmax[wid] = lmax;
    __syncthreads();
    float m = redmax[0];
    #pragma unroll
    for (int w = 1; w < 8; w++) m = fmaxf(m, redmax[w]);

    bool empty = (m < -8.9e15f);
    float p[4];
    float lsum = 0.0f;
    #pragma unroll
    for (int q = 0; q < 4; q++) {
        p[q] = empty ? 1.0f : (((mw >> q) & 1u) ? __expf(e[q] - m) : 0.0f);
        lsum += p[q];
    }
    #pragma unroll
    for (int off = 16; off > 0; off >>= 1)
        lsum += __shfl_xor_sync(0xffffffffu, lsum, off);
    if (lane == 0) redsum[wid] = lsum;
    __syncthreads();
    float s = 0.0f;
    #pragma unroll
    for (int w = 0; w < 8; w++) s += redsum[w];
    float inv = 1.0f / s;

    // write into A-fragment layout: base + word(mt= i/16, kt=j/16, lane) uint4
    unsigned* abase = (unsigned*)(g_attf +
        (((size_t)kk * NT + t) * BATCH + b) * ((size_t)64 * 64 * 32));
    int r = i & 15;
    int rl = (r & 7) * 4;
    int chi = r >> 3;
    int mtw = (i >> 4) * 64;             // * ktiles(64)
    #pragma unroll
    for (int q = 0; q < 4; q += 2) {
        int j = j0 + q;
        int jm = j & 15;
        int kl = jm >> 1;
        int lane_w = rl + (kl & 3);
        int comp = ((jm >= 8) ? 2 : 0) + chi;
        size_t word = ((size_t)(mtw + (j >> 4)) << 5) + lane_w;
        abase[word * 4 + comp] = packh2(p[q] * inv, p[q + 1] * inv);
    }
}

// ---------------- final combine ---------------------------------------------
__global__ void combine_kernel(const float* __restrict__ Ww, const float* __restrict__ bw,
                               const float* __restrict__ Wc, float* __restrict__ out) {
    int bn = blockIdx.x;
    int tid = threadIdx.x;
    __shared__ float sh[NLAY * FD];
    __shared__ float part[NLAY][128];
    __shared__ float sy[NLAY];

    const float* Hp = &g_H[(size_t)bn * NLAY * FD];
    for (int i = tid; i < NLAY * FD; i += 128) sh[i] = Hp[i];
    __syncthreads();

    float loc[NLAY] = {0.0f, 0.0f, 0.0f};
    if (tid < 100) {
        float wc = Wc[tid];
        float bwv = bw[tid];
        #pragma unroll
        for (int k = 0; k < NLAY; k++) {
            float y = bwv;
            #pragma unroll 8
            for (int i = 0; i < FD; i++)
                y = fmaf(sh[k * FD + i], Ww[i * 100 + tid], y);
            loc[k] = tanhf(y) * wc;
        }
    }
    #pragma unroll
    for (int k = 0; k < NLAY; k++) part[k][tid] = loc[k];
    __syncthreads();
    for (int s = 64; s > 0; s >>= 1) {
        if (tid < s) {
            part[0][tid] += part[0][tid + s];
            part[1][tid] += part[1][tid + s];
            part[2][tid] += part[2][tid + s];
        }
        __syncthreads();
    }
    if (tid == 0) {
        float s0 = part[0][0], s1 = part[1][0], s2 = part[2][0];
        float mx = fmaxf(s0, fmaxf(s1, s2));
        float e0 = __expf(s0 - mx), e1 = __expf(s1 - mx), e2 = __expf(s2 - mx);
        float invs = 1.0f / (e0 + e1 + e2);
        sy[0] = e0 * invs; sy[1] = e1 * invs; sy[2] = e2 * invs;
    }
    __syncthreads();

    float w0 = sy[0], w1 = sy[1], w2 = sy[2];
    for (int f = tid; f < FD; f += 128)
        out[(size_t)bn * FD + f] =
            w0 * sh[f] + w1 * sh[FD + f] + w2 * sh[2 * FD + f];
}

// ---------------- launch ----------------------------------------------------
extern "C" void kernel_launch(void* const* d_in, const int* in_sizes, int n_in,
                              void* d_out, int out_size) {
    const float* adj = (const float*)d_in[0];
    const float* X   = (const float*)d_in[1];
    const float* W   = (const float*)d_in[2];
    const float* a1  = (const float*)d_in[3];
    const float* a2  = (const float*)d_in[4];
    const float* Ww  = (const float*)d_in[5];
    const float* bw  = (const float*)d_in[6];
    const float* Wc  = (const float*)d_in[7];
    float* out = (float*)d_out;

    void *ph, *pH, *pxf, *pwf, *paf, *phf;
    cudaGetSymbolAddress(&ph, g_h);
    cudaGetSymbolAddress(&pH, g_H);
    cudaGetSymbolAddress(&pxf, g_xf);
    cudaGetSymbolAddress(&pwf, g_wf);
    cudaGetSymbolAddress(&paf, g_attf);
    cudaGetSymbolAddress(&phf, g_htf);
    float* hbuf = (float*)ph;
    float* Hbuf = (float*)pH;

    // 1. adjacency bitsets + boolean powers (adj^3 via adj * adj^2)
    bits_kernel<<<BATCH * NT * NSEQ, 1024>>>(adj);
    bmm_kernel<<<BATCH * NT * NSEQ, 32>>>(0, 0, 1);
    bmm_kernel<<<BATCH * NT * NSEQ, 32>>>(0, 1, 2);

    // 2. fragment-major fp16 operand prep: X, W
    xf_kernel<<<(BATCH * NSEQ / 16 * (IND / 16) * 32) / 256, 256>>>(X);
    wf_kernel<<<(9 * (FD / 8) * (IND / 16) * 32) / 256, 256>>>(W);

    // 3. h[t,k] = X @ W[t,k]  for all 9 (t,k)
    {
        dim3 grid(FD / BN, (BATCH * NSEQ) / BM, 9);
        tgemm16f<<<grid, 256>>>((const uint4*)pxf, (const uint2*)pwf, hbuf,
                                IND / 16, FD,
                                0LL, (long long)(FD / 8) * (IND / 16) * 32,
                                (long long)BATCH * NSEQ * FD,
                                0LL, 0LL, 1);
    }

    // 4. f1/f2 projections
    f_kernel<<<(9 * BATCH * NSEQ) / 8, 256>>>(a1, a2);

    // 5. h B-fragments for k=1,2 relations
    htf_kernel<<<(6 * BATCH * 32 * 64 * 32) / 256, 256>>>();

    // 6. sparse layer k=0
    spmm_kernel<<<dim3(NSEQ, BATCH), 256>>>(0, Hbuf);

    // 7. all dense masked-softmax rows (k=1,2 x t=0..2), A-fragment output
    att_kernel<<<dim3(NSEQ, BATCH, 6), 256>>>();

    // 8. dense layers k=1,2: one segmented-K fragment GEMM each
    for (int k = 1; k < NLAY; k++) {
        dim3 grid(FD / BN, NSEQ / BM, BATCH);
        tgemm16f<<<grid, 256>>>(
            (const uint4*)paf + (size_t)(k - 1) * NT * BATCH * 64 * 64 * 32,
            (const uint2*)phf + (size_t)(k - 1) * NT * BATCH * 32 * 64 * 32,
            Hbuf + k * FD,
            NSEQ / 16, NLAY * FD,
            (long long)64 * 64 * 32,                // A b-stride (words)
            (long long)32 * 64 * 32,                // B b-stride (words)
            (long long)NSEQ * NLAY * FD,            // C b-stride
            (long long)BATCH * 64 * 64 * 32,        // A t-stride (words)
            (long long)BATCH * 32 * 64 * 32,        // B t-stride (words)
            NT);
    }

    // 9. combine
    combine_kernel<<<BATCH * NSEQ, 128>>>(Ww, bw, Wc, out);
}

// round 13
// speedup vs baseline: 2.2410x; 1.0680x over previous
#include <cuda_runtime.h>
#include <cuda_fp16.h>
#include <cstdint>

#define BATCH 16
#define NT 3
#define NSEQ 1024
#define IND 512
#define FD 256
#define NLAY 3
#define NWRD 32
#define ALPHAV 0.2f
#define NEGV -9e15f

// ---------------- scratch (device globals; no allocations allowed) ----------
__device__ unsigned g_mask[NLAY][BATCH * NT * NSEQ * NWRD];
__device__ float g_h[(size_t)9 * BATCH * NSEQ * FD];
__device__ float g_f1[9 * BATCH * NSEQ];
__device__ float g_f2[9 * BATCH * NSEQ];
// fragment-major operand buffers
__device__ uint4 g_xf[(size_t)(BATCH * NSEQ / 16) * (IND / 16) * 32];       // 16MB
__device__ uint2 g_wf[9 * (FD / 8) * (IND / 16) * 32];                      // 2.4MB
__device__ uint4 g_attf[(size_t)2 * NT * BATCH * 64 * 64 * 32];             // 201MB
__device__ uint2 g_htf[(size_t)6 * BATCH * 32 * 64 * 32];                   // 50MB
__device__ float g_H[(size_t)BATCH * NSEQ * NLAY * FD];

__device__ __forceinline__ unsigned packh2(float a, float b) {
    __half2 h = __floats2half2_rn(a, b);
    return *(unsigned*)&h;
}

// ---------------- adj -> bitset --------------------------------------------
__global__ void bits_kernel(const float* __restrict__ adj) {
    int r = blockIdx.x;
    int tid = threadIdx.x;
    float v = adj[(size_t)r * NSEQ + tid];
    unsigned bal = __ballot_sync(0xffffffffu, v > 0.0f);
    if ((tid & 31) == 0) g_mask[0][(size_t)r * NWRD + (tid >> 5)] = bal;
}

__global__ void bmm_kernel(int lft, int rgt, int dst) {
    int r = blockIdx.x;
    int bt = r / NSEQ;
    int lane = threadIdx.x;
    const unsigned* lrow = &g_mask[lft][(size_t)r * NWRD];
    const unsigned* rbase = &g_mask[rgt][(size_t)bt * NSEQ * NWRD];
    unsigned myw = lrow[lane];
    unsigned acc = 0;
    #pragma unroll 1
    for (int w = 0; w < NWRD; ++w) {
        unsigned bitsw = __shfl_sync(0xffffffffu, myw, w);
        while (bitsw) {
            int j = (w << 5) + (__ffs(bitsw) - 1);
            bitsw &= bitsw - 1;
            acc |= rbase[(size_t)j * NWRD + lane];
        }
    }
    g_mask[dst][(size_t)r * NWRD + lane] = acc;
}

// ---------------- operand prep (fragment-major) ------------------------------
__global__ void xf_kernel(const float* __restrict__ X) {
    int idx = blockIdx.x * blockDim.x + threadIdx.x;
    int lane = idx & 31;
    int kt = (idx >> 5) & 31;
    int mt = idx >> 10;
    int m = mt * 16 + (lane >> 2);
    int k = kt * 16 + (lane & 3) * 2;
    const float* p0 = X + (size_t)m * IND + k;
    const float* p8 = p0 + (size_t)8 * IND;
    uint4 t;
    t.x = packh2(p0[0], p0[1]);
    t.y = packh2(p8[0], p8[1]);
    t.z = packh2(p0[8], p0[9]);
    t.w = packh2(p8[8], p8[9]);
    g_xf[idx] = t;
}

__global__ void wf_kernel(const float* __restrict__ W) {
    int idx = blockIdx.x * blockDim.x + threadIdx.x;
    int lane = idx & 31;
    int kt = (idx >> 5) & 31;
    int nt = (idx >> 10) & 31;
    int z = idx >> 15;
    int n = nt * 8 + (lane >> 2);
    int k = kt * 16 + (lane & 3) * 2;
    const float* Wz = W + (size_t)z * IND * FD;
    uint2 t;
    t.x = packh2(Wz[(size_t)k * FD + n], Wz[(size_t)(k + 1) * FD + n]);
    t.y = packh2(Wz[(size_t)(k + 8) * FD + n], Wz[(size_t)(k + 9) * FD + n]);
    g_wf[idx] = t;
}

__global__ void htf_kernel() {
    int idx = blockIdx.x * blockDim.x + threadIdx.x;
    int lane = idx & 31;
    int kt = (idx >> 5) & 63;
    int nt = (idx >> 11) & 31;
    int b = (idx >> 16) & 15;
    int z6 = idx >> 20;                  // kk*3 + t
    int t = z6 % 3, kk = z6 / 3;
    int z = t * 3 + (kk + 1);
    int f = nt * 8 + (lane >> 2);
    int s = kt * 16 + (lane & 3) * 2;
    const float* src = g_h + ((size_t)z * BATCH + b) * NSEQ * FD;
    uint2 w;
    w.x = packh2(src[(size_t)s * FD + f], src[(size_t)(s + 1) * FD + f]);
    w.y = packh2(src[(size_t)(s + 8) * FD + f], src[(size_t)(s + 9) * FD + f]);
    g_htf[idx] = w;
}

// ---------------- cp.async helpers ------------------------------------------
__device__ __forceinline__ uint32_t smem_u32(const void* p) {
    return (uint32_t)__cvta_generic_to_shared(p);
}
#define CPA16(dst, src) \
    asm volatile("cp.async.cg.shared.global [%0], [%1], 16;" :: "r"(dst), "l"(src))
#define CPA8(dst, src) \
    asm volatile("cp.async.ca.shared.global [%0], [%1], 8;" :: "r"(dst), "l"(src))
#define CPCOMMIT() asm volatile("cp.async.commit_group;" ::: "memory")
#define CPWAIT2()  asm volatile("cp.async.wait_group 2;" ::: "memory")

// ---------------- fp16 fragment-direct GEMM (128x128, BK=16, 4-stage) -------
// z decomposes as z1 = z % nz1, z2 = z / nz1; offsets = z1*s? + z2*s?2.
#define BM 128
#define BN 128

__global__ __launch_bounds__(256) void tgemm16f(
    const uint4* __restrict__ Af, const uint2* __restrict__ Bf, float* __restrict__ C,
    int kiter, int ldc, int nz1,
    long long sA, long long sB, long long sC,
    long long sA2, long long sB2, long long sC2,
    long long sAseg, long long sBseg, int nseg)
{
    __shared__ uint4 As[4][8][32];
    __shared__ uint2 Bs[4][16][32];

    int tid = threadIdx.x;
    int lane = tid & 31;
    int wid = tid >> 5;
    int wm = wid >> 2;
    int wn = wid & 3;
    int z = blockIdx.z;
    int z2 = z / nz1;
    int z1 = z - z2 * nz1;
    int mt0 = blockIdx.y * 8;
    int nt0 = blockIdx.x * 16;

    C += (size_t)z1 * sC + (size_t)z2 * sC2;

    const uint4* asrc = Af + (size_t)z1 * sA + (size_t)z2 * sA2
                        + ((size_t)(mt0 + wid) * kiter) * 32 + lane;
    const uint2* bsrc0 = Bf + (size_t)z1 * sB + (size_t)z2 * sB2
                         + ((size_t)(nt0 + 2 * wid) * kiter) * 32 + lane;
    const uint2* bsrc1 = bsrc0 + (size_t)kiter * 32;
    long long awrap = sAseg - (long long)kiter * 32;
    long long bwrap = sBseg - (long long)kiter * 32;
    int ktc = 0;

    uint32_t sa = smem_u32(&As[0][wid][lane]);
    uint32_t sb0 = smem_u32(&Bs[0][2 * wid][lane]);
    uint32_t sb1 = smem_u32(&Bs[0][2 * wid + 1][lane]);

    #define ISSUE(st)                                                          \
        do {                                                                   \
            CPA16(sa + (st) * 4096, asrc);                                     \
            CPA8(sb0 + (st) * 4096, bsrc0);                                    \
            CPA8(sb1 + (st) * 4096, bsrc1);                                    \
            CPCOMMIT();                                                        \
            asrc += 32; bsrc0 += 32; bsrc1 += 32;                              \
            if (++ktc == kiter) {                                              \
                ktc = 0;                                                       \
                asrc += awrap; bsrc0 += bwrap; bsrc1 += bwrap;                 \
            }                                                                  \
        } while (0)

    float d[4][4][4];
    #pragma unroll
    for (int i = 0; i < 4; i++)
        #pragma unroll
        for (int j = 0; j < 4; j++)
            #pragma unroll
            for (int r = 0; r < 4; r++) d[i][j][r] = 0.0f;

    int total = nseg * kiter;
    ISSUE(0);
    if (total > 1) { ISSUE(1); } else { CPCOMMIT(); }
    if (total > 2) { ISSUE(2); } else { CPCOMMIT(); }

    for (int c = 0; c < total; c++) {
        CPWAIT2();
        __syncthreads();
        if (c + 3 < total) { ISSUE((c + 3) & 3); } else { CPCOMMIT(); }
        int cur = c & 3;
        unsigned af[4][4];
        unsigned bf[4][2];
        #pragma unroll
        for (int mt = 0; mt < 4; mt++) {
            uint4 t = As[cur][wm * 4 + mt][lane];
            af[mt][0] = t.x; af[mt][1] = t.y; af[mt][2] = t.z; af[mt][3] = t.w;
        }
        #pragma unroll
        for (int nt = 0; nt < 4; nt++) {
            uint2 t = Bs[cur][wn * 4 + nt][lane];
            bf[nt][0] = t.x; bf[nt][1] = t.y;
        }
        #pragma unroll
        for (int mt = 0; mt < 4; mt++)
            #pragma unroll
            for (int nt = 0; nt < 4; nt++) {
                asm volatile(
                    "mma.sync.aligned.m16n8k16.row.col.f32.f16.f16.f32 "
                    "{%0,%1,%2,%3}, {%4,%5,%6,%7}, {%8,%9}, {%0,%1,%2,%3};"
                    : "+f"(d[mt][nt][0]), "+f"(d[mt][nt][1]),
                      "+f"(d[mt][nt][2]), "+f"(d[mt][nt][3])
                    : "r"(af[mt][0]), "r"(af[mt][1]),
                      "r"(af[mt][2]), "r"(af[mt][3]),
                      "r"(bf[nt][0]), "r"(bf[nt][1]));
            }
        __syncthreads();
    }

    int cr = lane >> 2;
    int cc = (lane & 3) * 2;
    int bm = blockIdx.y * BM, bn = blockIdx.x * BN;
    #pragma unroll
    for (int mt = 0; mt < 4; mt++) {
        #pragma unroll
        for (int half = 0; half < 2; half++) {
            int row = bm + wm * 64 + mt * 16 + cr + half * 8;
            float* cp = C + (size_t)row * ldc + bn + wn * 32 + cc;
            #pragma unroll
            for (int nt = 0; nt < 4; nt++) {
                float2 v = make_float2(d[mt][nt][half * 2], d[mt][nt][half * 2 + 1]);
                *(float2*)(cp + nt * 8) = v;
            }
        }
    }
}

// ---------------- f1/f2 -----------------------------------------------------
__global__ void f_kernel(const float* __restrict__ a1, const float* __restrict__ a2) {
    int gw = (blockIdx.x * blockDim.x + threadIdx.x) >> 5;
    int lane = threadIdx.x & 31;
    if (gw >= 9 * BATCH * NSEQ) return;
    int z = gw / (BATCH * NSEQ);
    const float* hp = &g_h[(size_t)gw * FD];
    const float* a1p = a1 + (size_t)z * FD;
    const float* a2p = a2 + (size_t)z * FD;
    float s1 = 0.0f, s2 = 0.0f;
    #pragma unroll
    for (int i = lane; i < FD; i += 32) {
        float hv = hp[i];
        s1 = fmaf(hv, a1p[i], s1);
        s2 = fmaf(hv, a2p[i], s2);
    }
    #pragma unroll
    for (int off = 16; off > 0; off >>= 1) {
        s1 += __shfl_down_sync(0xffffffffu, s1, off);
        s2 += __shfl_down_sync(0xffffffffu, s2, off);
    }
    if (lane == 0) { g_f1[gw] = s1; g_f2[gw] = s2; }
}

// ---------------- fused sparse softmax + SpMM (layer k=0 only) --------------
__global__ __launch_bounds__(256) void spmm_kernel(int k, float* __restrict__ Hout) {
    int n = blockIdx.x, b = blockIdx.y;
    int tid = threadIdx.x;

    __shared__ int   list[NSEQ];
    __shared__ float pn[NSEQ];
    __shared__ int   s_cnt;
    __shared__ float red[256];

    float acc = 0.0f;

    for (int t = 0; t < NT; t++) {
        int z = t * 3 + k;
        if (tid == 0) s_cnt = 0;
        __syncthreads();
        if (tid < NWRD) {
            unsigned w = g_mask[k][(((size_t)b * NT + t) * NSEQ + n) * NWRD + tid];
            while (w) {
                int j = (tid << 5) + (__ffs(w) - 1);
                w &= w - 1;
                int p = atomicAdd(&s_cnt, 1);
                list[p] = j;
            }
        }
        __syncthreads();
        int cnt = s_cnt;

        const float* f2p = &g_f2[(size_t)z * BATCH * NSEQ + (size_t)b * NSEQ];
        float f1v = g_f1[(size_t)z * BATCH * NSEQ + (size_t)b * NSEQ + n];
        const float* hp = &g_h[((size_t)z * BATCH + b) * NSEQ * FD];

        if (cnt == 0) {
            float a = 0.0f;
            for (int j = 0; j < NSEQ; j++) a += hp[(size_t)j * FD + tid];
            acc += a * (1.0f / NSEQ);
            __syncthreads();
            continue;
        }

        float lmax = -1e30f;
        for (int i = tid; i < cnt; i += 256) {
            float x = f1v + f2p[list[i]];
            x = (x > 0.0f) ? x : ALPHAV * x;
            pn[i] = x;
            lmax = fmaxf(lmax, x);
        }
        red[tid] = lmax;
        __syncthreads();
        for (int s = 128; s > 0; s >>= 1) {
            if (tid < s) red[tid] = fmaxf(red[tid], red[tid + s]);
            __syncthreads();
        }
        float m = red[0];
        __syncthreads();

        float lsum = 0.0f;
        for (int i = tid; i < cnt; i += 256) {
            float p = __expf(pn[i] - m);
            pn[i] = p;
            lsum += p;
        }
        red[tid] = lsum;
        __syncthreads();
        for (int s = 128; s > 0; s >>= 1) {
            if (tid < s) red[tid] += red[tid + s];
            __syncthreads();
        }
        float inv = 1.0f / red[0];
        __syncthreads();

        int i = 0;
        for (; i + 4 <= cnt; i += 4) {
            int j0 = list[i], j1 = list[i + 1], j2 = list[i + 2], j3 = list[i + 3];
            float p0 = pn[i] * inv, p1 = pn[i + 1] * inv;
            float p2 = pn[i + 2] * inv, p3 = pn[i + 3] * inv;
            float h0 = hp[(size_t)j0 * FD + tid];
            float h1 = hp[(size_t)j1 * FD + tid];
            float h2 = hp[(size_t)j2 * FD + tid];
            float h3 = hp[(size_t)j3 * FD + tid];
            acc = fmaf(p0, h0, acc);
            acc = fmaf(p1, h1, acc);
            acc = fmaf(p2, h2, acc);
            acc = fmaf(p3, h3, acc);
        }
        for (; i < cnt; i++)
            acc = fmaf(pn[i] * inv, hp[(size_t)list[i] * FD + tid], acc);
        __syncthreads();
    }

    Hout[(((size_t)b * NSEQ + n) * NLAY + k) * FD + tid] = acc;
}

// ---------------- masked softmax (16 rows/block) -> coalesced A-fragments ---
// grid (NSEQ/16, BATCH, 6): zz -> t = zz%3, k = 1 + zz/3.
// Half-warp per row: row = tid/16, c = tid%16; thread handles j = 2c + 32s.
__global__ __launch_bounds__(256) void att_kernel(void) {
    int mt = blockIdx.x, b = blockIdx.y, zz = blockIdx.z;
    int t = zz % 3, kk = zz / 3, k = kk + 1;
    int tid = threadIdx.x;
    int row = tid >> 4, c = tid & 15;
    int z = t * 3 + k;

    __shared__ float sf2[NSEQ];                 // 4KB
    __shared__ unsigned smask[16][NWRD];        // 2KB
    __shared__ unsigned stage[16 * 512];        // 32KB (pair-packed fp16)

    const float* f2p = &g_f2[(size_t)z * BATCH * NSEQ + (size_t)b * NSEQ];
    for (int j = tid; j < NSEQ; j += 256) sf2[j] = f2p[j];
    {
        const unsigned* mb = &g_mask[k][(((size_t)b * NT + t) * NSEQ + mt * 16) * NWRD];
        for (int i = tid; i < 16 * NWRD; i += 256)
            smask[i >> 5][i & 31] = mb[i];
    }
    __syncthreads();

    float f1v = g_f1[(size_t)z * BATCH * NSEQ + (size_t)b * NSEQ + mt * 16 + row];
    const unsigned* mrow = smask[row];

    float pv[64];
    float lmax = NEGV;
    #pragma unroll
    for (int s = 0; s < 32; s++) {
        unsigned m2 = (mrow[s] >> (2 * c)) & 3u;
        float x0 = f1v + sf2[32 * s + 2 * c];
        x0 = (x0 > 0.0f) ? x0 : ALPHAV * x0;
        float x1 = f1v + sf2[32 * s + 2 * c + 1];
        x1 = (x1 > 0.0f) ? x1 : ALPHAV * x1;
        float e0 = (m2 & 1u) ? x0 : NEGV;
        float e1 = (m2 & 2u) ? x1 : NEGV;
        pv[2 * s] = e0;
        pv[2 * s + 1] = e1;
        lmax = fmaxf(lmax, fmaxf(e0, e1));
    }
    #pragma unroll
    for (int off = 8; off > 0; off >>= 1)
        lmax = fmaxf(lmax, __shfl_xor_sync(0xffffffffu, lmax, off));
    float m = lmax;

    bool empty = (m < -8.9e15f);
    float lsum = 0.0f;
    #pragma unroll
    for (int q = 0; q < 64; q++) {
        float p = empty ? 1.0f : __expf(pv[q] - m);
        pv[q] = p;
        lsum += p;
    }
    #pragma unroll
    for (int off = 8; off > 0; off >>= 1)
        lsum += __shfl_xor_sync(0xffffffffu, lsum, off);
    float inv = 1.0f / lsum;

    unsigned* srow = &stage[row * 512];
    #pragma unroll
    for (int s = 0; s < 32; s++)
        srow[c + 16 * s] = packh2(pv[2 * s] * inv, pv[2 * s + 1] * inv);
    __syncthreads();

    // coalesced fragment output: 2048 uint4, 8 per thread
    uint4* obase = g_attf + (((size_t)kk * NT + t) * BATCH + b) * ((size_t)64 * 64 * 32)
                   + (size_t)mt * 64 * 32;
    #pragma unroll
    for (int w = 0; w < 8; w++) {
        int widx = tid + 256 * w;
        int ktw = widx >> 5;
        int lw = widx & 31;
        int r0 = lw >> 2;
        int p0 = ktw * 8 + (lw & 3);
        uint4 u;
        u.x = stage[r0 * 512 + p0];
        u.y = stage[(r0 + 8) * 512 + p0];
        u.z = stage[r0 * 512 + p0 + 4];
        u.w = stage[(r0 + 8) * 512 + p0 + 4];
        obase[widx] = u;
    }
}

// ---------------- final combine ---------------------------------------------
__global__ void combine_kernel(const float* __restrict__ Ww, const float* __restrict__ bw,
                               const float* __restrict__ Wc, float* __restrict__ out) {
    int bn = blockIdx.x;
    int tid = threadIdx.x;
    __shared__ float sh[NLAY * FD];
    __shared__ float part[NLAY][128];
    __shared__ float sy[NLAY];

    const float* Hp = &g_H[(size_t)bn * NLAY * FD];
    for (int i = tid; i < NLAY * FD; i += 128) sh[i] = Hp[i];
    __syncthreads();

    float loc[NLAY] = {0.0f, 0.0f, 0.0f};
    if (tid < 100) {
        float wc = Wc[tid];
        float bwv = bw[tid];
        #pragma unroll
        for (int k = 0; k < NLAY; k++) {
            float y = bwv;
            #pragma unroll 8
            for (int i = 0; i < FD; i++)
                y = fmaf(sh[k * FD + i], Ww[i * 100 + tid], y);
            loc[k] = tanhf(y) * wc;
        }
    }
    #pragma unroll
    for (int k = 0; k < NLAY; k++) part[k][tid] = loc[k];
    __syncthreads();
    for (int s = 64; s > 0; s >>= 1) {
        if (tid < s) {
            part[0][tid] += part[0][tid + s];
            part[1][tid] += part[1][tid + s];
            part[2][tid] += part[2][tid + s];
        }
        __syncthreads();
    }
    if (tid == 0) {
        float s0 = part[0][0], s1 = part[1][0], s2 = part[2][0];
        float mx = fmaxf(s0, fmaxf(s1, s2));
        float e0 = __expf(s0 - mx), e1 = __expf(s1 - mx), e2 = __expf(s2 - mx);
        float invs = 1.0f / (e0 + e1 + e2);
        sy[0] = e0 * invs; sy[1] = e1 * invs; sy[2] = e2 * invs;
    }
    __syncthreads();

    float w0 = sy[0], w1 = sy[1], w2 = sy[2];
    for (int f = tid; f < FD; f += 128)
        out[(size_t)bn * FD + f] =
            w0 * sh[f] + w1 * sh[FD + f] + w2 * sh[2 * FD + f];
}

// ---------------- launch ----------------------------------------------------
extern "C" void kernel_launch(void* const* d_in, const int* in_sizes, int n_in,
                              void* d_out, int out_size) {
    const float* adj = (const float*)d_in[0];
    const float* X   = (const float*)d_in[1];
    const float* W   = (const float*)d_in[2];
    const float* a1  = (const float*)d_in[3];
    const float* a2  = (const float*)d_in[4];
    const float* Ww  = (const float*)d_in[5];
    const float* bw  = (const float*)d_in[6];
    const float* Wc  = (const float*)d_in[7];
    float* out = (float*)d_out;

    void *ph, *pH, *pxf, *pwf, *paf, *phf;
    cudaGetSymbolAddress(&ph, g_h);
    cudaGetSymbolAddress(&pH, g_H);
    cudaGetSymbolAddress(&pxf, g_xf);
    cudaGetSymbolAddress(&pwf, g_wf);
    cudaGetSymbolAddress(&paf, g_attf);
    cudaGetSymbolAddress(&phf, g_htf);
    float* hbuf = (float*)ph;
    float* Hbuf = (float*)pH;

    // 1. adjacency bitsets + boolean powers (adj^3 via adj * adj^2)
    bits_kernel<<<BATCH * NT * NSEQ, 1024>>>(adj);
    bmm_kernel<<<BATCH * NT * NSEQ, 32>>>(0, 0, 1);
    bmm_kernel<<<BATCH * NT * NSEQ, 32>>>(0, 1, 2);

    // 2. fragment-major fp16 operand prep: X, W
    xf_kernel<<<(BATCH * NSEQ / 16 * (IND / 16) * 32) / 256, 256>>>(X);
    wf_kernel<<<(9 * (FD / 8) * (IND / 16) * 32) / 256, 256>>>(W);

    // 3. h[t,k] = X @ W[t,k]  for all 9 (t,k)
    {
        dim3 grid(FD / BN, (BATCH * NSEQ) / BM, 9);
        tgemm16f<<<grid, 256>>>((const uint4*)pxf, (const uint2*)pwf, hbuf,
                                IND / 16, FD, 9,
                                0LL, (long long)(FD / 8) * (IND / 16) * 32,
                                (long long)BATCH * NSEQ * FD,
                                0LL, 0LL, 0LL,
                                0LL, 0LL, 1);
    }

    // 4. f1/f2 projections
    f_kernel<<<(9 * BATCH * NSEQ) / 8, 256>>>(a1, a2);

    // 5. h B-fragments for k=1,2 relations
    htf_kernel<<<(6 * BATCH * 32 * 64 * 32) / 256, 256>>>();

    // 6. sparse layer k=0
    spmm_kernel<<<dim3(NSEQ, BATCH), 256>>>(0, Hbuf);

    // 7. all dense masked-softmax rows (k=1,2 x t=0..2), coalesced A-fragments
    att_kernel<<<dim3(NSEQ / 16, BATCH, 6), 256>>>();

    // 8. dense layers k=1,2 in ONE launch: grid.z = (kk, b), segmented over t
    {
        dim3 grid(FD / BN, NSEQ / BM, 2 * BATCH);
        tgemm16f<<<grid, 256>>>(
            (const uint4*)paf, (const uint2*)phf,
            Hbuf + 1 * FD,
            NSEQ / 16, NLAY * FD, BATCH,
            (long long)64 * 64 * 32,                     // A b-stride (uint4)
            (long long)32 * 64 * 32,                     // B b-stride (uint2)
            (long long)NSEQ * NLAY * FD,                 // C b-stride
            (long long)NT * BATCH * 64 * 64 * 32,        // A kk-stride
            (long long)NT * BATCH * 32 * 64 * 32,        // B kk-stride
            (long long)FD,                               // C kk-stride
            (long long)BATCH * 64 * 64 * 32,             // A t-seg stride
            (long long)BATCH * 32 * 64 * 32,             // B t-seg stride
            NT);
    }

    // 9. combine
    combine_kernel<<<BATCH * NSEQ, 128>>>(Ww, bw, Wc, out);
}

// round 14
// speedup vs baseline: 2.3098x; 1.0307x over previous
#include <cuda_runtime.h>
#include <cuda_fp16.h>
#include <cstdint>

#define BATCH 16
#define NT 3
#define NSEQ 1024
#define IND 512
#define FD 256
#define NLAY 3
#define NWRD 32
#define ALPHAV 0.2f
#define NEGV -9e15f

// ---------------- scratch (device globals; no allocations allowed) ----------
__device__ unsigned g_mask[NLAY][BATCH * NT * NSEQ * NWRD];
__device__ float g_h[(size_t)9 * BATCH * NSEQ * FD];
__device__ float g_f1[9 * BATCH * NSEQ];
__device__ float g_f2[9 * BATCH * NSEQ];
// fragment-major operand buffers
__device__ uint4 g_xf[(size_t)(BATCH * NSEQ / 16) * (IND / 16) * 32];       // 16MB
__device__ uint2 g_wf[9 * (FD / 8) * (IND / 16) * 32];                      // 2.4MB
__device__ uint4 g_attf[(size_t)2 * NT * BATCH * 64 * 64 * 32];             // 201MB
__device__ uint2 g_htf[(size_t)6 * BATCH * 32 * 64 * 32];                   // 50MB
__device__ float g_H[(size_t)BATCH * NSEQ * NLAY * FD];

__device__ __forceinline__ unsigned packh2(float a, float b) {
    __half2 h = __floats2half2_rn(a, b);
    return *(unsigned*)&h;
}

// ---------------- adj -> bitset --------------------------------------------
__global__ void bits_kernel(const float* __restrict__ adj) {
    int r = blockIdx.x;
    int tid = threadIdx.x;
    float v = adj[(size_t)r * NSEQ + tid];
    unsigned bal = __ballot_sync(0xffffffffu, v > 0.0f);
    if ((tid & 31) == 0) g_mask[0][(size_t)r * NWRD + (tid >> 5)] = bal;
}

__global__ void zero_f_kernel() {
    int i = blockIdx.x * blockDim.x + threadIdx.x;
    if (i < 9 * BATCH * NSEQ) { g_f1[i] = 0.0f; g_f2[i] = 0.0f; }
}

__global__ void bmm_kernel(int lft, int rgt, int dst) {
    int r = blockIdx.x;
    int bt = r / NSEQ;
    int lane = threadIdx.x;
    const unsigned* lrow = &g_mask[lft][(size_t)r * NWRD];
    const unsigned* rbase = &g_mask[rgt][(size_t)bt * NSEQ * NWRD];
    unsigned myw = lrow[lane];
    unsigned acc = 0;
    #pragma unroll 1
    for (int w = 0; w < NWRD; ++w) {
        unsigned bitsw = __shfl_sync(0xffffffffu, myw, w);
        while (bitsw) {
            int j = (w << 5) + (__ffs(bitsw) - 1);
            bitsw &= bitsw - 1;
            acc |= rbase[(size_t)j * NWRD + lane];
        }
    }
    g_mask[dst][(size_t)r * NWRD + lane] = acc;
}

// ---------------- operand prep (fragment-major) ------------------------------
__global__ void xf_kernel(const float* __restrict__ X) {
    int idx = blockIdx.x * blockDim.x + threadIdx.x;
    int lane = idx & 31;
    int kt = (idx >> 5) & 31;
    int mt = idx >> 10;
    int m = mt * 16 + (lane >> 2);
    int k = kt * 16 + (lane & 3) * 2;
    const float* p0 = X + (size_t)m * IND + k;
    const float* p8 = p0 + (size_t)8 * IND;
    uint4 t;
    t.x = packh2(p0[0], p0[1]);
    t.y = packh2(p8[0], p8[1]);
    t.z = packh2(p0[8], p0[9]);
    t.w = packh2(p8[8], p8[9]);
    g_xf[idx] = t;
}

__global__ void wf_kernel(const float* __restrict__ W) {
    int idx = blockIdx.x * blockDim.x + threadIdx.x;
    int lane = idx & 31;
    int kt = (idx >> 5) & 31;
    int nt = (idx >> 10) & 31;
    int z = idx >> 15;
    int n = nt * 8 + (lane >> 2);
    int k = kt * 16 + (lane & 3) * 2;
    const float* Wz = W + (size_t)z * IND * FD;
    uint2 t;
    t.x = packh2(Wz[(size_t)k * FD + n], Wz[(size_t)(k + 1) * FD + n]);
    t.y = packh2(Wz[(size_t)(k + 8) * FD + n], Wz[(size_t)(k + 9) * FD + n]);
    g_wf[idx] = t;
}

__global__ void htf_kernel() {
    int idx = blockIdx.x * blockDim.x + threadIdx.x;
    int lane = idx & 31;
    int kt = (idx >> 5) & 63;
    int nt = (idx >> 11) & 31;
    int b = (idx >> 16) & 15;
    int z6 = idx >> 20;                  // kk*3 + t
    int t = z6 % 3, kk = z6 / 3;
    int z = t * 3 + (kk + 1);
    int f = nt * 8 + (lane >> 2);
    int s = kt * 16 + (lane & 3) * 2;
    const float* src = g_h + ((size_t)z * BATCH + b) * NSEQ * FD;
    uint2 w;
    w.x = packh2(src[(size_t)s * FD + f], src[(size_t)(s + 1) * FD + f]);
    w.y = packh2(src[(size_t)(s + 8) * FD + f], src[(size_t)(s + 9) * FD + f]);
    g_htf[idx] = w;
}

// ---------------- cp.async helpers ------------------------------------------
__device__ __forceinline__ uint32_t smem_u32(const void* p) {
    return (uint32_t)__cvta_generic_to_shared(p);
}
#define CPA16(dst, src) \
    asm volatile("cp.async.cg.shared.global [%0], [%1], 16;" :: "r"(dst), "l"(src))
#define CPA8(dst, src) \
    asm volatile("cp.async.ca.shared.global [%0], [%1], 8;" :: "r"(dst), "l"(src))
#define CPCOMMIT() asm volatile("cp.async.commit_group;" ::: "memory")
#define CPWAIT1()  asm volatile("cp.async.wait_group 1;" ::: "memory")

// ---------------- fp16 fragment-direct GEMM (128x128, BK=32 stage, 3-stage) -
// z decomposes as z1 = z % nz1, z2 = z / nz1.
// If doF: also accumulate f1/f2 = C-row . a1/a2 via atomics (gemm1 only).
#define BM 128
#define BN 128
#define STG_A (8 * 2 * 32)        // uint4 words per A stage
#define STG_B (16 * 2 * 32)       // uint2 words per B stage

__global__ __launch_bounds__(256) void tgemm16f(
    const uint4* __restrict__ Af, const uint2* __restrict__ Bf, float* __restrict__ C,
    int kiter, int ldc, int nz1,
    long long sA, long long sB, long long sC,
    long long sA2, long long sB2, long long sC2,
    long long sAseg, long long sBseg, int nseg,
    int doF, const float* __restrict__ A1, const float* __restrict__ A2)
{
    __shared__ uint4 As[3][2][8][32];
    __shared__ uint2 Bs[3][2][16][32];
    __shared__ float sa1[128];
    __shared__ float sa2[128];

    int tid = threadIdx.x;
    int lane = tid & 31;
    int wid = tid >> 5;
    int wm = wid >> 2;
    int wn = wid & 3;
    int z = blockIdx.z;
    int z2 = z / nz1;
    int z1 = z - z2 * nz1;
    int mt0 = blockIdx.y * 8;
    int nt0 = blockIdx.x * 16;

    C += (size_t)z1 * sC + (size_t)z2 * sC2;

    const uint4* asrc = Af + (size_t)z1 * sA + (size_t)z2 * sA2
                        + ((size_t)(mt0 + wid) * kiter) * 32 + lane;
    const uint2* bsrc0 = Bf + (size_t)z1 * sB + (size_t)z2 * sB2
                         + ((size_t)(nt0 + 2 * wid) * kiter) * 32 + lane;
    const uint2* bsrc1 = bsrc0 + (size_t)kiter * 32;
    long long awrap = sAseg - (long long)kiter * 32;
    long long bwrap = sBseg - (long long)kiter * 32;
    int ktc = 0;

    uint32_t saA0 = smem_u32(&As[0][0][wid][lane]);
    uint32_t saA1 = smem_u32(&As[0][1][wid][lane]);
    uint32_t sbB00 = smem_u32(&Bs[0][0][2 * wid][lane]);
    uint32_t sbB01 = smem_u32(&Bs[0][1][2 * wid][lane]);
    uint32_t sbB10 = smem_u32(&Bs[0][0][2 * wid + 1][lane]);
    uint32_t sbB11 = smem_u32(&Bs[0][1][2 * wid + 1][lane]);

    #define ISSUE(st)                                                          \
        do {                                                                   \
            CPA16(saA0 + (st) * (STG_A * 16), asrc);                           \
            CPA16(saA1 + (st) * (STG_A * 16), asrc + 32);                      \
            CPA8(sbB00 + (st) * (STG_B * 8), bsrc0);                           \
            CPA8(sbB01 + (st) * (STG_B * 8), bsrc0 + 32);                      \
            CPA8(sbB10 + (st) * (STG_B * 8), bsrc1);                           \
            CPA8(sbB11 + (st) * (STG_B * 8), bsrc1 + 32);                      \
            CPCOMMIT();                                                        \
            asrc += 64; bsrc0 += 64; bsrc1 += 64;                              \
            ktc += 2;                                                          \
            if (ktc == kiter) {                                                \
                ktc = 0;                                                       \
                asrc += awrap; bsrc0 += bwrap; bsrc1 += bwrap;                 \
            }                                                                  \
        } while (0)

    float d[4][4][4];
    #pragma unroll
    for (int i = 0; i < 4; i++)
        #pragma unroll
        for (int j = 0; j < 4; j++)
            #pragma unroll
            for (int r = 0; r < 4; r++) d[i][j][r] = 0.0f;

    int total = (nseg * kiter) >> 1;     // iterations of 2 ktiles each
    ISSUE(0);
    if (total > 1) { ISSUE(1); } else { CPCOMMIT(); }

    for (int c = 0; c < total; c++) {
        CPWAIT1();
        __syncthreads();
        if (c + 2 < total) { ISSUE((c + 2) % 3); } else { CPCOMMIT(); }
        int cur = c % 3;
        #pragma unroll
        for (int kt = 0; kt < 2; kt++) {
            unsigned af[4][4];
            unsigned bf[4][2];
            #pragma unroll
            for (int mt = 0; mt < 4; mt++) {
                uint4 t = As[cur][kt][wm * 4 + mt][lane];
                af[mt][0] = t.x; af[mt][1] = t.y; af[mt][2] = t.z; af[mt][3] = t.w;
            }
            #pragma unroll
            for (int nt = 0; nt < 4; nt++) {
                uint2 t = Bs[cur][kt][wn * 4 + nt][lane];
                bf[nt][0] = t.x; bf[nt][1] = t.y;
            }
            #pragma unroll
            for (int mt = 0; mt < 4; mt++)
                #pragma unroll
                for (int nt = 0; nt < 4; nt++) {
                    asm volatile(
                        "mma.sync.aligned.m16n8k16.row.col.f32.f16.f16.f32 "
                        "{%0,%1,%2,%3}, {%4,%5,%6,%7}, {%8,%9}, {%0,%1,%2,%3};"
                        : "+f"(d[mt][nt][0]), "+f"(d[mt][nt][1]),
                          "+f"(d[mt][nt][2]), "+f"(d[mt][nt][3])
                        : "r"(af[mt][0]), "r"(af[mt][1]),
                          "r"(af[mt][2]), "r"(af[mt][3]),
                          "r"(bf[nt][0]), "r"(bf[nt][1]));
                }
        }
    }

    int cr = lane >> 2;
    int cc = (lane & 3) * 2;
    int bm = blockIdx.y * BM, bn = blockIdx.x * BN;
    #pragma unroll
    for (int mt = 0; mt < 4; mt++) {
        #pragma unroll
        for (int half = 0; half < 2; half++) {
            int row = bm + wm * 64 + mt * 16 + cr + half * 8;
            float* cp = C + (size_t)row * ldc + bn + wn * 32 + cc;
            #pragma unroll
            for (int nt = 0; nt < 4; nt++) {
                float2 v = make_float2(d[mt][nt][half * 2], d[mt][nt][half * 2 + 1]);
                *(float2*)(cp + nt * 8) = v;
            }
        }
    }

    if (doF) {
        // stage a1/a2 slices for this block's 128 columns
        if (tid < 128) {
            sa1[tid] = A1[(size_t)z1 * FD + bn + tid];
            sa2[tid] = A2[(size_t)z1 * FD + bn + tid];
        }
        __syncthreads();
        float* f1g = g_f1 + (size_t)z1 * BATCH * NSEQ;
        float* f2g = g_f2 + (size_t)z1 * BATCH * NSEQ;
        #pragma unroll
        for (int mt = 0; mt < 4; mt++) {
            #pragma unroll
            for (int half = 0; half < 2; half++) {
                int row = bm + wm * 64 + mt * 16 + cr + half * 8;
                float s1 = 0.0f, s2 = 0.0f;
                #pragma unroll
                for (int nt = 0; nt < 4; nt++) {
                    #pragma unroll
                    for (int e = 0; e < 2; e++) {
                        int col = wn * 32 + cc + nt * 8 + e;
                        float v = d[mt][nt][half * 2 + e];
                        s1 = fmaf(v, sa1[col], s1);
                        s2 = fmaf(v, sa2[col], s2);
                    }
                }
                s1 += __shfl_xor_sync(0xffffffffu, s1, 1);
                s1 += __shfl_xor_sync(0xffffffffu, s1, 2);
                s2 += __shfl_xor_sync(0xffffffffu, s2, 1);
                s2 += __shfl_xor_sync(0xffffffffu, s2, 2);
                if ((lane & 3) == 0) {
                    atomicAdd(&f1g[row], s1);
                    atomicAdd(&f2g[row], s2);
                }
            }
        }
    }
}

// ---------------- fused sparse softmax + SpMM (layer k=0 only) --------------
__global__ __launch_bounds__(256) void spmm_kernel(int k, float* __restrict__ Hout) {
    int n = blockIdx.x, b = blockIdx.y;
    int tid = threadIdx.x;

    __shared__ int   list[NSEQ];
    __shared__ float pn[NSEQ];
    __shared__ int   s_cnt;
    __shared__ float red[256];

    float acc = 0.0f;

    for (int t = 0; t < NT; t++) {
        int z = t * 3 + k;
        if (tid == 0) s_cnt = 0;
        __syncthreads();
        if (tid < NWRD) {
            unsigned w = g_mask[k][(((size_t)b * NT + t) * NSEQ + n) * NWRD + tid];
            while (w) {
                int j = (tid << 5) + (__ffs(w) - 1);
                w &= w - 1;
                int p = atomicAdd(&s_cnt, 1);
                list[p] = j;
            }
        }
        __syncthreads();
        int cnt = s_cnt;

        const float* f2p = &g_f2[(size_t)z * BATCH * NSEQ + (size_t)b * NSEQ];
        float f1v = g_f1[(size_t)z * BATCH * NSEQ + (size_t)b * NSEQ + n];
        const float* hp = &g_h[((size_t)z * BATCH + b) * NSEQ * FD];

        if (cnt == 0) {
            float a = 0.0f;
            for (int j = 0; j < NSEQ; j++) a += hp[(size_t)j * FD + tid];
            acc += a * (1.0f / NSEQ);
            __syncthreads();
            continue;
        }

        float lmax = -1e30f;
        for (int i = tid; i < cnt; i += 256) {
            float x = f1v + f2p[list[i]];
            x = (x > 0.0f) ? x : ALPHAV * x;
            pn[i] = x;
            lmax = fmaxf(lmax, x);
        }
        red[tid] = lmax;
        __syncthreads();
        for (int s = 128; s > 0; s >>= 1) {
            if (tid < s) red[tid] = fmaxf(red[tid], red[tid + s]);
            __syncthreads();
        }
        float m = red[0];
        __syncthreads();

        float lsum = 0.0f;
        for (int i = tid; i < cnt; i += 256) {
            float p = __expf(pn[i] - m);
            pn[i] = p;
            lsum += p;
        }
        red[tid] = lsum;
        __syncthreads();
        for (int s = 128; s > 0; s >>= 1) {
            if (tid < s) red[tid] += red[tid + s];
            __syncthreads();
        }
        float inv = 1.0f / red[0];
        __syncthreads();

        int i = 0;
        for (; i + 4 <= cnt; i += 4) {
            int j0 = list[i], j1 = list[i + 1], j2 = list[i + 2], j3 = list[i + 3];
            float p0 = pn[i] * inv, p1 = pn[i + 1] * inv;
            float p2 = pn[i + 2] * inv, p3 = pn[i + 3] * inv;
            float h0 = hp[(size_t)j0 * FD + tid];
            float h1 = hp[(size_t)j1 * FD + tid];
            float h2 = hp[(size_t)j2 * FD + tid];
            float h3 = hp[(size_t)j3 * FD + tid];
            acc = fmaf(p0, h0, acc);
            acc = fmaf(p1, h1, acc);
            acc = fmaf(p2, h2, acc);
            acc = fmaf(p3, h3, acc);
        }
        for (; i < cnt; i++)
            acc = fmaf(pn[i] * inv, hp[(size_t)list[i] * FD + tid], acc);
        __syncthreads();
    }

    Hout[(((size_t)b * NSEQ + n) * NLAY + k) * FD + tid] = acc;
}

// ---------------- masked softmax (16 rows/block) -> coalesced A-fragments ---
__global__ __launch_bounds__(256) void att_kernel(void) {
    int mt = blockIdx.x, b = blockIdx.y, zz = blockIdx.z;
    int t = zz % 3, kk = zz / 3, k = kk + 1;
    int tid = threadIdx.x;
    int row = tid >> 4, c = tid & 15;
    int z = t * 3 + k;

    __shared__ float sf2[NSEQ];
    __shared__ unsigned smask[16][NWRD];
    __shared__ unsigned stage[16 * 512];

    const float* f2p = &g_f2[(size_t)z * BATCH * NSEQ + (size_t)b * NSEQ];
    for (int j = tid; j < NSEQ; j += 256) sf2[j] = f2p[j];
    {
        const unsigned* mb = &g_mask[k][(((size_t)b * NT + t) * NSEQ + mt * 16) * NWRD];
        for (int i = tid; i < 16 * NWRD; i += 256)
            smask[i >> 5][i & 31] = mb[i];
    }
    __syncthreads();

    float f1v = g_f1[(size_t)z * BATCH * NSEQ + (size_t)b * NSEQ + mt * 16 + row];
    const unsigned* mrow = smask[row];

    float pv[64];
    float lmax = NEGV;
    #pragma unroll
    for (int s = 0; s < 32; s++) {
        unsigned m2 = (mrow[s] >> (2 * c)) & 3u;
        float x0 = f1v + sf2[32 * s + 2 * c];
        x0 = (x0 > 0.0f) ? x0 : ALPHAV * x0;
        float x1 = f1v + sf2[32 * s + 2 * c + 1];
        x1 = (x1 > 0.0f) ? x1 : ALPHAV * x1;
        float e0 = (m2 & 1u) ? x0 : NEGV;
        float e1 = (m2 & 2u) ? x1 : NEGV;
        pv[2 * s] = e0;
        pv[2 * s + 1] = e1;
        lmax = fmaxf(lmax, fmaxf(e0, e1));
    }
    #pragma unroll
    for (int off = 8; off > 0; off >>= 1)
        lmax = fmaxf(lmax, __shfl_xor_sync(0xffffffffu, lmax, off));
    float m = lmax;

    bool empty = (m < -8.9e15f);
    float lsum = 0.0f;
    #pragma unroll
    for (int q = 0; q < 64; q++) {
        float p = empty ? 1.0f : __expf(pv[q] - m);
        pv[q] = p;
        lsum += p;
    }
    #pragma unroll
    for (int off = 8; off > 0; off >>= 1)
        lsum += __shfl_xor_sync(0xffffffffu, lsum, off);
    float inv = 1.0f / lsum;

    unsigned* srow = &stage[row * 512];
    #pragma unroll
    for (int s = 0; s < 32; s++)
        srow[c + 16 * s] = packh2(pv[2 * s] * inv, pv[2 * s + 1] * inv);
    __syncthreads();

    uint4* obase = g_attf + (((size_t)kk * NT + t) * BATCH + b) * ((size_t)64 * 64 * 32)
                   + (size_t)mt * 64 * 32;
    #pragma unroll
    for (int w = 0; w < 8; w++) {
        int widx = tid + 256 * w;
        int ktw = widx >> 5;
        int lw = widx & 31;
        int r0 = lw >> 2;
        int p0 = ktw * 8 + (lw & 3);
        uint4 u;
        u.x = stage[r0 * 512 + p0];
        u.y = stage[(r0 + 8) * 512 + p0];
        u.z = stage[r0 * 512 + p0 + 4];
        u.w = stage[(r0 + 8) * 512 + p0 + 4];
        obase[widx] = u;
    }
}

// ---------------- final combine ---------------------------------------------
__global__ void combine_kernel(const float* __restrict__ Ww, const float* __restrict__ bw,
                               const float* __restrict__ Wc, float* __restrict__ out) {
    int bn = blockIdx.x;
    int tid = threadIdx.x;
    __shared__ float sh[NLAY * FD];
    __shared__ float part[NLAY][128];
    __shared__ float sy[NLAY];

    const float* Hp = &g_H[(size_t)bn * NLAY * FD];
    for (int i = tid; i < NLAY * FD; i += 128) sh[i] = Hp[i];
    __syncthreads();

    float loc[NLAY] = {0.0f, 0.0f, 0.0f};
    if (tid < 100) {
        float wc = Wc[tid];
        float bwv = bw[tid];
        #pragma unroll
        for (int k = 0; k < NLAY; k++) {
            float y = bwv;
            #pragma unroll 8
            for (int i = 0; i < FD; i++)
                y = fmaf(sh[k * FD + i], Ww[i * 100 + tid], y);
            loc[k] = tanhf(y) * wc;
        }
    }
    #pragma unroll
    for (int k = 0; k < NLAY; k++) part[k][tid] = loc[k];
    __syncthreads();
    for (int s = 64; s > 0; s >>= 1) {
        if (tid < s) {
            part[0][tid] += part[0][tid + s];
            part[1][tid] += part[1][tid + s];
            part[2][tid] += part[2][tid + s];
        }
        __syncthreads();
    }
    if (tid == 0) {
        float s0 = part[0][0], s1 = part[1][0], s2 = part[2][0];
        float mx = fmaxf(s0, fmaxf(s1, s2));
        float e0 = __expf(s0 - mx), e1 = __expf(s1 - mx), e2 = __expf(s2 - mx);
        float invs = 1.0f / (e0 + e1 + e2);
        sy[0] = e0 * invs; sy[1] = e1 * invs; sy[2] = e2 * invs;
    }
    __syncthreads();

    float w0 = sy[0], w1 = sy[1], w2 = sy[2];
    for (int f = tid; f < FD; f += 128)
        out[(size_t)bn * FD + f] =
            w0 * sh[f] + w1 * sh[FD + f] + w2 * sh[2 * FD + f];
}

// ---------------- launch ----------------------------------------------------
extern "C" void kernel_launch(void* const* d_in, const int* in_sizes, int n_in,
                              void* d_out, int out_size) {
    const float* adj = (const float*)d_in[0];
    const float* X   = (const float*)d_in[1];
    const float* W   = (const float*)d_in[2];
    const float* a1  = (const float*)d_in[3];
    const float* a2  = (const float*)d_in[4];
    const float* Ww  = (const float*)d_in[5];
    const float* bw  = (const float*)d_in[6];
    const float* Wc  = (const float*)d_in[7];
    float* out = (float*)d_out;

    void *ph, *pH, *pxf, *pwf, *paf, *phf;
    cudaGetSymbolAddress(&ph, g_h);
    cudaGetSymbolAddress(&pH, g_H);
    cudaGetSymbolAddress(&pxf, g_xf);
    cudaGetSymbolAddress(&pwf, g_wf);
    cudaGetSymbolAddress(&paf, g_attf);
    cudaGetSymbolAddress(&phf, g_htf);
    float* hbuf = (float*)ph;
    float* Hbuf = (float*)pH;

    // 1. adjacency bitsets + boolean powers (adj^3 via adj * adj^2)
    bits_kernel<<<BATCH * NT * NSEQ, 1024>>>(adj);
    zero_f_kernel<<<(9 * BATCH * NSEQ + 1023) / 1024, 1024>>>();
    bmm_kernel<<<BATCH * NT * NSEQ, 32>>>(0, 0, 1);
    bmm_kernel<<<BATCH * NT * NSEQ, 32>>>(0, 1, 2);

    // 2. fragment-major fp16 operand prep: X, W
    xf_kernel<<<(BATCH * NSEQ / 16 * (IND / 16) * 32) / 256, 256>>>(X);
    wf_kernel<<<(9 * (FD / 8) * (IND / 16) * 32) / 256, 256>>>(W);

    // 3. h[t,k] = X @ W[t,k] (fused f1/f2 epilogue)
    {
        dim3 grid(FD / BN, (BATCH * NSEQ) / BM, 9);
        tgemm16f<<<grid, 256>>>((const uint4*)pxf, (const uint2*)pwf, hbuf,
                                IND / 16, FD, 9,
                                0LL, (long long)(FD / 8) * (IND / 16) * 32,
                                (long long)BATCH * NSEQ * FD,
                                0LL, 0LL, 0LL,
                                0LL, 0LL, 1,
                                1, a1, a2);
    }

    // 4. h B-fragments for k=1,2 relations
    htf_kernel<<<(6 * BATCH * 32 * 64 * 32) / 256, 256>>>();

    // 5. sparse layer k=0
    spmm_kernel<<<dim3(NSEQ, BATCH), 256>>>(0, Hbuf);

    // 6. all dense masked-softmax rows (k=1,2 x t=0..2), coalesced A-fragments
    att_kernel<<<dim3(NSEQ / 16, BATCH, 6), 256>>>();

    // 7. dense layers k=1,2 in ONE launch: grid.z = (kk, b), segmented over t
    {
        dim3 grid(FD / BN, NSEQ / BM, 2 * BATCH);
        tgemm16f<<<grid, 256>>>(
            (const uint4*)paf, (const uint2*)phf,
            Hbuf + 1 * FD,
            NSEQ / 16, NLAY * FD, BATCH,
            (long long)64 * 64 * 32,
            (long long)32 * 64 * 32,
            (long long)NSEQ * NLAY * FD,
            (long long)NT * BATCH * 64 * 64 * 32,
            (long long)NT * BATCH * 32 * 64 * 32,
            (long long)FD,
            (long long)BATCH * 64 * 64 * 32,
            (long long)BATCH * 32 * 64 * 32,
            NT,
            0, (const float*)0, (const float*)0);
    }

    // 8. combine
    combine_kernel<<<BATCH * NSEQ, 128>>>(Ww, bw, Wc, out);
}

// round 15
// speedup vs baseline: 2.4303x; 1.0522x over previous
#include <cuda_runtime.h>
#include <cuda_fp16.h>
#include <cstdint>

#define BATCH 16
#define NT 3
#define NSEQ 1024
#define IND 512
#define FD 256
#define NLAY 3
#define NWRD 32
#define ALPHAV 0.2f
#define NEGV -9e15f

// ---------------- scratch (device globals; no allocations allowed) ----------
__device__ unsigned g_mask[NLAY][BATCH * NT * NSEQ * NWRD];
__device__ float g_h[(size_t)9 * BATCH * NSEQ * FD];
__device__ float g_f1[9 * BATCH * NSEQ];
__device__ float g_f2[9 * BATCH * NSEQ];
// fragment-major operand buffers
__device__ uint4 g_xf[(size_t)(BATCH * NSEQ / 16) * (IND / 16) * 32];       // 16MB
__device__ uint2 g_wf[9 * (FD / 8) * (IND / 16) * 32];                      // 2.4MB
__device__ uint4 g_attf[(size_t)2 * NT * BATCH * 64 * 64 * 32];             // 201MB
__device__ uint2 g_htf[(size_t)6 * BATCH * 32 * 64 * 32];                   // 50MB
__device__ float g_H[(size_t)BATCH * NSEQ * NLAY * FD];

__device__ __forceinline__ unsigned packh2(float a, float b) {
    __half2 h = __floats2half2_rn(a, b);
    return *(unsigned*)&h;
}

// ---------------- adj -> bitset --------------------------------------------
__global__ void bits_kernel(const float* __restrict__ adj) {
    int r = blockIdx.x;
    int tid = threadIdx.x;
    float v = adj[(size_t)r * NSEQ + tid];
    unsigned bal = __ballot_sync(0xffffffffu, v > 0.0f);
    if ((tid & 31) == 0) g_mask[0][(size_t)r * NWRD + (tid >> 5)] = bal;
}

__global__ void zero_f_kernel() {
    int i = blockIdx.x * blockDim.x + threadIdx.x;
    if (i < 9 * BATCH * NSEQ) { g_f1[i] = 0.0f; g_f2[i] = 0.0f; }
}

// 8 rows per block (8 warps) — lifts the 32-blocks/SM occupancy cap
__global__ __launch_bounds__(256) void bmm_kernel(int lft, int rgt, int dst) {
    int r = blockIdx.x * 8 + (threadIdx.x >> 5);
    int bt = r / NSEQ;
    int lane = threadIdx.x & 31;
    const unsigned* lrow = &g_mask[lft][(size_t)r * NWRD];
    const unsigned* rbase = &g_mask[rgt][(size_t)bt * NSEQ * NWRD];
    unsigned myw = lrow[lane];
    unsigned acc = 0;
    #pragma unroll 1
    for (int w = 0; w < NWRD; ++w) {
        unsigned bitsw = __shfl_sync(0xffffffffu, myw, w);
        while (bitsw) {
            int j = (w << 5) + (__ffs(bitsw) - 1);
            bitsw &= bitsw - 1;
            acc |= rbase[(size_t)j * NWRD + lane];
        }
    }
    g_mask[dst][(size_t)r * NWRD + lane] = acc;
}

// ---------------- operand prep (fragment-major) ------------------------------
__global__ void xf_kernel(const float* __restrict__ X) {
    int idx = blockIdx.x * blockDim.x + threadIdx.x;
    int lane = idx & 31;
    int kt = (idx >> 5) & 31;
    int mt = idx >> 10;
    int m = mt * 16 + (lane >> 2);
    int k = kt * 16 + (lane & 3) * 2;
    const float* p0 = X + (size_t)m * IND + k;
    const float* p8 = p0 + (size_t)8 * IND;
    uint4 t;
    t.x = packh2(p0[0], p0[1]);
    t.y = packh2(p8[0], p8[1]);
    t.z = packh2(p0[8], p0[9]);
    t.w = packh2(p8[8], p8[9]);
    g_xf[idx] = t;
}

__global__ void wf_kernel(const float* __restrict__ W) {
    int idx = blockIdx.x * blockDim.x + threadIdx.x;
    int lane = idx & 31;
    int kt = (idx >> 5) & 31;
    int nt = (idx >> 10) & 31;
    int z = idx >> 15;
    int n = nt * 8 + (lane >> 2);
    int k = kt * 16 + (lane & 3) * 2;
    const float* Wz = W + (size_t)z * IND * FD;
    uint2 t;
    t.x = packh2(Wz[(size_t)k * FD + n], Wz[(size_t)(k + 1) * FD + n]);
    t.y = packh2(Wz[(size_t)(k + 8) * FD + n], Wz[(size_t)(k + 9) * FD + n]);
    g_wf[idx] = t;
}

__global__ void htf_kernel() {
    int idx = blockIdx.x * blockDim.x + threadIdx.x;
    int lane = idx & 31;
    int kt = (idx >> 5) & 63;
    int nt = (idx >> 11) & 31;
    int b = (idx >> 16) & 15;
    int z6 = idx >> 20;                  // kk*3 + t
    int t = z6 % 3, kk = z6 / 3;
    int z = t * 3 + (kk + 1);
    int f = nt * 8 + (lane >> 2);
    int s = kt * 16 + (lane & 3) * 2;
    const float* src = g_h + ((size_t)z * BATCH + b) * NSEQ * FD;
    uint2 w;
    w.x = packh2(src[(size_t)s * FD + f], src[(size_t)(s + 1) * FD + f]);
    w.y = packh2(src[(size_t)(s + 8) * FD + f], src[(size_t)(s + 9) * FD + f]);
    g_htf[idx] = w;
}

// ---------------- cp.async helpers ------------------------------------------
__device__ __forceinline__ uint32_t smem_u32(const void* p) {
    return (uint32_t)__cvta_generic_to_shared(p);
}
#define CPA16(dst, src) \
    asm volatile("cp.async.cg.shared.global [%0], [%1], 16;" :: "r"(dst), "l"(src))
#define CPA8(dst, src) \
    asm volatile("cp.async.ca.shared.global [%0], [%1], 8;" :: "r"(dst), "l"(src))
#define CPCOMMIT() asm volatile("cp.async.commit_group;" ::: "memory")
#define CPWAIT1()  asm volatile("cp.async.wait_group 1;" ::: "memory")

// ---------------- fp16 fragment-direct GEMM (128x128, BK=32 stage, 3-stage) -
#define BM 128
#define BN 128
#define STG_A (8 * 2 * 32)
#define STG_B (16 * 2 * 32)

__global__ __launch_bounds__(256) void tgemm16f(
    const uint4* __restrict__ Af, const uint2* __restrict__ Bf, float* __restrict__ C,
    int kiter, int ldc, int nz1,
    long long sA, long long sB, long long sC,
    long long sA2, long long sB2, long long sC2,
    long long sAseg, long long sBseg, int nseg,
    int doF, const float* __restrict__ A1, const float* __restrict__ A2)
{
    __shared__ uint4 As[3][2][8][32];
    __shared__ uint2 Bs[3][2][16][32];
    __shared__ float sa1[128];
    __shared__ float sa2[128];

    int tid = threadIdx.x;
    int lane = tid & 31;
    int wid = tid >> 5;
    int wm = wid >> 2;
    int wn = wid & 3;
    int z = blockIdx.z;
    int z2 = z / nz1;
    int z1 = z - z2 * nz1;
    int mt0 = blockIdx.y * 8;
    int nt0 = blockIdx.x * 16;

    C += (size_t)z1 * sC + (size_t)z2 * sC2;

    const uint4* asrc = Af + (size_t)z1 * sA + (size_t)z2 * sA2
                        + ((size_t)(mt0 + wid) * kiter) * 32 + lane;
    const uint2* bsrc0 = Bf + (size_t)z1 * sB + (size_t)z2 * sB2
                         + ((size_t)(nt0 + 2 * wid) * kiter) * 32 + lane;
    const uint2* bsrc1 = bsrc0 + (size_t)kiter * 32;
    long long awrap = sAseg - (long long)kiter * 32;
    long long bwrap = sBseg - (long long)kiter * 32;
    int ktc = 0;

    uint32_t saA0 = smem_u32(&As[0][0][wid][lane]);
    uint32_t saA1 = smem_u32(&As[0][1][wid][lane]);
    uint32_t sbB00 = smem_u32(&Bs[0][0][2 * wid][lane]);
    uint32_t sbB01 = smem_u32(&Bs[0][1][2 * wid][lane]);
    uint32_t sbB10 = smem_u32(&Bs[0][0][2 * wid + 1][lane]);
    uint32_t sbB11 = smem_u32(&Bs[0][1][2 * wid + 1][lane]);

    #define ISSUE(st)                                                          \
        do {                                                                   \
            CPA16(saA0 + (st) * (STG_A * 16), asrc);                           \
            CPA16(saA1 + (st) * (STG_A * 16), asrc + 32);                      \
            CPA8(sbB00 + (st) * (STG_B * 8), bsrc0);                           \
            CPA8(sbB01 + (st) * (STG_B * 8), bsrc0 + 32);                      \
            CPA8(sbB10 + (st) * (STG_B * 8), bsrc1);                           \
            CPA8(sbB11 + (st) * (STG_B * 8), bsrc1 + 32);                      \
            CPCOMMIT();                                                        \
            asrc += 64; bsrc0 += 64; bsrc1 += 64;                              \
            ktc += 2;                                                          \
            if (ktc == kiter) {                                                \
                ktc = 0;                                                       \
                asrc += awrap; bsrc0 += bwrap; bsrc1 += bwrap;                 \
            }                                                                  \
        } while (0)

    float d[4][4][4];
    #pragma unroll
    for (int i = 0; i < 4; i++)
        #pragma unroll
        for (int j = 0; j < 4; j++)
            #pragma unroll
            for (int r = 0; r < 4; r++) d[i][j][r] = 0.0f;

    int total = (nseg * kiter) >> 1;
    ISSUE(0);
    if (total > 1) { ISSUE(1); } else { CPCOMMIT(); }

    for (int c = 0; c < total; c++) {
        CPWAIT1();
        __syncthreads();
        if (c + 2 < total) { ISSUE((c + 2) % 3); } else { CPCOMMIT(); }
        int cur = c % 3;
        #pragma unroll
        for (int kt = 0; kt < 2; kt++) {
            unsigned af[4][4];
            unsigned bf[4][2];
            #pragma unroll
            for (int mt = 0; mt < 4; mt++) {
                uint4 t = As[cur][kt][wm * 4 + mt][lane];
                af[mt][0] = t.x; af[mt][1] = t.y; af[mt][2] = t.z; af[mt][3] = t.w;
            }
            #pragma unroll
            for (int nt = 0; nt < 4; nt++) {
                uint2 t = Bs[cur][kt][wn * 4 + nt][lane];
                bf[nt][0] = t.x; bf[nt][1] = t.y;
            }
            #pragma unroll
            for (int mt = 0; mt < 4; mt++)
                #pragma unroll
                for (int nt = 0; nt < 4; nt++) {
                    asm volatile(
                        "mma.sync.aligned.m16n8k16.row.col.f32.f16.f16.f32 "
                        "{%0,%1,%2,%3}, {%4,%5,%6,%7}, {%8,%9}, {%0,%1,%2,%3};"
                        : "+f"(d[mt][nt][0]), "+f"(d[mt][nt][1]),
                          "+f"(d[mt][nt][2]), "+f"(d[mt][nt][3])
                        : "r"(af[mt][0]), "r"(af[mt][1]),
                          "r"(af[mt][2]), "r"(af[mt][3]),
                          "r"(bf[nt][0]), "r"(bf[nt][1]));
                }
        }
    }

    int cr = lane >> 2;
    int cc = (lane & 3) * 2;
    int bm = blockIdx.y * BM, bn = blockIdx.x * BN;
    #pragma unroll
    for (int mt = 0; mt < 4; mt++) {
        #pragma unroll
        for (int half = 0; half < 2; half++) {
            int row = bm + wm * 64 + mt * 16 + cr + half * 8;
            float* cp = C + (size_t)row * ldc + bn + wn * 32 + cc;
            #pragma unroll
            for (int nt = 0; nt < 4; nt++) {
                float2 v = make_float2(d[mt][nt][half * 2], d[mt][nt][half * 2 + 1]);
                *(float2*)(cp + nt * 8) = v;
            }
        }
    }

    if (doF) {
        if (tid < 128) {
            sa1[tid] = A1[(size_t)z1 * FD + bn + tid];
            sa2[tid] = A2[(size_t)z1 * FD + bn + tid];
        }
        __syncthreads();
        float* f1g = g_f1 + (size_t)z1 * BATCH * NSEQ;
        float* f2g = g_f2 + (size_t)z1 * BATCH * NSEQ;
        #pragma unroll
        for (int mt = 0; mt < 4; mt++) {
            #pragma unroll
            for (int half = 0; half < 2; half++) {
                int row = bm + wm * 64 + mt * 16 + cr + half * 8;
                float s1 = 0.0f, s2 = 0.0f;
                #pragma unroll
                for (int nt = 0; nt < 4; nt++) {
                    #pragma unroll
                    for (int e = 0; e < 2; e++) {
                        int col = wn * 32 + cc + nt * 8 + e;
                        float v = d[mt][nt][half * 2 + e];
                        s1 = fmaf(v, sa1[col], s1);
                        s2 = fmaf(v, sa2[col], s2);
                    }
                }
                s1 += __shfl_xor_sync(0xffffffffu, s1, 1);
                s1 += __shfl_xor_sync(0xffffffffu, s1, 2);
                s2 += __shfl_xor_sync(0xffffffffu, s2, 1);
                s2 += __shfl_xor_sync(0xffffffffu, s2, 2);
                if ((lane & 3) == 0) {
                    atomicAdd(&f1g[row], s1);
                    atomicAdd(&f2g[row], s2);
                }
            }
        }
    }
}

// ---------------- fused sparse softmax + SpMM (layer k=0 only) --------------
__global__ __launch_bounds__(256) void spmm_kernel(int k, float* __restrict__ Hout) {
    int n = blockIdx.x, b = blockIdx.y;
    int tid = threadIdx.x;
    int lane = tid & 31, wid = tid >> 5;

    __shared__ int   list[NSEQ];
    __shared__ float pn[NSEQ];
    __shared__ int   s_cnt;
    __shared__ float red8[8];

    float acc = 0.0f;

    for (int t = 0; t < NT; t++) {
        int z = t * 3 + k;
        if (tid == 0) s_cnt = 0;
        __syncthreads();
        if (tid < NWRD) {
            unsigned w = g_mask[k][(((size_t)b * NT + t) * NSEQ + n) * NWRD + tid];
            while (w) {
                int j = (tid << 5) + (__ffs(w) - 1);
                w &= w - 1;
                int p = atomicAdd(&s_cnt, 1);
                list[p] = j;
            }
        }
        __syncthreads();
        int cnt = s_cnt;

        const float* f2p = &g_f2[(size_t)z * BATCH * NSEQ + (size_t)b * NSEQ];
        float f1v = g_f1[(size_t)z * BATCH * NSEQ + (size_t)b * NSEQ + n];
        const float* hp = &g_h[((size_t)z * BATCH + b) * NSEQ * FD];

        if (cnt == 0) {
            float a = 0.0f;
            for (int j = 0; j < NSEQ; j++) a += hp[(size_t)j * FD + tid];
            acc += a * (1.0f / NSEQ);
            __syncthreads();
            continue;
        }

        // shfl-based max reduction (1 barrier)
        float lmax = -1e30f;
        for (int i = tid; i < cnt; i += 256) {
            float x = f1v + f2p[list[i]];
            x = (x > 0.0f) ? x : ALPHAV * x;
            pn[i] = x;
            lmax = fmaxf(lmax, x);
        }
        #pragma unroll
        for (int off = 16; off > 0; off >>= 1)
            lmax = fmaxf(lmax, __shfl_xor_sync(0xffffffffu, lmax, off));
        if (lane == 0) red8[wid] = lmax;
        __syncthreads();
        float m = red8[0];
        #pragma unroll
        for (int w = 1; w < 8; w++) m = fmaxf(m, red8[w]);
        __syncthreads();

        // shfl-based sum reduction (1 barrier)
        float lsum = 0.0f;
        for (int i = tid; i < cnt; i += 256) {
            float p = __expf(pn[i] - m);
            pn[i] = p;
            lsum += p;
        }
        #pragma unroll
        for (int off = 16; off > 0; off >>= 1)
            lsum += __shfl_xor_sync(0xffffffffu, lsum, off);
        if (lane == 0) red8[wid] = lsum;
        __syncthreads();
        float ssum = 0.0f;
        #pragma unroll
        for (int w = 0; w < 8; w++) ssum += red8[w];
        float inv = 1.0f / ssum;

        int i = 0;
        for (; i + 4 <= cnt; i += 4) {
            int j0 = list[i], j1 = list[i + 1], j2 = list[i + 2], j3 = list[i + 3];
            float p0 = pn[i] * inv, p1 = pn[i + 1] * inv;
            float p2 = pn[i + 2] * inv, p3 = pn[i + 3] * inv;
            float h0 = hp[(size_t)j0 * FD + tid];
            float h1 = hp[(size_t)j1 * FD + tid];
            float h2 = hp[(size_t)j2 * FD + tid];
            float h3 = hp[(size_t)j3 * FD + tid];
            acc = fmaf(p0, h0, acc);
            acc = fmaf(p1, h1, acc);
            acc = fmaf(p2, h2, acc);
            acc = fmaf(p3, h3, acc);
        }
        for (; i < cnt; i++)
            acc = fmaf(pn[i] * inv, hp[(size_t)list[i] * FD + tid], acc);
        __syncthreads();
    }

    Hout[(((size_t)b * NSEQ + n) * NLAY + k) * FD + tid] = acc;
}

// ---------------- masked softmax (16 rows/block) -> coalesced A-fragments ---
__global__ __launch_bounds__(256) void att_kernel(void) {
    int mt = blockIdx.x, b = blockIdx.y, zz = blockIdx.z;
    int t = zz % 3, kk = zz / 3, k = kk + 1;
    int tid = threadIdx.x;
    int row = tid >> 4, c = tid & 15;
    int z = t * 3 + k;

    __shared__ float sf2[NSEQ];
    __shared__ unsigned smask[16][NWRD];
    __shared__ unsigned stage[16 * 512];

    const float* f2p = &g_f2[(size_t)z * BATCH * NSEQ + (size_t)b * NSEQ];
    for (int j = tid; j < NSEQ; j += 256) sf2[j] = f2p[j];
    {
        const unsigned* mb = &g_mask[k][(((size_t)b * NT + t) * NSEQ + mt * 16) * NWRD];
        for (int i = tid; i < 16 * NWRD; i += 256)
            smask[i >> 5][i & 31] = mb[i];
    }
    __syncthreads();

    float f1v = g_f1[(size_t)z * BATCH * NSEQ + (size_t)b * NSEQ + mt * 16 + row];
    const unsigned* mrow = smask[row];

    float pv[64];
    float lmax = NEGV;
    #pragma unroll
    for (int s = 0; s < 32; s++) {
        unsigned m2 = (mrow[s] >> (2 * c)) & 3u;
        float x0 = f1v + sf2[32 * s + 2 * c];
        x0 = (x0 > 0.0f) ? x0 : ALPHAV * x0;
        float x1 = f1v + sf2[32 * s + 2 * c + 1];
        x1 = (x1 > 0.0f) ? x1 : ALPHAV * x1;
        float e0 = (m2 & 1u) ? x0 : NEGV;
        float e1 = (m2 & 2u) ? x1 : NEGV;
        pv[2 * s] = e0;
        pv[2 * s + 1] = e1;
        lmax = fmaxf(lmax, fmaxf(e0, e1));
    }
    #pragma unroll
    for (int off = 8; off > 0; off >>= 1)
        lmax = fmaxf(lmax, __shfl_xor_sync(0xffffffffu, lmax, off));
    float m = lmax;

    bool empty = (m < -8.9e15f);
    float lsum = 0.0f;
    #pragma unroll
    for (int q = 0; q < 64; q++) {
        float p = empty ? 1.0f : __expf(pv[q] - m);
        pv[q] = p;
        lsum += p;
    }
    #pragma unroll
    for (int off = 8; off > 0; off >>= 1)
        lsum += __shfl_xor_sync(0xffffffffu, lsum, off);
    float inv = 1.0f / lsum;

    unsigned* srow = &stage[row * 512];
    #pragma unroll
    for (int s = 0; s < 32; s++)
        srow[c + 16 * s] = packh2(pv[2 * s] * inv, pv[2 * s + 1] * inv);
    __syncthreads();

    uint4* obase = g_attf + (((size_t)kk * NT + t) * BATCH + b) * ((size_t)64 * 64 * 32)
                   + (size_t)mt * 64 * 32;
    #pragma unroll
    for (int w = 0; w < 8; w++) {
        int widx = tid + 256 * w;
        int ktw = widx >> 5;
        int lw = widx & 31;
        int r0 = lw >> 2;
        int p0 = ktw * 8 + (lw & 3);
        uint4 u;
        u.x = stage[r0 * 512 + p0];
        u.y = stage[(r0 + 8) * 512 + p0];
        u.z = stage[r0 * 512 + p0 + 4];
        u.w = stage[(r0 + 8) * 512 + p0 + 4];
        obase[widx] = u;
    }
}

// ---------------- final combine ---------------------------------------------
__global__ void combine_kernel(const float* __restrict__ Ww, const float* __restrict__ bw,
                               const float* __restrict__ Wc, float* __restrict__ out) {
    int bn = blockIdx.x;
    int tid = threadIdx.x;
    __shared__ float sh[NLAY * FD];
    __shared__ float part[NLAY][128];
    __shared__ float sy[NLAY];

    const float* Hp = &g_H[(size_t)bn * NLAY * FD];
    for (int i = tid; i < NLAY * FD; i += 128) sh[i] = Hp[i];
    __syncthreads();

    float loc[NLAY] = {0.0f, 0.0f, 0.0f};
    if (tid < 100) {
        float wc = Wc[tid];
        float bwv = bw[tid];
        #pragma unroll
        for (int k = 0; k < NLAY; k++) {
            float y = bwv;
            #pragma unroll 8
            for (int i = 0; i < FD; i++)
                y = fmaf(sh[k * FD + i], Ww[i * 100 + tid], y);
            loc[k] = tanhf(y) * wc;
        }
    }
    #pragma unroll
    for (int k = 0; k < NLAY; k++) part[k][tid] = loc[k];
    __syncthreads();
    for (int s = 64; s > 0; s >>= 1) {
        if (tid < s) {
            part[0][tid] += part[0][tid + s];
            part[1][tid] += part[1][tid + s];
            part[2][tid] += part[2][tid + s];
        }
        __syncthreads();
    }
    if (tid == 0) {
        float s0 = part[0][0], s1 = part[1][0], s2 = part[2][0];
        float mx = fmaxf(s0, fmaxf(s1, s2));
        float e0 = __expf(s0 - mx), e1 = __expf(s1 - mx), e2 = __expf(s2 - mx);
        float invs = 1.0f / (e0 + e1 + e2);
        sy[0] = e0 * invs; sy[1] = e1 * invs; sy[2] = e2 * invs;
    }
    __syncthreads();

    float w0 = sy[0], w1 = sy[1], w2 = sy[2];
    for (int f = tid; f < FD; f += 128)
        out[(size_t)bn * FD + f] =
            w0 * sh[f] + w1 * sh[FD + f] + w2 * sh[2 * FD + f];
}

// ---------------- launch ----------------------------------------------------
extern "C" void kernel_launch(void* const* d_in, const int* in_sizes, int n_in,
                              void* d_out, int out_size) {
    const float* adj = (const float*)d_in[0];
    const float* X   = (const float*)d_in[1];
    const float* W   = (const float*)d_in[2];
    const float* a1  = (const float*)d_in[3];
    const float* a2  = (const float*)d_in[4];
    const float* Ww  = (const float*)d_in[5];
    const float* bw  = (const float*)d_in[6];
    const float* Wc  = (const float*)d_in[7];
    float* out = (float*)d_out;

    void *ph, *pH, *pxf, *pwf, *paf, *phf;
    cudaGetSymbolAddress(&ph, g_h);
    cudaGetSymbolAddress(&pH, g_H);
    cudaGetSymbolAddress(&pxf, g_xf);
    cudaGetSymbolAddress(&pwf, g_wf);
    cudaGetSymbolAddress(&paf, g_attf);
    cudaGetSymbolAddress(&phf, g_htf);
    float* hbuf = (float*)ph;
    float* Hbuf = (float*)pH;

    // 1. adjacency bitsets + boolean powers (adj^3 via adj * adj^2)
    bits_kernel<<<BATCH * NT * NSEQ, 1024>>>(adj);
    zero_f_kernel<<<(9 * BATCH * NSEQ + 1023) / 1024, 1024>>>();
    bmm_kernel<<<BATCH * NT * NSEQ / 8, 256>>>(0, 0, 1);
    bmm_kernel<<<BATCH * NT * NSEQ / 8, 256>>>(0, 1, 2);

    // 2. fragment-major fp16 operand prep: X, W
    xf_kernel<<<(BATCH * NSEQ / 16 * (IND / 16) * 32) / 256, 256>>>(X);
    wf_kernel<<<(9 * (FD / 8) * (IND / 16) * 32) / 256, 256>>>(W);

    // 3. h[t,k] = X @ W[t,k] (fused f1/f2 epilogue)
    {
        dim3 grid(FD / BN, (BATCH * NSEQ) / BM, 9);
        tgemm16f<<<grid, 256>>>((const uint4*)pxf, (const uint2*)pwf, hbuf,
                                IND / 16, FD, 9,
                                0LL, (long long)(FD / 8) * (IND / 16) * 32,
                                (long long)BATCH * NSEQ * FD,
                                0LL, 0LL, 0LL,
                                0LL, 0LL, 1,
                                1, a1, a2);
    }

    // 4. h B-fragments for k=1,2 relations
    htf_kernel<<<(6 * BATCH * 32 * 64 * 32) / 256, 256>>>();

    // 5. sparse layer k=0
    spmm_kernel<<<dim3(NSEQ, BATCH), 256>>>(0, Hbuf);

    // 6. all dense masked-softmax rows (k=1,2 x t=0..2), coalesced A-fragments
    att_kernel<<<dim3(NSEQ / 16, BATCH, 6), 256>>>();

    // 7. dense layers k=1,2 in ONE launch: grid.z = (kk, b), segmented over t
    {
        dim3 grid(FD / BN, NSEQ / BM, 2 * BATCH);
        tgemm16f<<<grid, 256>>>(
            (const uint4*)paf, (const uint2*)phf,
            Hbuf + 1 * FD,
            NSEQ / 16, NLAY * FD, BATCH,
            (long long)64 * 64 * 32,
            (long long)32 * 64 * 32,
            (long long)NSEQ * NLAY * FD,
            (long long)NT * BATCH * 64 * 64 * 32,
            (long long)NT * BATCH * 32 * 64 * 32,
            (long long)FD,
            (long long)BATCH * 64 * 64 * 32,
            (long long)BATCH * 32 * 64 * 32,
            NT,
            0, (const float*)0, (const float*)0);
    }

    // 8. combine
    combine_kernel<<<BATCH * NSEQ, 128>>>(Ww, bw, Wc, out);
}

// round 16
// speedup vs baseline: 2.4705x; 1.0165x over previous
#include <cuda_runtime.h>
#include <cuda_fp16.h>
#include <cstdint>

#define BATCH 16
#define NT 3
#define NSEQ 1024
#define IND 512
#define FD 256
#define NLAY 3
#define NWRD 32
#define ALPHAV 0.2f
#define NEGV -9e15f

// ---------------- scratch (device globals; no allocations allowed) ----------
__device__ unsigned g_mask[NLAY][BATCH * NT * NSEQ * NWRD];
__device__ __half g_h16[(size_t)NT * BATCH * NSEQ * FD];        // k=0 h, fp16 (25MB)
__device__ float g_f1[9 * BATCH * NSEQ];
__device__ float g_f2[9 * BATCH * NSEQ];
// fragment-major operand buffers
__device__ uint4 g_xf[(size_t)(BATCH * NSEQ / 16) * (IND / 16) * 32];       // 16MB
__device__ uint2 g_wf[9 * (FD / 8) * (IND / 16) * 32];                      // 2.4MB
__device__ uint4 g_attf[(size_t)2 * NT * BATCH * 64 * 64 * 32];             // 201MB
__device__ uint2 g_htf[(size_t)6 * BATCH * 32 * 64 * 32];                   // 50MB
__device__ float g_H[(size_t)BATCH * NSEQ * NLAY * FD];

__device__ __forceinline__ unsigned packh2(float a, float b) {
    __half2 h = __floats2half2_rn(a, b);
    return *(unsigned*)&h;
}

// ---------------- adj -> bitset --------------------------------------------
__global__ void bits_kernel(const float* __restrict__ adj) {
    int r = blockIdx.x;
    int tid = threadIdx.x;
    float v = adj[(size_t)r * NSEQ + tid];
    unsigned bal = __ballot_sync(0xffffffffu, v > 0.0f);
    if ((tid & 31) == 0) g_mask[0][(size_t)r * NWRD + (tid >> 5)] = bal;
}

__global__ void zero_f_kernel() {
    int i = blockIdx.x * blockDim.x + threadIdx.x;
    if (i < 9 * BATCH * NSEQ) { g_f1[i] = 0.0f; g_f2[i] = 0.0f; }
}

__global__ __launch_bounds__(256) void bmm_kernel(int lft, int rgt, int dst) {
    int r = blockIdx.x * 8 + (threadIdx.x >> 5);
    int bt = r / NSEQ;
    int lane = threadIdx.x & 31;
    const unsigned* lrow = &g_mask[lft][(size_t)r * NWRD];
    const unsigned* rbase = &g_mask[rgt][(size_t)bt * NSEQ * NWRD];
    unsigned myw = lrow[lane];
    unsigned acc = 0;
    #pragma unroll 1
    for (int w = 0; w < NWRD; ++w) {
        unsigned bitsw = __shfl_sync(0xffffffffu, myw, w);
        while (bitsw) {
            int j = (w << 5) + (__ffs(bitsw) - 1);
            bitsw &= bitsw - 1;
            acc |= rbase[(size_t)j * NWRD + lane];
        }
    }
    g_mask[dst][(size_t)r * NWRD + lane] = acc;
}

// ---------------- operand prep (fragment-major) ------------------------------
__global__ void xf_kernel(const float* __restrict__ X) {
    int idx = blockIdx.x * blockDim.x + threadIdx.x;
    int lane = idx & 31;
    int kt = (idx >> 5) & 31;
    int mt = idx >> 10;
    int m = mt * 16 + (lane >> 2);
    int k = kt * 16 + (lane & 3) * 2;
    const float* p0 = X + (size_t)m * IND + k;
    const float* p8 = p0 + (size_t)8 * IND;
    uint4 t;
    t.x = packh2(p0[0], p0[1]);
    t.y = packh2(p8[0], p8[1]);
    t.z = packh2(p0[8], p0[9]);
    t.w = packh2(p8[8], p8[9]);
    g_xf[idx] = t;
}

__global__ void wf_kernel(const float* __restrict__ W) {
    int idx = blockIdx.x * blockDim.x + threadIdx.x;
    int lane = idx & 31;
    int kt = (idx >> 5) & 31;
    int nt = (idx >> 10) & 31;
    int z = idx >> 15;
    int n = nt * 8 + (lane >> 2);
    int k = kt * 16 + (lane & 3) * 2;
    const float* Wz = W + (size_t)z * IND * FD;
    uint2 t;
    t.x = packh2(Wz[(size_t)k * FD + n], Wz[(size_t)(k + 1) * FD + n]);
    t.y = packh2(Wz[(size_t)(k + 8) * FD + n], Wz[(size_t)(k + 9) * FD + n]);
    g_wf[idx] = t;
}

// ---------------- cp.async helpers ------------------------------------------
__device__ __forceinline__ uint32_t smem_u32(const void* p) {
    return (uint32_t)__cvta_generic_to_shared(p);
}
#define CPA16(dst, src) \
    asm volatile("cp.async.cg.shared.global [%0], [%1], 16;" :: "r"(dst), "l"(src))
#define CPA8(dst, src) \
    asm volatile("cp.async.ca.shared.global [%0], [%1], 8;" :: "r"(dst), "l"(src))
#define CPCOMMIT() asm volatile("cp.async.commit_group;" ::: "memory")
#define CPWAIT1()  asm volatile("cp.async.wait_group 1;" ::: "memory")

// ---------------- fp16 fragment-direct GEMM (128x128, BK=32 stage, 3-stage) -
// doF=1 (gemm1): z1 in 0..8; fused f1/f2; output mode by z1%3:
//   z1%3==0 -> h16 row-major into (half*)C;  else -> B-fragments into g_htf.
// doF=0 (gemm2): fp32 C row-major as before.
#define BM 128
#define BN 128
#define STG_A (8 * 2 * 32)
#define STG_B (16 * 2 * 32)
#define HST 136          // staging row stride (halfs), padded

__global__ __launch_bounds__(256) void tgemm16f(
    const uint4* __restrict__ Af, const uint2* __restrict__ Bf, float* __restrict__ C,
    int kiter, int ldc, int nz1,
    long long sA, long long sB, long long sC,
    long long sA2, long long sB2, long long sC2,
    long long sAseg, long long sBseg, int nseg,
    int doF, const float* __restrict__ A1, const float* __restrict__ A2)
{
    __shared__ __align__(16) char smemraw[49152];
    __shared__ float sa1[128];
    __shared__ float sa2[128];
    uint4 (*As)[2][8][32] = (uint4(*)[2][8][32])smemraw;
    uint2 (*Bs)[2][16][32] = (uint2(*)[2][16][32])(smemraw + 24576);
    __half* stage = (__half*)smemraw;    // epilogue reuse (34KB < 48KB)

    int tid = threadIdx.x;
    int lane = tid & 31;
    int wid = tid >> 5;
    int wm = wid >> 2;
    int wn = wid & 3;
    int z = blockIdx.z;
    int z2 = z / nz1;
    int z1 = z - z2 * nz1;
    int mt0 = blockIdx.y * 8;
    int nt0 = blockIdx.x * 16;

    float* Cp = C + (size_t)z1 * sC + (size_t)z2 * sC2;

    const uint4* asrc = Af + (size_t)z1 * sA + (size_t)z2 * sA2
                        + ((size_t)(mt0 + wid) * kiter) * 32 + lane;
    const uint2* bsrc0 = Bf + (size_t)z1 * sB + (size_t)z2 * sB2
                         + ((size_t)(nt0 + 2 * wid) * kiter) * 32 + lane;
    const uint2* bsrc1 = bsrc0 + (size_t)kiter * 32;
    long long awrap = sAseg - (long long)kiter * 32;
    long long bwrap = sBseg - (long long)kiter * 32;
    int ktc = 0;

    uint32_t saA0 = smem_u32(&As[0][0][wid][lane]);
    uint32_t saA1 = smem_u32(&As[0][1][wid][lane]);
    uint32_t sbB00 = smem_u32(&Bs[0][0][2 * wid][lane]);
    uint32_t sbB01 = smem_u32(&Bs[0][1][2 * wid][lane]);
    uint32_t sbB10 = smem_u32(&Bs[0][0][2 * wid + 1][lane]);
    uint32_t sbB11 = smem_u32(&Bs[0][1][2 * wid + 1][lane]);

    #define ISSUE(st)                                                          \
        do {                                                                   \
            CPA16(saA0 + (st) * (STG_A * 16), asrc);                           \
            CPA16(saA1 + (st) * (STG_A * 16), asrc + 32);                      \
            CPA8(sbB00 + (st) * (STG_B * 8), bsrc0);                           \
            CPA8(sbB01 + (st) * (STG_B * 8), bsrc0 + 32);                      \
            CPA8(sbB10 + (st) * (STG_B * 8), bsrc1);                           \
            CPA8(sbB11 + (st) * (STG_B * 8), bsrc1 + 32);                      \
            CPCOMMIT();                                                        \
            asrc += 64; bsrc0 += 64; bsrc1 += 64;                              \
            ktc += 2;                                                          \
            if (ktc == kiter) {                                                \
                ktc = 0;                                                       \
                asrc += awrap; bsrc0 += bwrap; bsrc1 += bwrap;                 \
            }                                                                  \
        } while (0)

    float d[4][4][4];
    #pragma unroll
    for (int i = 0; i < 4; i++)
        #pragma unroll
        for (int j = 0; j < 4; j++)
            #pragma unroll
            for (int r = 0; r < 4; r++) d[i][j][r] = 0.0f;

    int total = (nseg * kiter) >> 1;
    ISSUE(0);
    if (total > 1) { ISSUE(1); } else { CPCOMMIT(); }

    for (int c = 0; c < total; c++) {
        CPWAIT1();
        __syncthreads();
        if (c + 2 < total) { ISSUE((c + 2) % 3); } else { CPCOMMIT(); }
        int cur = c % 3;
        #pragma unroll
        for (int kt = 0; kt < 2; kt++) {
            unsigned af[4][4];
            unsigned bf[4][2];
            #pragma unroll
            for (int mt = 0; mt < 4; mt++) {
                uint4 t = As[cur][kt][wm * 4 + mt][lane];
                af[mt][0] = t.x; af[mt][1] = t.y; af[mt][2] = t.z; af[mt][3] = t.w;
            }
            #pragma unroll
            for (int nt = 0; nt < 4; nt++) {
                uint2 t = Bs[cur][kt][wn * 4 + nt][lane];
                bf[nt][0] = t.x; bf[nt][1] = t.y;
            }
            #pragma unroll
            for (int mt = 0; mt < 4; mt++)
                #pragma unroll
                for (int nt = 0; nt < 4; nt++) {
                    asm volatile(
                        "mma.sync.aligned.m16n8k16.row.col.f32.f16.f16.f32 "
                        "{%0,%1,%2,%3}, {%4,%5,%6,%7}, {%8,%9}, {%0,%1,%2,%3};"
                        : "+f"(d[mt][nt][0]), "+f"(d[mt][nt][1]),
                          "+f"(d[mt][nt][2]), "+f"(d[mt][nt][3])
                        : "r"(af[mt][0]), "r"(af[mt][1]),
                          "r"(af[mt][2]), "r"(af[mt][3]),
                          "r"(bf[nt][0]), "r"(bf[nt][1]));
                }
        }
    }

    int cr = lane >> 2;
    int cc = (lane & 3) * 2;
    int bm = blockIdx.y * BM, bn = blockIdx.x * BN;

    if (!doF) {
        // gemm2: fp32 C row-major
        #pragma unroll
        for (int mt = 0; mt < 4; mt++) {
            #pragma unroll
            for (int half = 0; half < 2; half++) {
                int row = bm + wm * 64 + mt * 16 + cr + half * 8;
                float* cp = Cp + (size_t)row * ldc + bn + wn * 32 + cc;
                #pragma unroll
                for (int nt = 0; nt < 4; nt++) {
                    float2 v = make_float2(d[mt][nt][half * 2], d[mt][nt][half * 2 + 1]);
                    *(float2*)(cp + nt * 8) = v;
                }
            }
        }
        return;
    }

    // ---- gemm1 outputs ----
    int tt = z1 / 3, kk = z1 % 3;     // relation t, layer k
    if (kk == 0) {
        // h16 row-major for spmm: (t*BATCH*NSEQ + row)*FD + col
        __half* hb = (__half*)C + (size_t)tt * BATCH * NSEQ * FD;
        #pragma unroll
        for (int mt = 0; mt < 4; mt++) {
            #pragma unroll
            for (int half = 0; half < 2; half++) {
                int row = bm + wm * 64 + mt * 16 + cr + half * 8;
                __half* cp = hb + (size_t)row * FD + bn + wn * 32 + cc;
                #pragma unroll
                for (int nt = 0; nt < 4; nt++) {
                    unsigned v = packh2(d[mt][nt][half * 2], d[mt][nt][half * 2 + 1]);
                    *(unsigned*)(cp + nt * 8) = v;
                }
            }
        }
    } else {
        // B-fragment output into g_htf, staged through smem (layout [f][s], pad)
        __syncthreads();   // all warps done reading As/Bs
        #pragma unroll
        for (int mt = 0; mt < 4; mt++) {
            #pragma unroll
            for (int half = 0; half < 2; half++) {
                int s_local = wm * 64 + mt * 16 + cr + half * 8;
                #pragma unroll
                for (int nt = 0; nt < 4; nt++) {
                    int f_local = wn * 32 + cc + nt * 8;
                    stage[(f_local) * HST + s_local] =
                        __float2half(d[mt][nt][half * 2]);
                    stage[(f_local + 1) * HST + s_local] =
                        __float2half(d[mt][nt][half * 2 + 1]);
                }
            }
        }
        __syncthreads();
        int z6 = (kk - 1) * 3 + tt;
        int b = bm >> 10;
        int s_base = bm & (NSEQ - 1);
        uint2* obase = g_htf + ((size_t)z6 * BATCH + b) * ((size_t)32 * 64 * 32);
        int ntg0 = bn >> 3;
        int ktg0 = s_base >> 4;
        #pragma unroll
        for (int w = 0; w < 16; w++) {
            int widx = tid + 256 * w;
            int lw = widx & 31;
            int ktl = (widx >> 5) & 7;
            int ntl = widx >> 8;
            int n_local = ntl * 8 + (lw >> 2);
            int k_local = ktl * 16 + (lw & 3) * 2;
            uint2 u;
            u.x = *(unsigned*)&stage[n_local * HST + k_local];
            u.y = *(unsigned*)&stage[n_local * HST + k_local + 8];
            obase[((size_t)(ntg0 + ntl) * 64 + (ktg0 + ktl)) * 32 + lw] = u;
        }
    }

    // fused f1/f2 accumulation (all gemm1 z's)
    if (tid < 128) {
        sa1[tid] = A1[(size_t)z1 * FD + bn + tid];
        sa2[tid] = A2[(size_t)z1 * FD + bn + tid];
    }
    __syncthreads();
    float* f1g = g_f1 + (size_t)z1 * BATCH * NSEQ;
    float* f2g = g_f2 + (size_t)z1 * BATCH * NSEQ;
    #pragma unroll
    for (int mt = 0; mt < 4; mt++) {
        #pragma unroll
        for (int half = 0; half < 2; half++) {
            int row = bm + wm * 64 + mt * 16 + cr + half * 8;
            float s1 = 0.0f, s2 = 0.0f;
            #pragma unroll
            for (int nt = 0; nt < 4; nt++) {
                #pragma unroll
                for (int e = 0; e < 2; e++) {
                    int col = wn * 32 + cc + nt * 8 + e;
                    float v = d[mt][nt][half * 2 + e];
                    s1 = fmaf(v, sa1[col], s1);
                    s2 = fmaf(v, sa2[col], s2);
                }
            }
            s1 += __shfl_xor_sync(0xffffffffu, s1, 1);
            s1 += __shfl_xor_sync(0xffffffffu, s1, 2);
            s2 += __shfl_xor_sync(0xffffffffu, s2, 1);
            s2 += __shfl_xor_sync(0xffffffffu, s2, 2);
            if ((lane & 3) == 0) {
                atomicAdd(&f1g[row], s1);
                atomicAdd(&f2g[row], s2);
            }
        }
    }
}

// ---------------- fused sparse softmax + SpMM (layer k=0, fp16 h) -----------
__global__ __launch_bounds__(256) void spmm_kernel(int k, float* __restrict__ Hout) {
    int n = blockIdx.x, b = blockIdx.y;
    int tid = threadIdx.x;
    int lane = tid & 31, wid = tid >> 5;

    __shared__ int   list[NSEQ];
    __shared__ float pn[NSEQ];
    __shared__ int   s_cnt;
    __shared__ float red8[8];

    float acc = 0.0f;

    for (int t = 0; t < NT; t++) {
        int z = t * 3 + k;
        if (tid == 0) s_cnt = 0;
        __syncthreads();
        if (tid < NWRD) {
            unsigned w = g_mask[k][(((size_t)b * NT + t) * NSEQ + n) * NWRD + tid];
            while (w) {
                int j = (tid << 5) + (__ffs(w) - 1);
                w &= w - 1;
                int p = atomicAdd(&s_cnt, 1);
                list[p] = j;
            }
        }
        __syncthreads();
        int cnt = s_cnt;

        const float* f2p = &g_f2[(size_t)z * BATCH * NSEQ + (size_t)b * NSEQ];
        float f1v = g_f1[(size_t)z * BATCH * NSEQ + (size_t)b * NSEQ + n];
        const __half* hp = g_h16 + ((size_t)t * BATCH + b) * NSEQ * FD;

        if (cnt == 0) {
            float a = 0.0f;
            for (int j = 0; j < NSEQ; j++) a += __half2float(hp[(size_t)j * FD + tid]);
            acc += a * (1.0f / NSEQ);
            __syncthreads();
            continue;
        }

        float lmax = -1e30f;
        for (int i = tid; i < cnt; i += 256) {
            float x = f1v + f2p[list[i]];
            x = (x > 0.0f) ? x : ALPHAV * x;
            pn[i] = x;
            lmax = fmaxf(lmax, x);
        }
        #pragma unroll
        for (int off = 16; off > 0; off >>= 1)
            lmax = fmaxf(lmax, __shfl_xor_sync(0xffffffffu, lmax, off));
        if (lane == 0) red8[wid] = lmax;
        __syncthreads();
        float m = red8[0];
        #pragma unroll
        for (int w = 1; w < 8; w++) m = fmaxf(m, red8[w]);
        __syncthreads();

        float lsum = 0.0f;
        for (int i = tid; i < cnt; i += 256) {
            float p = __expf(pn[i] - m);
            pn[i] = p;
            lsum += p;
        }
        #pragma unroll
        for (int off = 16; off > 0; off >>= 1)
            lsum += __shfl_xor_sync(0xffffffffu, lsum, off);
        if (lane == 0) red8[wid] = lsum;
        __syncthreads();
        float ssum = 0.0f;
        #pragma unroll
        for (int w = 0; w < 8; w++) ssum += red8[w];
        float inv = 1.0f / ssum;

        int i = 0;
        for (; i + 4 <= cnt; i += 4) {
            int j0 = list[i], j1 = list[i + 1], j2 = list[i + 2], j3 = list[i + 3];
            float p0 = pn[i] * inv, p1 = pn[i + 1] * inv;
            float p2 = pn[i + 2] * inv, p3 = pn[i + 3] * inv;
            float h0 = __half2float(hp[(size_t)j0 * FD + tid]);
            float h1 = __half2float(hp[(size_t)j1 * FD + tid]);
            float h2 = __half2float(hp[(size_t)j2 * FD + tid]);
            float h3 = __half2float(hp[(size_t)j3 * FD + tid]);
            acc = fmaf(p0, h0, acc);
            acc = fmaf(p1, h1, acc);
            acc = fmaf(p2, h2, acc);
            acc = fmaf(p3, h3, acc);
        }
        for (; i < cnt; i++)
            acc = fmaf(pn[i] * inv, __half2float(hp[(size_t)list[i] * FD + tid]), acc);
        __syncthreads();
    }

    Hout[(((size_t)b * NSEQ + n) * NLAY + k) * FD + tid] = acc;
}

// ---------------- masked softmax (16 rows/block) -> coalesced A-fragments ---
__global__ __launch_bounds__(256) void att_kernel(void) {
    int mt = blockIdx.x, b = blockIdx.y, zz = blockIdx.z;
    int t = zz % 3, kk = zz / 3, k = kk + 1;
    int tid = threadIdx.x;
    int row = tid >> 4, c = tid & 15;
    int z = t * 3 + k;

    __shared__ float sf2[NSEQ];
    __shared__ unsigned smask[16][NWRD];
    __shared__ unsigned stage[16 * 512];

    const float* f2p = &g_f2[(size_t)z * BATCH * NSEQ + (size_t)b * NSEQ];
    for (int j = tid; j < NSEQ; j += 256) sf2[j] = f2p[j];
    {
        const unsigned* mb = &g_mask[k][(((size_t)b * NT + t) * NSEQ + mt * 16) * NWRD];
        for (int i = tid; i < 16 * NWRD; i += 256)
            smask[i >> 5][i & 31] = mb[i];
    }
    __syncthreads();

    float f1v = g_f1[(size_t)z * BATCH * NSEQ + (size_t)b * NSEQ + mt * 16 + row];
    const unsigned* mrow = smask[row];

    float pv[64];
    float lmax = NEGV;
    #pragma unroll
    for (int s = 0; s < 32; s++) {
        unsigned m2 = (mrow[s] >> (2 * c)) & 3u;
        float x0 = f1v + sf2[32 * s + 2 * c];
        x0 = (x0 > 0.0f) ? x0 : ALPHAV * x0;
        float x1 = f1v + sf2[32 * s + 2 * c + 1];
        x1 = (x1 > 0.0f) ? x1 : ALPHAV * x1;
        float e0 = (m2 & 1u) ? x0 : NEGV;
        float e1 = (m2 & 2u) ? x1 : NEGV;
        pv[2 * s] = e0;
        pv[2 * s + 1] = e1;
        lmax = fmaxf(lmax, fmaxf(e0, e1));
    }
    #pragma unroll
    for (int off = 8; off > 0; off >>= 1)
        lmax = fmaxf(lmax, __shfl_xor_sync(0xffffffffu, lmax, off));
    float m = lmax;

    bool empty = (m < -8.9e15f);
    float lsum = 0.0f;
    #pragma unroll
    for (int q = 0; q < 64; q++) {
        float p = empty ? 1.0f : __expf(pv[q] - m);
        pv[q] = p;
        lsum += p;
    }
    #pragma unroll
    for (int off = 8; off > 0; off >>= 1)
        lsum += __shfl_xor_sync(0xffffffffu, lsum, off);
    float inv = 1.0f / lsum;

    unsigned* srow = &stage[row * 512];
    #pragma unroll
    for (int s = 0; s < 32; s++)
        srow[c + 16 * s] = packh2(pv[2 * s] * inv, pv[2 * s + 1] * inv);
    __syncthreads();

    uint4* obase = g_attf + (((size_t)kk * NT + t) * BATCH + b) * ((size_t)64 * 64 * 32)
                   + (size_t)mt * 64 * 32;
    #pragma unroll
    for (int w = 0; w < 8; w++) {
        int widx = tid + 256 * w;
        int ktw = widx >> 5;
        int lw = widx & 31;
        int r0 = lw >> 2;
        int p0 = ktw * 8 + (lw & 3);
        uint4 u;
        u.x = stage[r0 * 512 + p0];
        u.y = stage[(r0 + 8) * 512 + p0];
        u.z = stage[r0 * 512 + p0 + 4];
        u.w = stage[(r0 + 8) * 512 + p0 + 4];
        obase[widx] = u;
    }
}

// ---------------- final combine ---------------------------------------------
__global__ void combine_kernel(const float* __restrict__ Ww, const float* __restrict__ bw,
                               const float* __restrict__ Wc, float* __restrict__ out) {
    int bn = blockIdx.x;
    int tid = threadIdx.x;
    __shared__ float sh[NLAY * FD];
    __shared__ float part[NLAY][128];
    __shared__ float sy[NLAY];

    const float* Hp = &g_H[(size_t)bn * NLAY * FD];
    for (int i = tid; i < NLAY * FD; i += 128) sh[i] = Hp[i];
    __syncthreads();

    float loc[NLAY] = {0.0f, 0.0f, 0.0f};
    if (tid < 100) {
        float wc = Wc[tid];
        float bwv = bw[tid];
        #pragma unroll
        for (int k = 0; k < NLAY; k++) {
            float y = bwv;
            #pragma unroll 8
            for (int i = 0; i < FD; i++)
                y = fmaf(sh[k * FD + i], Ww[i * 100 + tid], y);
            loc[k] = tanhf(y) * wc;
        }
    }
    #pragma unroll
    for (int k = 0; k < NLAY; k++) part[k][tid] = loc[k];
    __syncthreads();
    for (int s = 64; s > 0; s >>= 1) {
        if (tid < s) {
            part[0][tid] += part[0][tid + s];
            part[1][tid] += part[1][tid + s];
            part[2][tid] += part[2][tid + s];
        }
        __syncthreads();
    }
    if (tid == 0) {
        float s0 = part[0][0], s1 = part[1][0], s2 = part[2][0];
        float mx = fmaxf(s0, fmaxf(s1, s2));
        float e0 = __expf(s0 - mx), e1 = __expf(s1 - mx), e2 = __expf(s2 - mx);
        float invs = 1.0f / (e0 + e1 + e2);
        sy[0] = e0 * invs; sy[1] = e1 * invs; sy[2] = e2 * invs;
    }
    __syncthreads();

    float w0 = sy[0], w1 = sy[1], w2 = sy[2];
    for (int f = tid; f < FD; f += 128)
        out[(size_t)bn * FD + f] =
            w0 * sh[f] + w1 * sh[FD + f] + w2 * sh[2 * FD + f];
}

// ---------------- launch ----------------------------------------------------
extern "C" void kernel_launch(void* const* d_in, const int* in_sizes, int n_in,
                              void* d_out, int out_size) {
    const float* adj = (const float*)d_in[0];
    const float* X   = (const float*)d_in[1];
    const float* W   = (const float*)d_in[2];
    const float* a1  = (const float*)d_in[3];
    const float* a2  = (const float*)d_in[4];
    const float* Ww  = (const float*)d_in[5];
    const float* bw  = (const float*)d_in[6];
    const float* Wc  = (const float*)d_in[7];
    float* out = (float*)d_out;

    void *ph16, *pH, *pxf, *pwf, *paf, *phf;
    cudaGetSymbolAddress(&ph16, g_h16);
    cudaGetSymbolAddress(&pH, g_H);
    cudaGetSymbolAddress(&pxf, g_xf);
    cudaGetSymbolAddress(&pwf, g_wf);
    cudaGetSymbolAddress(&paf, g_attf);
    cudaGetSymbolAddress(&phf, g_htf);
    float* Hbuf = (float*)pH;

    // 1. adjacency bitsets + boolean powers (adj^3 via adj * adj^2)
    bits_kernel<<<BATCH * NT * NSEQ, 1024>>>(adj);
    zero_f_kernel<<<(9 * BATCH * NSEQ + 1023) / 1024, 1024>>>();
    bmm_kernel<<<BATCH * NT * NSEQ / 8, 256>>>(0, 0, 1);
    bmm_kernel<<<BATCH * NT * NSEQ / 8, 256>>>(0, 1, 2);

    // 2. fragment-major fp16 operand prep: X, W
    xf_kernel<<<(BATCH * NSEQ / 16 * (IND / 16) * 32) / 256, 256>>>(X);
    wf_kernel<<<(9 * (FD / 8) * (IND / 16) * 32) / 256, 256>>>(W);

    // 3. h[t,k] = X @ W[t,k]: k=0 -> h16 row-major; k=1,2 -> g_htf B-frags
    //    (fused f1/f2 epilogue for all z)
    {
        dim3 grid(FD / BN, (BATCH * NSEQ) / BM, 9);
        tgemm16f<<<grid, 256>>>((const uint4*)pxf, (const uint2*)pwf, (float*)ph16,
                                IND / 16, FD, 9,
                                0LL, (long long)(FD / 8) * (IND / 16) * 32,
                                0LL,
                                0LL, 0LL, 0LL,
                                0LL, 0LL, 1,
                                1, a1, a2);
    }

    // 4. sparse layer k=0 (fp16 h)
    spmm_kernel<<<dim3(NSEQ, BATCH), 256>>>(0, Hbuf);

    // 5. all dense masked-softmax rows (k=1,2 x t=0..2), coalesced A-fragments
    att_kernel<<<dim3(NSEQ / 16, BATCH, 6), 256>>>();

    // 6. dense layers k=1,2 in ONE launch: grid.z = (kk, b), segmented over t
    {
        dim3 grid(FD / BN, NSEQ / BM, 2 * BATCH);
        tgemm16f<<<grid, 256>>>(
            (const uint4*)paf, (const uint2*)phf,
            Hbuf + 1 * FD,
            NSEQ / 16, NLAY * FD, BATCH,
            (long long)64 * 64 * 32,
            (long long)32 * 64 * 32,
            (long long)NSEQ * NLAY * FD,
            (long long)NT * BATCH * 64 * 64 * 32,
            (long long)NT * BATCH * 32 * 64 * 32,
            (long long)FD,
            (long long)BATCH * 64 * 64 * 32,
            (long long)BATCH * 32 * 64 * 32,
            NT,
            0, (const float*)0, (const float*)0);
    }

    // 7. combine
    combine_kernel<<<BATCH * NSEQ, 128>>>(Ww, bw, Wc, out);
}